// round 5
// baseline (speedup 1.0000x reference)
#include <cuda_runtime.h>
#include <cuda_bf16.h>
#include <cstdint>
#include <cstddef>

// Problem dims
#define T_STEPS 512
#define BATCH   256
#define DIM     512
#define HID     256
#define FOURH   1024
#define NACT    32
#define OUTC    33

// Scratch for x_proj: [T, B, 4H] fp32
__device__ float g_xproj[(size_t)T_STEPS * BATCH * FOURH];

// ===========================================================================
// Shared helpers
// ===========================================================================
__device__ __forceinline__ uint32_t smem_u32(const void* p) {
    uint32_t a;
    asm("{ .reg .u64 t; cvta.to.shared.u64 t, %1; cvt.u32.u64 %0, t; }"
        : "=r"(a) : "l"(p));
    return a;
}
__device__ __forceinline__ void ldsm_x4(uint32_t* r, uint32_t addr) {
    asm volatile("ldmatrix.sync.aligned.m8n8.x4.shared.b16 {%0,%1,%2,%3}, [%4];"
        : "=r"(r[0]), "=r"(r[1]), "=r"(r[2]), "=r"(r[3]) : "r"(addr));
}
__device__ __forceinline__ void ldsm_x4_t(uint32_t* r, uint32_t addr) {
    asm volatile("ldmatrix.sync.aligned.m8n8.x4.trans.shared.b16 {%0,%1,%2,%3}, [%4];"
        : "=r"(r[0]), "=r"(r[1]), "=r"(r[2]), "=r"(r[3]) : "r"(addr));
}
__device__ __forceinline__ void ldsm_x2_t(uint32_t* r, uint32_t addr) {
    asm volatile("ldmatrix.sync.aligned.m8n8.x2.trans.shared.b16 {%0,%1}, [%2];"
        : "=r"(r[0]), "=r"(r[1]) : "r"(addr));
}
__device__ __forceinline__ void mma_bf16(float* c, const uint32_t* a,
                                         uint32_t b0, uint32_t b1) {
    asm volatile(
        "mma.sync.aligned.m16n8k16.row.col.f32.bf16.bf16.f32 "
        "{%0,%1,%2,%3}, {%4,%5,%6,%7}, {%8,%9}, {%0,%1,%2,%3};"
        : "+f"(c[0]), "+f"(c[1]), "+f"(c[2]), "+f"(c[3])
        : "r"(a[0]), "r"(a[1]), "r"(a[2]), "r"(a[3]), "r"(b0), "r"(b1));
}
__device__ __forceinline__ uint32_t pack2(__nv_bfloat16 a, __nv_bfloat16 b) {
    union { __nv_bfloat162 v; uint32_t u; } c;
    c.v = __nv_bfloat162(a, b);
    return c.u;
}
__device__ __forceinline__ void split_store4(float4 v,
                                             __nv_bfloat16* hip,
                                             __nv_bfloat16* lop) {
    __nv_bfloat16 h0 = __float2bfloat16_rn(v.x);
    __nv_bfloat16 h1 = __float2bfloat16_rn(v.y);
    __nv_bfloat16 h2 = __float2bfloat16_rn(v.z);
    __nv_bfloat16 h3 = __float2bfloat16_rn(v.w);
    __nv_bfloat16 l0 = __float2bfloat16_rn(v.x - __bfloat162float(h0));
    __nv_bfloat16 l1 = __float2bfloat16_rn(v.y - __bfloat162float(h1));
    __nv_bfloat16 l2 = __float2bfloat16_rn(v.z - __bfloat162float(h2));
    __nv_bfloat16 l3 = __float2bfloat16_rn(v.w - __bfloat162float(h3));
    ((uint32_t*)hip)[0] = pack2(h0, h1);
    ((uint32_t*)hip)[1] = pack2(h2, h3);
    ((uint32_t*)lop)[0] = pack2(l0, l1);
    ((uint32_t*)lop)[1] = pack2(l2, l3);
}

// ---- MUFU-free activations (FMA/ALU pipes only) ----
__device__ __forceinline__ float fast_exp(float x) {
    const float L2E = 1.4426950408889634f;
    float t  = fmaf(x, L2E, 12582912.0f);
    int   n  = __float_as_int(t) - 0x4B400000;
    float nf = t - 12582912.0f;
    float r  = fmaf(nf, -0.693359375f, x);
    r = fmaf(nf, 2.12194440e-4f, r);
    float p = 1.9841270e-4f;
    p = fmaf(p, r, 1.3888889e-3f);
    p = fmaf(p, r, 8.3333333e-3f);
    p = fmaf(p, r, 4.1666667e-2f);
    p = fmaf(p, r, 1.6666667e-1f);
    p = fmaf(p, r, 0.5f);
    p = fmaf(p, r, 1.0f);
    p = fmaf(p, r, 1.0f);
    return __int_as_float(__float_as_int(p) + (n << 23));
}
__device__ __forceinline__ float fast_rcp(float d) {
    float r = __int_as_float(0x7EF127EAu - __float_as_int(d));
    r = r * fmaf(-d, r, 2.0f);
    r = r * fmaf(-d, r, 2.0f);
    r = r * fmaf(-d, r, 2.0f);
    return r;
}
__device__ __forceinline__ float fsig(float x) {
    x = fminf(fmaxf(x, -30.0f), 30.0f);
    float e = fast_exp(-x);
    return fast_rcp(1.0f + e);
}
__device__ __forceinline__ float ftanh(float x) {
    return fmaf(2.0f, fsig(2.0f * x), -1.0f);
}

// ===========================================================================
// Kernel 1: x_proj = inputs @ Wx + b (unchanged — measured ~1.2 ms)
// ===========================================================================
#define XBM 128
#define XBN 128
#define XBK 32
#define KPA 40
#define NPB 136
#define A_TERM_ELEMS (XBM * KPA)
#define B_TERM_ELEMS (XBK * NPB)
#define STAGE_ELEMS  (2 * A_TERM_ELEMS + 2 * B_TERM_ELEMS)
#define XSMEM_BYTES  (2 * STAGE_ELEMS * 2)

__global__ __launch_bounds__(256) void xproj_mma_kernel(
    const float* __restrict__ A,
    const float* __restrict__ W,
    const float* __restrict__ bias)
{
    extern __shared__ __nv_bfloat16 xsm[];

    const int tid   = threadIdx.x;
    const int lane  = tid & 31;
    const int wid   = tid >> 5;
    const int warpM = wid & 3;
    const int warpN = wid >> 2;
    const int bM    = blockIdx.y;
    const int bN    = blockIdx.x;

    const int arow0 = tid >> 3;
    const int ac4   = tid & 7;
    const int bkr0  = tid >> 5;
    const int bn4   = tid & 31;

    const float* Ag = A + (size_t)bM * XBM * DIM;
    const float* Wg = W + (size_t)bN * XBN;

    float acc[2][8][4];
    #pragma unroll
    for (int mt = 0; mt < 2; mt++)
        #pragma unroll
        for (int j = 0; j < 8; j++)
            #pragma unroll
            for (int q = 0; q < 4; q++) acc[mt][j][q] = 0.f;

    const int a_row_l = (lane & 15);
    const int a_koff  = ((lane >> 4) << 3);
    const int b_krow  = (lane & 7) + ((lane >> 3) & 1) * 8;
    const int b_ncol  = ((lane >> 4) & 1) * 8;

    float4 aReg[4], bReg[4];

    #pragma unroll
    for (int i = 0; i < 4; i++) {
        aReg[i] = *(const float4*)(Ag + (size_t)(arow0 + 32 * i) * DIM + ac4 * 4);
        bReg[i] = *(const float4*)(Wg + (size_t)(bkr0 + 8 * i) * FOURH + bn4 * 4);
    }
    {
        __nv_bfloat16* Ahi = xsm;
        __nv_bfloat16* Alo = Ahi + A_TERM_ELEMS;
        __nv_bfloat16* Bhi = Alo + A_TERM_ELEMS;
        __nv_bfloat16* Blo = Bhi + B_TERM_ELEMS;
        #pragma unroll
        for (int i = 0; i < 4; i++) {
            int ar = arow0 + 32 * i;
            split_store4(aReg[i], &Ahi[ar * KPA + ac4 * 4], &Alo[ar * KPA + ac4 * 4]);
            int bk = bkr0 + 8 * i;
            split_store4(bReg[i], &Bhi[bk * NPB + bn4 * 4], &Blo[bk * NPB + bn4 * 4]);
        }
    }
    __syncthreads();

    const int NSTAGE = DIM / XBK;

    for (int s = 0; s < NSTAGE; s++) {
        if (s + 1 < NSTAGE) {
            int k0 = (s + 1) * XBK;
            #pragma unroll
            for (int i = 0; i < 4; i++) {
                aReg[i] = *(const float4*)(Ag + (size_t)(arow0 + 32 * i) * DIM + k0 + ac4 * 4);
                bReg[i] = *(const float4*)(Wg + (size_t)(k0 + bkr0 + 8 * i) * FOURH + bn4 * 4);
            }
        }

        const __nv_bfloat16* st = xsm + (s & 1) * STAGE_ELEMS;
        uint32_t sAhi = smem_u32(st);
        uint32_t sAlo = sAhi + A_TERM_ELEMS * 2;
        uint32_t sBhi = sAlo + A_TERM_ELEMS * 2;
        uint32_t sBlo = sBhi + B_TERM_ELEMS * 2;

        #pragma unroll
        for (int ks = 0; ks < 2; ks++) {
            const int kk0 = ks * 16;
            uint32_t aHi[2][4], aLo[2][4];
            #pragma unroll
            for (int mt = 0; mt < 2; mt++) {
                uint32_t off =
                    (uint32_t)((warpM * 32 + mt * 16 + a_row_l) * KPA + kk0 + a_koff) * 2;
                ldsm_x4(aHi[mt], sAhi + off);
                ldsm_x4(aLo[mt], sAlo + off);
            }
            uint32_t bHi[4][4], bLo[4][4];
            #pragma unroll
            for (int nt = 0; nt < 4; nt++) {
                uint32_t off =
                    (uint32_t)((kk0 + b_krow) * NPB + warpN * 64 + nt * 16 + b_ncol) * 2;
                ldsm_x4_t(bHi[nt], sBhi + off);
                ldsm_x4_t(bLo[nt], sBlo + off);
            }
            #pragma unroll
            for (int mt = 0; mt < 2; mt++) {
                #pragma unroll
                for (int j = 0; j < 8; j++) {
                    uint32_t bh0 = bHi[j >> 1][(j & 1) * 2];
                    uint32_t bh1 = bHi[j >> 1][(j & 1) * 2 + 1];
                    uint32_t bl0 = bLo[j >> 1][(j & 1) * 2];
                    uint32_t bl1 = bLo[j >> 1][(j & 1) * 2 + 1];
                    mma_bf16(acc[mt][j], aHi[mt], bh0, bh1);
                    mma_bf16(acc[mt][j], aHi[mt], bl0, bl1);
                    mma_bf16(acc[mt][j], aLo[mt], bh0, bh1);
                }
            }
        }

        if (s + 1 < NSTAGE) {
            __nv_bfloat16* dst = xsm + ((s + 1) & 1) * STAGE_ELEMS;
            __nv_bfloat16* Ahi = dst;
            __nv_bfloat16* Alo = Ahi + A_TERM_ELEMS;
            __nv_bfloat16* Bhi = Alo + A_TERM_ELEMS;
            __nv_bfloat16* Blo = Bhi + B_TERM_ELEMS;
            #pragma unroll
            for (int i = 0; i < 4; i++) {
                int ar = arow0 + 32 * i;
                split_store4(aReg[i], &Ahi[ar * KPA + ac4 * 4], &Alo[ar * KPA + ac4 * 4]);
                int bk = bkr0 + 8 * i;
                split_store4(bReg[i], &Bhi[bk * NPB + bn4 * 4], &Blo[bk * NPB + bn4 * 4]);
            }
        }
        __syncthreads();
    }

    const int g  = lane >> 2;
    const int t2 = (lane & 3) * 2;
    #pragma unroll
    for (int mt = 0; mt < 2; mt++) {
        int row = bM * XBM + warpM * 32 + mt * 16 + g;
        #pragma unroll
        for (int j = 0; j < 8; j++) {
            int col = bN * XBN + warpN * 64 + j * 8 + t2;
            float b0 = bias[col], b1 = bias[col + 1];
            float2 o0 = make_float2(acc[mt][j][0] + b0, acc[mt][j][1] + b1);
            float2 o1 = make_float2(acc[mt][j][2] + b0, acc[mt][j][3] + b1);
            *(float2*)&g_xproj[(size_t)row * FOURH + col] = o0;
            *(float2*)&g_xproj[(size_t)(row + 8) * FOURH + col] = o1;
        }
    }
}

// ===========================================================================
// Kernel 2: recurrent kernel — 512 threads, reset folded into gating,
// 2 syncthreads/step, epi resident in smem.
// ===========================================================================
#define CLUSTER 8
#define NB      16
#define LC      128
#define RTHREADS 512

#define HSTRIDE 264
#define WSTRIDE 136
#define ZSTRIDE 132

#define SMB_WHHI 0
#define SMB_WHLO (SMB_WHHI + 256 * WSTRIDE * 2)
#define SMB_HB   (SMB_WHLO + 256 * WSTRIDE * 2)
#define HB_ARR_BYTES (NB * HSTRIDE * 2)
#define HB_BUF_BYTES (2 * HB_ARR_BYTES)
#define SMB_Z    (SMB_HB + 2 * HB_BUF_BYTES)
#define SMB_C    (SMB_Z + NB * ZSTRIDE * 4)
#define SMB_WO   (SMB_C + NB * 32 * 4)
#define SMB_BO   (SMB_WO + 5 * 256 * 4)
#define SMB_EP   (SMB_BO + 32)
#define RSMEM_BYTES (SMB_EP + T_STEPS * NB * 4)   // 221504

__device__ __forceinline__ void st_cluster_v4(uint32_t saddr, int rank,
                                              uint32_t a, uint32_t b,
                                              uint32_t c, uint32_t d) {
    asm volatile(
        "{ .reg .b32 ra; mapa.shared::cluster.u32 ra, %0, %1;"
        "  st.shared::cluster.v4.b32 [ra], {%2,%3,%4,%5}; }"
        :: "r"(saddr), "r"(rank), "r"(a), "r"(b), "r"(c), "r"(d) : "memory");
}

__global__ void __cluster_dims__(CLUSTER, 1, 1) __launch_bounds__(RTHREADS, 1)
lstm_rec_kernel(const int*   __restrict__ epi,
                const float* __restrict__ carry_c,
                const float* __restrict__ carry_h,
                const float* __restrict__ Wh,
                const float* __restrict__ Wa,
                const float* __restrict__ ba,
                const float* __restrict__ Wv,
                const float* __restrict__ bv,
                float*       __restrict__ out)
{
    extern __shared__ char smraw[];
    __nv_bfloat16* WhHi = (__nv_bfloat16*)(smraw + SMB_WHHI);
    __nv_bfloat16* WhLo = (__nv_bfloat16*)(smraw + SMB_WHLO);
    float* z_s  = (float*)(smraw + SMB_Z);
    float* c_s  = (float*)(smraw + SMB_C);
    float* Wo_s = (float*)(smraw + SMB_WO);
    float* bo_s = (float*)(smraw + SMB_BO);
    int*   ep_s = (int*)  (smraw + SMB_EP);

    const int tid  = threadIdx.x;
    const int lane = tid & 31;
    const int wid  = tid >> 5;            // 0..15
    uint32_t rank;
    asm("mov.u32 %0, %%cluster_ctarank;" : "=r"(rank));
    const int cl = blockIdx.x / CLUSTER;
    const int b0 = cl * NB;

    // --- preload Wh slice (split bf16) ---
    for (int idx = tid; idx < 256 * LC; idx += RTHREADS) {
        int k = idx >> 7;
        int c = idx & 127;
        int gcol = ((c >> 5) << 8) + ((int)rank << 5) + (c & 31);
        float w = Wh[k * FOURH + gcol];
        __nv_bfloat16 hi = __float2bfloat16_rn(w);
        __nv_bfloat16 lo = __float2bfloat16_rn(w - __bfloat162float(hi));
        WhHi[k * WSTRIDE + c] = hi;
        WhLo[k * WSTRIDE + c] = lo;
    }
    // --- preload carry_h into buffer 1 (input for t=0), split bf16 ---
    for (int idx = tid; idx < NB * HID; idx += RTHREADS) {
        int b = idx >> 8;
        int k = idx & 255;
        float v = carry_h[(size_t)(b0 + b) * HID + k];
        __nv_bfloat16 hi = __float2bfloat16_rn(v);
        __nv_bfloat16 lo = __float2bfloat16_rn(v - __bfloat162float(hi));
        __nv_bfloat16* hHi = (__nv_bfloat16*)(smraw + SMB_HB + 1 * HB_BUF_BYTES);
        __nv_bfloat16* hLo = hHi + NB * HSTRIDE;
        hHi[b * HSTRIDE + k] = hi;
        hLo[b * HSTRIDE + k] = lo;
    }
    // --- preload carry_c slice ---
    for (int idx = tid; idx < NB * 32; idx += RTHREADS) {
        int b = idx >> 5;
        int j = idx & 31;
        c_s[idx] = carry_c[(size_t)(b0 + b) * HID + (int)rank * 32 + j];
    }
    // --- preload output-head columns ---
    #pragma unroll
    for (int q = 0; q < 5; q++) {
        int col = (int)rank + 8 * q;
        if (col <= 32) {
            for (int k = tid; k < HID; k += RTHREADS)
                Wo_s[q * 256 + k] = (col < 32) ? Wa[k * NACT + col] : Wv[k];
            if (tid == 0) bo_s[q] = (col < 32) ? ba[col] : bv[0];
        }
    }
    // --- preload full epi slice: [T][NB] ---
    for (int idx = tid; idx < T_STEPS * NB; idx += RTHREADS) {
        int t = idx >> 4;
        int b = idx & 15;
        ep_s[idx] = epi[t * BATCH + b0 + b];
    }
    __syncthreads();

    // matvec frag geometry: 16 warps, warp wid handles local cols [wid*8, wid*8+8)
    const int a_row_l = (lane & 15);
    const int a_koff  = ((lane >> 4) << 3);
    const int b_row_l = (lane & 15);

    const uint32_t sWhHi = smem_u32(WhHi);
    const uint32_t sWhLo = smem_u32(WhLo);

    // gating mapping: 1 element per thread
    const int gb = tid >> 5;     // batch row 0..15
    const int gj = tid & 31;     // hidden unit 0..31 within this CTA's slice

    for (int t = 0; t < T_STEPS; t++) {
        const int p_out = t & 1;
        const int p_in  = p_out ^ 1;
        __nv_bfloat16* hinHi  = (__nv_bfloat16*)(smraw + SMB_HB + p_in * HB_BUF_BYTES);
        __nv_bfloat16* hinLo  = hinHi + NB * HSTRIDE;
        __nv_bfloat16* houtHi = (__nv_bfloat16*)(smraw + SMB_HB + p_out * HB_BUF_BYTES);
        __nv_bfloat16* houtLo = houtHi + NB * HSTRIDE;

        // -- prefetch x_proj gate values for this thread's element --
        const size_t xbase = (size_t)t * BATCH * FOURH
                           + (size_t)(b0 + gb) * FOURH + (int)rank * 32 + gj;
        float xi = g_xproj[xbase];
        float xf = g_xproj[xbase + 256];
        float xg = g_xproj[xbase + 512];
        float xo = g_xproj[xbase + 768];
        int   ep = ep_s[t * NB + gb];

        // -- z = h @ Wh_slice via mma: M=16, N=8 per warp, K=256 --
        {
            const uint32_t sHinHi = smem_u32(hinHi);
            const uint32_t sHinLo = smem_u32(hinLo);
            float acc[4] = {0.f, 0.f, 0.f, 0.f};

            #pragma unroll 8
            for (int ks = 0; ks < 16; ks++) {
                const int kk0 = ks * 16;
                uint32_t aoff = (uint32_t)(a_row_l * HSTRIDE + kk0 + a_koff) * 2;
                uint32_t aHi[4], aLo[4];
                ldsm_x4(aHi, sHinHi + aoff);
                ldsm_x4(aLo, sHinLo + aoff);
                uint32_t boff =
                    (uint32_t)((kk0 + b_row_l) * WSTRIDE + wid * 8) * 2;
                uint32_t bHi[2], bLo[2];
                ldsm_x2_t(bHi, sWhHi + boff);
                ldsm_x2_t(bLo, sWhLo + boff);
                mma_bf16(acc, aHi, bHi[0], bHi[1]);
                mma_bf16(acc, aHi, bLo[0], bLo[1]);
                mma_bf16(acc, aLo, bHi[0], bHi[1]);
            }
            // z write: rows lane>>2 and +8; cols wid*8 + 2*(lane&3)
            int r0 = lane >> 2;
            int col = wid * 8 + 2 * (lane & 3);
            *(float2*)&z_s[r0 * ZSTRIDE + col] = make_float2(acc[0], acc[1]);
            *(float2*)&z_s[(r0 + 8) * ZSTRIDE + col] = make_float2(acc[2], acc[3]);
        }
        __syncthreads();

        // -- gating (reset folded in; MUFU-free activations) --
        {
            float zi = z_s[gb * ZSTRIDE + gj];
            float zf = z_s[gb * ZSTRIDE + 32 + gj];
            float zg = z_s[gb * ZSTRIDE + 64 + gj];
            float zo = z_s[gb * ZSTRIDE + 96 + gj];
            float c_old = c_s[gb * 32 + gj];
            if (ep) { zi = 0.f; zf = 0.f; zg = 0.f; zo = 0.f; c_old = 0.f; }
            float iz = zi + xi;
            float fz = zf + xf;
            float gz = zg + xg;
            float oz = zo + xo;
            float nc = fsig(fz) * c_old + fsig(iz) * ftanh(gz);
            float nh = fsig(oz) * ftanh(nc);
            c_s[gb * 32 + gj] = nc;
            __nv_bfloat16 hi = __float2bfloat16_rn(nh);
            __nv_bfloat16 lo = __float2bfloat16_rn(nh - __bfloat162float(hi));
            int hoff = gb * HSTRIDE + (int)rank * 32 + gj;
            houtHi[hoff] = hi;
            houtLo[hoff] = lo;
        }
        __syncthreads();

        // -- vectorized DSMEM broadcast of local slice --
        if (tid < 128) {
            int arr = tid >> 6;
            int row = (tid >> 2) & 15;
            int seg = tid & 3;
            __nv_bfloat16* base = arr ? houtLo : houtHi;
            uint32_t saddr = smem_u32(base) +
                             (uint32_t)(row * HSTRIDE + (int)rank * 32) * 2 + seg * 16;
            uint4 v = *(const uint4*)((const char*)base +
                         (size_t)(row * HSTRIDE + (int)rank * 32) * 2 + seg * 16);
            #pragma unroll
            for (int rr = 0; rr < CLUSTER; rr++)
                if (rr != (int)rank)
                    st_cluster_v4(saddr, rr, v.x, v.y, v.z, v.w);
        }

        asm volatile("barrier.cluster.arrive.aligned;" ::: "memory");
        asm volatile("barrier.cluster.wait.aligned;"   ::: "memory");

        // -- output head: 4 tasks per warp (+1 for rank0), unrolled --
        {
            float sacc[4];
            #pragma unroll
            for (int u = 0; u < 4; u++) {
                int task = wid + 16 * u;        // q = u, b = wid
                int q = task >> 4;
                int b = task & 15;
                const __nv_bfloat16* hHr = &houtHi[b * HSTRIDE];
                const __nv_bfloat16* hLr = &houtLo[b * HSTRIDE];
                const float* wcol = &Wo_s[q * 256];
                float s = 0.f;
                #pragma unroll
                for (int uu = 0; uu < 8; uu++) {
                    int k = lane + 32 * uu;
                    float hv = __bfloat162float(hHr[k]) + __bfloat162float(hLr[k]);
                    s = fmaf(hv, wcol[k], s);
                }
                sacc[u] = s;
            }
            float sv = 0.f;
            if (rank == 0) {
                const __nv_bfloat16* hHr = &houtHi[wid * HSTRIDE];
                const __nv_bfloat16* hLr = &houtLo[wid * HSTRIDE];
                const float* wcol = &Wo_s[4 * 256];
                #pragma unroll
                for (int uu = 0; uu < 8; uu++) {
                    int k = lane + 32 * uu;
                    float hv = __bfloat162float(hHr[k]) + __bfloat162float(hLr[k]);
                    sv = fmaf(hv, wcol[k], sv);
                }
            }
            #pragma unroll
            for (int u = 0; u < 4; u++) {
                float s = sacc[u];
                #pragma unroll
                for (int off = 16; off; off >>= 1)
                    s += __shfl_xor_sync(0xFFFFFFFFu, s, off);
                sacc[u] = s;
            }
            #pragma unroll
            for (int off = 16; off; off >>= 1)
                sv += __shfl_xor_sync(0xFFFFFFFFu, sv, off);
            if (lane == 0) {
                size_t obase = ((size_t)t * BATCH + b0 + wid) * OUTC;
                #pragma unroll
                for (int u = 0; u < 4; u++)
                    out[obase + (int)rank + 8 * u] = sacc[u] + bo_s[u];
                if (rank == 0)
                    out[obase + 32] = sv + bo_s[4];
            }
        }
        // no extra syncthreads: next-step hazards are covered by the
        // gating-sync + cluster barrier chain (see analysis)
    }
}

// ---------------------------------------------------------------------------
extern "C" void kernel_launch(void* const* d_in, const int* in_sizes, int n_in,
                              void* d_out, int out_size) {
    const float* inputs  = (const float*)d_in[0];
    const int*   epi     = (const int*)  d_in[1];
    const float* carry_c = (const float*)d_in[2];
    const float* carry_h = (const float*)d_in[3];
    const float* Wx      = (const float*)d_in[4];
    const float* Wh      = (const float*)d_in[5];
    const float* bias    = (const float*)d_in[6];
    const float* Wa      = (const float*)d_in[7];
    const float* ba      = (const float*)d_in[8];
    const float* Wv      = (const float*)d_in[9];
    const float* bv      = (const float*)d_in[10];
    float* out = (float*)d_out;

    cudaFuncSetAttribute(xproj_mma_kernel,
                         cudaFuncAttributeMaxDynamicSharedMemorySize, XSMEM_BYTES);
    cudaFuncSetAttribute(lstm_rec_kernel,
                         cudaFuncAttributeMaxDynamicSharedMemorySize, RSMEM_BYTES);

    dim3 g1(FOURH / XBN, (T_STEPS * BATCH) / XBM);
    xproj_mma_kernel<<<g1, 256, XSMEM_BYTES>>>(inputs, Wx, bias);

    lstm_rec_kernel<<<(BATCH / NB) * CLUSTER, RTHREADS, RSMEM_BYTES>>>(
        epi, carry_c, carry_h, Wh, Wa, ba, Wv, bv, out);
}

// round 6
// speedup vs baseline: 1.0619x; 1.0619x over previous
#include <cuda_runtime.h>
#include <cuda_bf16.h>
#include <cstdint>
#include <cstddef>

// Problem dims
#define T_STEPS 512
#define BATCH   256
#define DIM     512
#define HID     256
#define FOURH   1024
#define NACT    32
#define OUTC    33

// Scratch for x_proj: [T, B, 4H] fp32
__device__ float g_xproj[(size_t)T_STEPS * BATCH * FOURH];

// ===========================================================================
// Shared helpers
// ===========================================================================
__device__ __forceinline__ uint32_t smem_u32(const void* p) {
    uint32_t a;
    asm("{ .reg .u64 t; cvta.to.shared.u64 t, %1; cvt.u32.u64 %0, t; }"
        : "=r"(a) : "l"(p));
    return a;
}
__device__ __forceinline__ void ldsm_x4(uint32_t* r, uint32_t addr) {
    asm volatile("ldmatrix.sync.aligned.m8n8.x4.shared.b16 {%0,%1,%2,%3}, [%4];"
        : "=r"(r[0]), "=r"(r[1]), "=r"(r[2]), "=r"(r[3]) : "r"(addr));
}
__device__ __forceinline__ void ldsm_x4_t(uint32_t* r, uint32_t addr) {
    asm volatile("ldmatrix.sync.aligned.m8n8.x4.trans.shared.b16 {%0,%1,%2,%3}, [%4];"
        : "=r"(r[0]), "=r"(r[1]), "=r"(r[2]), "=r"(r[3]) : "r"(addr));
}
__device__ __forceinline__ void mma_bf16(float* c, const uint32_t* a,
                                         uint32_t b0, uint32_t b1) {
    asm volatile(
        "mma.sync.aligned.m16n8k16.row.col.f32.bf16.bf16.f32 "
        "{%0,%1,%2,%3}, {%4,%5,%6,%7}, {%8,%9}, {%0,%1,%2,%3};"
        : "+f"(c[0]), "+f"(c[1]), "+f"(c[2]), "+f"(c[3])
        : "r"(a[0]), "r"(a[1]), "r"(a[2]), "r"(a[3]), "r"(b0), "r"(b1));
}
__device__ __forceinline__ uint32_t pack2(__nv_bfloat16 a, __nv_bfloat16 b) {
    union { __nv_bfloat162 v; uint32_t u; } c;
    c.v = __nv_bfloat162(a, b);
    return c.u;
}
__device__ __forceinline__ void split_store4(float4 v,
                                             __nv_bfloat16* hip,
                                             __nv_bfloat16* lop) {
    __nv_bfloat16 h0 = __float2bfloat16_rn(v.x);
    __nv_bfloat16 h1 = __float2bfloat16_rn(v.y);
    __nv_bfloat16 h2 = __float2bfloat16_rn(v.z);
    __nv_bfloat16 h3 = __float2bfloat16_rn(v.w);
    __nv_bfloat16 l0 = __float2bfloat16_rn(v.x - __bfloat162float(h0));
    __nv_bfloat16 l1 = __float2bfloat16_rn(v.y - __bfloat162float(h1));
    __nv_bfloat16 l2 = __float2bfloat16_rn(v.z - __bfloat162float(h2));
    __nv_bfloat16 l3 = __float2bfloat16_rn(v.w - __bfloat162float(h3));
    ((uint32_t*)hip)[0] = pack2(h0, h1);
    ((uint32_t*)hip)[1] = pack2(h2, h3);
    ((uint32_t*)lop)[0] = pack2(l0, l1);
    ((uint32_t*)lop)[1] = pack2(l2, l3);
}

// ---- MUFU-free activations ----
__device__ __forceinline__ float fast_exp(float x) {
    const float L2E = 1.4426950408889634f;
    float t  = fmaf(x, L2E, 12582912.0f);
    int   n  = __float_as_int(t) - 0x4B400000;
    float nf = t - 12582912.0f;
    float r  = fmaf(nf, -0.693359375f, x);
    r = fmaf(nf, 2.12194440e-4f, r);
    float p = 1.9841270e-4f;
    p = fmaf(p, r, 1.3888889e-3f);
    p = fmaf(p, r, 8.3333333e-3f);
    p = fmaf(p, r, 4.1666667e-2f);
    p = fmaf(p, r, 1.6666667e-1f);
    p = fmaf(p, r, 0.5f);
    p = fmaf(p, r, 1.0f);
    p = fmaf(p, r, 1.0f);
    return __int_as_float(__float_as_int(p) + (n << 23));
}
__device__ __forceinline__ float fast_rcp(float d) {
    float r = __int_as_float(0x7EF127EAu - __float_as_int(d));
    r = r * fmaf(-d, r, 2.0f);
    r = r * fmaf(-d, r, 2.0f);
    r = r * fmaf(-d, r, 2.0f);
    return r;
}
__device__ __forceinline__ float fsig(float x) {
    x = fminf(fmaxf(x, -30.0f), 30.0f);
    float e = fast_exp(-x);
    return fast_rcp(1.0f + e);
}
__device__ __forceinline__ float ftanh(float x) {
    return fmaf(2.0f, fsig(2.0f * x), -1.0f);
}

// ===========================================================================
// Kernel 1: x_proj = inputs @ Wx + b (unchanged — measured ~1.2 ms)
// ===========================================================================
#define XBM 128
#define XBN 128
#define XBK 32
#define KPA 40
#define NPB 136
#define A_TERM_ELEMS (XBM * KPA)
#define B_TERM_ELEMS (XBK * NPB)
#define STAGE_ELEMS  (2 * A_TERM_ELEMS + 2 * B_TERM_ELEMS)
#define XSMEM_BYTES  (2 * STAGE_ELEMS * 2)

__global__ __launch_bounds__(256) void xproj_mma_kernel(
    const float* __restrict__ A,
    const float* __restrict__ W,
    const float* __restrict__ bias)
{
    extern __shared__ __nv_bfloat16 xsm[];

    const int tid   = threadIdx.x;
    const int lane  = tid & 31;
    const int wid   = tid >> 5;
    const int warpM = wid & 3;
    const int warpN = wid >> 2;
    const int bM    = blockIdx.y;
    const int bN    = blockIdx.x;

    const int arow0 = tid >> 3;
    const int ac4   = tid & 7;
    const int bkr0  = tid >> 5;
    const int bn4   = tid & 31;

    const float* Ag = A + (size_t)bM * XBM * DIM;
    const float* Wg = W + (size_t)bN * XBN;

    float acc[2][8][4];
    #pragma unroll
    for (int mt = 0; mt < 2; mt++)
        #pragma unroll
        for (int j = 0; j < 8; j++)
            #pragma unroll
            for (int q = 0; q < 4; q++) acc[mt][j][q] = 0.f;

    const int a_row_l = (lane & 15);
    const int a_koff  = ((lane >> 4) << 3);
    const int b_krow  = (lane & 7) + ((lane >> 3) & 1) * 8;
    const int b_ncol  = ((lane >> 4) & 1) * 8;

    float4 aReg[4], bReg[4];

    #pragma unroll
    for (int i = 0; i < 4; i++) {
        aReg[i] = *(const float4*)(Ag + (size_t)(arow0 + 32 * i) * DIM + ac4 * 4);
        bReg[i] = *(const float4*)(Wg + (size_t)(bkr0 + 8 * i) * FOURH + bn4 * 4);
    }
    {
        __nv_bfloat16* Ahi = xsm;
        __nv_bfloat16* Alo = Ahi + A_TERM_ELEMS;
        __nv_bfloat16* Bhi = Alo + A_TERM_ELEMS;
        __nv_bfloat16* Blo = Bhi + B_TERM_ELEMS;
        #pragma unroll
        for (int i = 0; i < 4; i++) {
            int ar = arow0 + 32 * i;
            split_store4(aReg[i], &Ahi[ar * KPA + ac4 * 4], &Alo[ar * KPA + ac4 * 4]);
            int bk = bkr0 + 8 * i;
            split_store4(bReg[i], &Bhi[bk * NPB + bn4 * 4], &Blo[bk * NPB + bn4 * 4]);
        }
    }
    __syncthreads();

    const int NSTAGE = DIM / XBK;

    for (int s = 0; s < NSTAGE; s++) {
        if (s + 1 < NSTAGE) {
            int k0 = (s + 1) * XBK;
            #pragma unroll
            for (int i = 0; i < 4; i++) {
                aReg[i] = *(const float4*)(Ag + (size_t)(arow0 + 32 * i) * DIM + k0 + ac4 * 4);
                bReg[i] = *(const float4*)(Wg + (size_t)(k0 + bkr0 + 8 * i) * FOURH + bn4 * 4);
            }
        }

        const __nv_bfloat16* st = xsm + (s & 1) * STAGE_ELEMS;
        uint32_t sAhi = smem_u32(st);
        uint32_t sAlo = sAhi + A_TERM_ELEMS * 2;
        uint32_t sBhi = sAlo + A_TERM_ELEMS * 2;
        uint32_t sBlo = sBhi + B_TERM_ELEMS * 2;

        #pragma unroll
        for (int ks = 0; ks < 2; ks++) {
            const int kk0 = ks * 16;
            uint32_t aHi[2][4], aLo[2][4];
            #pragma unroll
            for (int mt = 0; mt < 2; mt++) {
                uint32_t off =
                    (uint32_t)((warpM * 32 + mt * 16 + a_row_l) * KPA + kk0 + a_koff) * 2;
                ldsm_x4(aHi[mt], sAhi + off);
                ldsm_x4(aLo[mt], sAlo + off);
            }
            uint32_t bHi[4][4], bLo[4][4];
            #pragma unroll
            for (int nt = 0; nt < 4; nt++) {
                uint32_t off =
                    (uint32_t)((kk0 + b_krow) * NPB + warpN * 64 + nt * 16 + b_ncol) * 2;
                ldsm_x4_t(bHi[nt], sBhi + off);
                ldsm_x4_t(bLo[nt], sBlo + off);
            }
            #pragma unroll
            for (int mt = 0; mt < 2; mt++) {
                #pragma unroll
                for (int j = 0; j < 8; j++) {
                    uint32_t bh0 = bHi[j >> 1][(j & 1) * 2];
                    uint32_t bh1 = bHi[j >> 1][(j & 1) * 2 + 1];
                    uint32_t bl0 = bLo[j >> 1][(j & 1) * 2];
                    uint32_t bl1 = bLo[j >> 1][(j & 1) * 2 + 1];
                    mma_bf16(acc[mt][j], aHi[mt], bh0, bh1);
                    mma_bf16(acc[mt][j], aHi[mt], bl0, bl1);
                    mma_bf16(acc[mt][j], aLo[mt], bh0, bh1);
                }
            }
        }

        if (s + 1 < NSTAGE) {
            __nv_bfloat16* dst = xsm + ((s + 1) & 1) * STAGE_ELEMS;
            __nv_bfloat16* Ahi = dst;
            __nv_bfloat16* Alo = Ahi + A_TERM_ELEMS;
            __nv_bfloat16* Bhi = Alo + A_TERM_ELEMS;
            __nv_bfloat16* Blo = Bhi + B_TERM_ELEMS;
            #pragma unroll
            for (int i = 0; i < 4; i++) {
                int ar = arow0 + 32 * i;
                split_store4(aReg[i], &Ahi[ar * KPA + ac4 * 4], &Alo[ar * KPA + ac4 * 4]);
                int bk = bkr0 + 8 * i;
                split_store4(bReg[i], &Bhi[bk * NPB + bn4 * 4], &Blo[bk * NPB + bn4 * 4]);
            }
        }
        __syncthreads();
    }

    const int g  = lane >> 2;
    const int t2 = (lane & 3) * 2;
    #pragma unroll
    for (int mt = 0; mt < 2; mt++) {
        int row = bM * XBM + warpM * 32 + mt * 16 + g;
        #pragma unroll
        for (int j = 0; j < 8; j++) {
            int col = bN * XBN + warpN * 64 + j * 8 + t2;
            float b0 = bias[col], b1 = bias[col + 1];
            float2 o0 = make_float2(acc[mt][j][0] + b0, acc[mt][j][1] + b1);
            float2 o1 = make_float2(acc[mt][j][2] + b0, acc[mt][j][3] + b1);
            *(float2*)&g_xproj[(size_t)row * FOURH + col] = o0;
            *(float2*)&g_xproj[(size_t)(row + 8) * FOURH + col] = o1;
        }
    }
}

// ===========================================================================
// Kernel 2: recurrent kernel — mbarrier cluster sync, head off critical path,
// 4-chain K-split mma, 256 threads.
// ===========================================================================
#define CLUSTER 8
#define NB      16
#define LC      128
#define RTHREADS 256

#define HSTRIDE 264
#define WSTRIDE 136
#define ZSTRIDE 132

#define SMB_WHHI 0
#define SMB_WHLO (SMB_WHHI + 256 * WSTRIDE * 2)        // 69632
#define SMB_HB   (SMB_WHLO + 256 * WSTRIDE * 2)        // 139264
#define HB_ARR_BYTES (NB * HSTRIDE * 2)                 // 8448
#define HB_BUF_BYTES (2 * HB_ARR_BYTES)                 // 16896
#define SMB_Z    (SMB_HB + 2 * HB_BUF_BYTES)            // 173056
#define SMB_C    (SMB_Z + NB * ZSTRIDE * 4)             // 181504
#define SMB_WO   (SMB_C + NB * 32 * 4)                  // 183552
#define SMB_BO   (SMB_WO + 5 * 256 * 4)                 // 188672
#define SMB_MBAR (SMB_BO + 32)                          // 188704 (2 x 8B)
#define SMB_EP   (SMB_MBAR + 16)                        // 188720
#define RSMEM_BYTES (SMB_EP + T_STEPS * NB * 4)         // 221488

#define MBAR_COUNT 112   // 16 threads x 7 peer CTAs

__device__ __forceinline__ void st_cluster_v4(uint32_t saddr,
                                              uint32_t a, uint32_t b,
                                              uint32_t c, uint32_t d) {
    asm volatile("st.shared::cluster.v4.b32 [%0], {%1,%2,%3,%4};"
        :: "r"(saddr), "r"(a), "r"(b), "r"(c), "r"(d) : "memory");
}

__device__ __forceinline__ void mbar_wait_cluster(uint32_t mbar, uint32_t parity) {
    uint32_t done;
    asm volatile(
        "{ .reg .pred p;\n"
        " mbarrier.try_wait.parity.acquire.cluster.shared::cta.b64 p, [%1], %2;\n"
        " selp.b32 %0, 1, 0, p; }"
        : "=r"(done) : "r"(mbar), "r"(parity) : "memory");
    while (!done) {
        asm volatile(
            "{ .reg .pred p;\n"
            " mbarrier.try_wait.parity.acquire.cluster.shared::cta.b64 p, [%1], %2, 0x989680;\n"
            " selp.b32 %0, 1, 0, p; }"
            : "=r"(done) : "r"(mbar), "r"(parity) : "memory");
    }
}

// output head for one timestep (reads full h hi/lo rows from smem)
__device__ __forceinline__ void do_head(
    const __nv_bfloat16* hHi, const __nv_bfloat16* hLo,
    const float* Wo_s, const float* bo_s,
    float* out, int tt, int b0, int rank, int wid, int lane)
{
    float sacc[8];
    #pragma unroll
    for (int u = 0; u < 8; u++) {
        int task = wid + 8 * u;
        int q = task >> 4;
        int b = task & 15;
        const __nv_bfloat16* hHr = &hHi[b * HSTRIDE];
        const __nv_bfloat16* hLr = &hLo[b * HSTRIDE];
        const float* wcol = &Wo_s[q * 256];
        float s = 0.f;
        #pragma unroll
        for (int uu = 0; uu < 8; uu++) {
            int k = lane + 32 * uu;
            float hv = __bfloat162float(hHr[k]) + __bfloat162float(hLr[k]);
            s = fmaf(hv, wcol[k], s);
        }
        sacc[u] = s;
    }
    #pragma unroll
    for (int u = 0; u < 8; u++) {
        float s = sacc[u];
        #pragma unroll
        for (int off = 16; off; off >>= 1)
            s += __shfl_xor_sync(0xFFFFFFFFu, s, off);
        if (lane == 0) {
            int task = wid + 8 * u;
            int q = task >> 4;
            int b = task & 15;
            int col = rank + 8 * q;
            out[((size_t)tt * BATCH + b0 + b) * OUTC + col] = s + bo_s[q];
        }
    }
    if (rank == 0) {
        #pragma unroll
        for (int u = 0; u < 2; u++) {
            int b = wid + 8 * u;
            const __nv_bfloat16* hHr = &hHi[b * HSTRIDE];
            const __nv_bfloat16* hLr = &hLo[b * HSTRIDE];
            const float* wcol = &Wo_s[4 * 256];
            float s = 0.f;
            #pragma unroll
            for (int uu = 0; uu < 8; uu++) {
                int k = lane + 32 * uu;
                float hv = __bfloat162float(hHr[k]) + __bfloat162float(hLr[k]);
                s = fmaf(hv, wcol[k], s);
            }
            #pragma unroll
            for (int off = 16; off; off >>= 1)
                s += __shfl_xor_sync(0xFFFFFFFFu, s, off);
            if (lane == 0)
                out[((size_t)tt * BATCH + b0 + b) * OUTC + 32] = s + bo_s[4];
        }
    }
}

__global__ void __cluster_dims__(CLUSTER, 1, 1) __launch_bounds__(RTHREADS, 1)
lstm_rec_kernel(const int*   __restrict__ epi,
                const float* __restrict__ carry_c,
                const float* __restrict__ carry_h,
                const float* __restrict__ Wh,
                const float* __restrict__ Wa,
                const float* __restrict__ ba,
                const float* __restrict__ Wv,
                const float* __restrict__ bv,
                float*       __restrict__ out)
{
    extern __shared__ char smraw[];
    __nv_bfloat16* WhHi = (__nv_bfloat16*)(smraw + SMB_WHHI);
    __nv_bfloat16* WhLo = (__nv_bfloat16*)(smraw + SMB_WHLO);
    float* z_s  = (float*)(smraw + SMB_Z);
    float* c_s  = (float*)(smraw + SMB_C);
    float* Wo_s = (float*)(smraw + SMB_WO);
    float* bo_s = (float*)(smraw + SMB_BO);
    int*   ep_s = (int*)  (smraw + SMB_EP);

    const int tid  = threadIdx.x;
    const int lane = tid & 31;
    const int wid  = tid >> 5;            // 0..7
    uint32_t rank;
    asm("mov.u32 %0, %%cluster_ctarank;" : "=r"(rank));
    const int cl = blockIdx.x / CLUSTER;
    const int b0 = cl * NB;
    const uint32_t smbase = smem_u32(smraw);

    // --- init mbarriers ---
    if (tid == 0) {
        asm volatile("mbarrier.init.shared.b64 [%0], %1;"
            :: "r"(smbase + SMB_MBAR), "r"((uint32_t)MBAR_COUNT) : "memory");
        asm volatile("mbarrier.init.shared.b64 [%0], %1;"
            :: "r"(smbase + SMB_MBAR + 8), "r"((uint32_t)MBAR_COUNT) : "memory");
    }

    // --- preload Wh slice (split bf16) ---
    for (int idx = tid; idx < 256 * LC; idx += RTHREADS) {
        int k = idx >> 7;
        int c = idx & 127;
        int gcol = ((c >> 5) << 8) + ((int)rank << 5) + (c & 31);
        float w = Wh[k * FOURH + gcol];
        __nv_bfloat16 hi = __float2bfloat16_rn(w);
        __nv_bfloat16 lo = __float2bfloat16_rn(w - __bfloat162float(hi));
        WhHi[k * WSTRIDE + c] = hi;
        WhLo[k * WSTRIDE + c] = lo;
    }
    // --- preload carry_h into buffer 1 (input for t=0), split bf16 ---
    for (int idx = tid; idx < NB * HID; idx += RTHREADS) {
        int b = idx >> 8;
        int k = idx & 255;
        float v = carry_h[(size_t)(b0 + b) * HID + k];
        __nv_bfloat16 hi = __float2bfloat16_rn(v);
        __nv_bfloat16 lo = __float2bfloat16_rn(v - __bfloat162float(hi));
        __nv_bfloat16* hHi = (__nv_bfloat16*)(smraw + SMB_HB + 1 * HB_BUF_BYTES);
        __nv_bfloat16* hLo = hHi + NB * HSTRIDE;
        hHi[b * HSTRIDE + k] = hi;
        hLo[b * HSTRIDE + k] = lo;
    }
    // --- preload carry_c slice ---
    for (int idx = tid; idx < NB * 32; idx += RTHREADS) {
        int b = idx >> 5;
        int j = idx & 31;
        c_s[idx] = carry_c[(size_t)(b0 + b) * HID + (int)rank * 32 + j];
    }
    // --- preload output-head columns ---
    #pragma unroll
    for (int q = 0; q < 5; q++) {
        int col = (int)rank + 8 * q;
        if (col <= 32) {
            for (int k = tid; k < HID; k += RTHREADS)
                Wo_s[q * 256 + k] = (col < 32) ? Wa[k * NACT + col] : Wv[k];
            if (tid == 0) bo_s[q] = (col < 32) ? ba[col] : bv[0];
        }
    }
    // --- preload epi slice ---
    for (int idx = tid; idx < T_STEPS * NB; idx += RTHREADS) {
        int t = idx >> 4;
        int b = idx & 15;
        ep_s[idx] = epi[t * BATCH + b0 + b];
    }
    __syncthreads();
    // mbarriers + smem must be visible cluster-wide before any remote traffic
    asm volatile("barrier.cluster.arrive.aligned;" ::: "memory");
    asm volatile("barrier.cluster.wait.aligned;"   ::: "memory");

    // frag geometry (R4-proven): warp owns local cols [wid*16, wid*16+16)
    const int a_row_l = (lane & 15);
    const int a_koff  = ((lane >> 4) << 3);
    const int b_krow  = (lane & 7) + ((lane >> 3) & 1) * 8;
    const int b_ncol  = ((lane >> 4) & 1) * 8;

    const uint32_t sWhHi = smem_u32(WhHi);
    const uint32_t sWhLo = smem_u32(WhLo);

    // per-thread mbarrier phase trackers
    int ph0 = 0, ph1 = 0;

    // broadcast mapping (tid < 112): peer group + row
    const int bc_pp  = tid >> 4;                       // 0..6 (if tid<112)
    const int bc_p   = bc_pp + (bc_pp >= (int)rank);   // skip self
    const int bc_row = tid & 15;

    for (int t = 0; t < T_STEPS; t++) {
        const int p_out = t & 1;
        const int p_in  = p_out ^ 1;
        __nv_bfloat16* hinHi  = (__nv_bfloat16*)(smraw + SMB_HB + p_in * HB_BUF_BYTES);
        __nv_bfloat16* hinLo  = hinHi + NB * HSTRIDE;
        __nv_bfloat16* houtHi = (__nv_bfloat16*)(smraw + SMB_HB + p_out * HB_BUF_BYTES);
        __nv_bfloat16* houtLo = houtHi + NB * HSTRIDE;

        // -- prefetch x_proj gate values (before the wait; hidden by it) --
        float xi[2], xf[2], xg[2], xo[2];
        #pragma unroll
        for (int pp = 0; pp < 2; pp++) {
            int pr = tid + pp * 256;
            int b = pr >> 5, j = pr & 31;
            size_t base = (size_t)t * BATCH * FOURH
                        + (size_t)(b0 + b) * FOURH + (int)rank * 32 + j;
            xi[pp] = g_xproj[base];
            xf[pp] = g_xproj[base + 256];
            xg[pp] = g_xproj[base + 512];
            xo[pp] = g_xproj[base + 768];
        }

        // -- wait for peers' h slices (hin complete), then head(t-1) --
        if (t > 0) {
            if (t & 1) { mbar_wait_cluster(smbase + SMB_MBAR + 8, ph1); ph1 ^= 1; }
            else       { mbar_wait_cluster(smbase + SMB_MBAR,     ph0); ph0 ^= 1; }
            // head for step t-1: hin == hout(t-1), now complete
            do_head(hinHi, hinLo, Wo_s, bo_s, out, t - 1, b0, (int)rank, wid, lane);
        }

        // -- z = hin @ Wh_slice via mma: M=16, N=16/warp, K=256, 4 K-chains --
        {
            const uint32_t sHinHi = smem_u32(hinHi);
            const uint32_t sHinLo = smem_u32(hinLo);
            float acc[2][4][4];
            #pragma unroll
            for (int t2 = 0; t2 < 2; t2++)
                #pragma unroll
                for (int kc = 0; kc < 4; kc++)
                    #pragma unroll
                    for (int q = 0; q < 4; q++) acc[t2][kc][q] = 0.f;

            #pragma unroll
            for (int ks = 0; ks < 16; ks++) {
                const int kk0 = ks * 16;
                const int kc  = ks & 3;
                uint32_t aoff = (uint32_t)(a_row_l * HSTRIDE + kk0 + a_koff) * 2;
                uint32_t aHi[4], aLo[4];
                ldsm_x4(aHi, sHinHi + aoff);
                ldsm_x4(aLo, sHinLo + aoff);
                uint32_t boff =
                    (uint32_t)((kk0 + b_krow) * WSTRIDE + wid * 16 + b_ncol) * 2;
                uint32_t bHi[4], bLo[4];
                ldsm_x4_t(bHi, sWhHi + boff);
                ldsm_x4_t(bLo, sWhLo + boff);
                #pragma unroll
                for (int t2 = 0; t2 < 2; t2++) {
                    mma_bf16(acc[t2][kc], aHi, bHi[t2 * 2], bHi[t2 * 2 + 1]);
                    mma_bf16(acc[t2][kc], aHi, bLo[t2 * 2], bLo[t2 * 2 + 1]);
                    mma_bf16(acc[t2][kc], aLo, bHi[t2 * 2], bHi[t2 * 2 + 1]);
                }
            }
            int r0 = lane >> 2;
            int cb = wid * 16 + 2 * (lane & 3);
            #pragma unroll
            for (int t2 = 0; t2 < 2; t2++) {
                int col = cb + 8 * t2;
                float z0 = (acc[t2][0][0] + acc[t2][1][0]) + (acc[t2][2][0] + acc[t2][3][0]);
                float z1 = (acc[t2][0][1] + acc[t2][1][1]) + (acc[t2][2][1] + acc[t2][3][1]);
                float z2 = (acc[t2][0][2] + acc[t2][1][2]) + (acc[t2][2][2] + acc[t2][3][2]);
                float z3 = (acc[t2][0][3] + acc[t2][1][3]) + (acc[t2][2][3] + acc[t2][3][3]);
                *(float2*)&z_s[r0 * ZSTRIDE + col] = make_float2(z0, z1);
                *(float2*)&z_s[(r0 + 8) * ZSTRIDE + col] = make_float2(z2, z3);
            }
        }
        __syncthreads();

        // -- gating (reset folded; MUFU-free) --
        #pragma unroll
        for (int pp = 0; pp < 2; pp++) {
            int pr = tid + pp * 256;
            int b = pr >> 5, j = pr & 31;
            int ep = ep_s[t * NB + b];
            float zi = z_s[b * ZSTRIDE + j];
            float zf = z_s[b * ZSTRIDE + 32 + j];
            float zg = z_s[b * ZSTRIDE + 64 + j];
            float zo = z_s[b * ZSTRIDE + 96 + j];
            float c_old = c_s[b * 32 + j];
            if (ep) { zi = 0.f; zf = 0.f; zg = 0.f; zo = 0.f; c_old = 0.f; }
            float iz = zi + xi[pp];
            float fz = zf + xf[pp];
            float gz = zg + xg[pp];
            float oz = zo + xo[pp];
            float nc = fsig(fz) * c_old + fsig(iz) * ftanh(gz);
            float nh = fsig(oz) * ftanh(nc);
            c_s[b * 32 + j] = nc;
            __nv_bfloat16 hi = __float2bfloat16_rn(nh);
            __nv_bfloat16 lo = __float2bfloat16_rn(nh - __bfloat162float(hi));
            int hoff = b * HSTRIDE + (int)rank * 32 + j;
            houtHi[hoff] = hi;
            houtLo[hoff] = lo;
        }
        __syncthreads();

        // -- DSMEM broadcast: 16 threads per peer, one row each, then arrive --
        if (tid < 112) {
            uint32_t pbase;
            asm("mapa.shared::cluster.u32 %0, %1, %2;"
                : "=r"(pbase) : "r"(smbase), "r"(bc_p));
            uint32_t hoffHi = (uint32_t)SMB_HB + (uint32_t)p_out * HB_BUF_BYTES
                            + (uint32_t)(bc_row * HSTRIDE + (int)rank * 32) * 2;
            uint32_t hoffLo = hoffHi + (uint32_t)(NB * HSTRIDE) * 2;
            const uint4* srcHi = (const uint4*)(smraw + hoffHi);
            const uint4* srcLo = (const uint4*)(smraw + hoffLo);
            #pragma unroll
            for (int s4 = 0; s4 < 4; s4++) {
                uint4 v = srcHi[s4];
                st_cluster_v4(pbase + hoffHi + s4 * 16, v.x, v.y, v.z, v.w);
            }
            #pragma unroll
            for (int s4 = 0; s4 < 4; s4++) {
                uint4 v = srcLo[s4];
                st_cluster_v4(pbase + hoffLo + s4 * 16, v.x, v.y, v.z, v.w);
            }
            uint32_t mb = pbase + SMB_MBAR + (uint32_t)(((t + 1) & 1) * 8);
            asm volatile(
                "mbarrier.arrive.release.cluster.shared::cluster.b64 _, [%0];"
                :: "r"(mb) : "memory");
        }
    }

    // final wait + head for t = 511
    {
        mbar_wait_cluster(smbase + SMB_MBAR, ph0);   // mbar[512&1=0]
        __nv_bfloat16* hHi = (__nv_bfloat16*)(smraw + SMB_HB + 1 * HB_BUF_BYTES);
        __nv_bfloat16* hLo = hHi + NB * HSTRIDE;
        do_head(hHi, hLo, Wo_s, bo_s, out, T_STEPS - 1, b0, (int)rank, wid, lane);
    }

    // cluster-safe exit
    asm volatile("barrier.cluster.arrive.aligned;" ::: "memory");
    asm volatile("barrier.cluster.wait.aligned;"   ::: "memory");
}

// ---------------------------------------------------------------------------
extern "C" void kernel_launch(void* const* d_in, const int* in_sizes, int n_in,
                              void* d_out, int out_size) {
    const float* inputs  = (const float*)d_in[0];
    const int*   epi     = (const int*)  d_in[1];
    const float* carry_c = (const float*)d_in[2];
    const float* carry_h = (const float*)d_in[3];
    const float* Wx      = (const float*)d_in[4];
    const float* Wh      = (const float*)d_in[5];
    const float* bias    = (const float*)d_in[6];
    const float* Wa      = (const float*)d_in[7];
    const float* ba      = (const float*)d_in[8];
    const float* Wv      = (const float*)d_in[9];
    const float* bv      = (const float*)d_in[10];
    float* out = (float*)d_out;

    cudaFuncSetAttribute(xproj_mma_kernel,
                         cudaFuncAttributeMaxDynamicSharedMemorySize, XSMEM_BYTES);
    cudaFuncSetAttribute(lstm_rec_kernel,
                         cudaFuncAttributeMaxDynamicSharedMemorySize, RSMEM_BYTES);

    dim3 g1(FOURH / XBN, (T_STEPS * BATCH) / XBM);
    xproj_mma_kernel<<<g1, 256, XSMEM_BYTES>>>(inputs, Wx, bias);

    lstm_rec_kernel<<<(BATCH / NB) * CLUSTER, RTHREADS, RSMEM_BYTES>>>(
        epi, carry_c, carry_h, Wh, Wa, ba, Wv, bv, out);
}

// round 7
// speedup vs baseline: 1.0932x; 1.0295x over previous
#include <cuda_runtime.h>
#include <cuda_bf16.h>
#include <cstdint>
#include <cstddef>

// Problem dims
#define T_STEPS 512
#define BATCH   256
#define DIM     512
#define HID     256
#define FOURH   1024
#define NACT    32
#define OUTC    33

// Scratch for x_proj: [T, B, 4H] fp32
__device__ float g_xproj[(size_t)T_STEPS * BATCH * FOURH];

// ===========================================================================
// Shared helpers
// ===========================================================================
__device__ __forceinline__ uint32_t smem_u32(const void* p) {
    uint32_t a;
    asm("{ .reg .u64 t; cvta.to.shared.u64 t, %1; cvt.u32.u64 %0, t; }"
        : "=r"(a) : "l"(p));
    return a;
}
__device__ __forceinline__ void ldsm_x4(uint32_t* r, uint32_t addr) {
    asm volatile("ldmatrix.sync.aligned.m8n8.x4.shared.b16 {%0,%1,%2,%3}, [%4];"
        : "=r"(r[0]), "=r"(r[1]), "=r"(r[2]), "=r"(r[3]) : "r"(addr));
}
__device__ __forceinline__ void ldsm_x4_t(uint32_t* r, uint32_t addr) {
    asm volatile("ldmatrix.sync.aligned.m8n8.x4.trans.shared.b16 {%0,%1,%2,%3}, [%4];"
        : "=r"(r[0]), "=r"(r[1]), "=r"(r[2]), "=r"(r[3]) : "r"(addr));
}
__device__ __forceinline__ void ldsm_x2_t(uint32_t* r, uint32_t addr) {
    asm volatile("ldmatrix.sync.aligned.m8n8.x2.trans.shared.b16 {%0,%1}, [%2];"
        : "=r"(r[0]), "=r"(r[1]) : "r"(addr));
}
__device__ __forceinline__ void mma_bf16(float* c, const uint32_t* a,
                                         uint32_t b0, uint32_t b1) {
    asm volatile(
        "mma.sync.aligned.m16n8k16.row.col.f32.bf16.bf16.f32 "
        "{%0,%1,%2,%3}, {%4,%5,%6,%7}, {%8,%9}, {%0,%1,%2,%3};"
        : "+f"(c[0]), "+f"(c[1]), "+f"(c[2]), "+f"(c[3])
        : "r"(a[0]), "r"(a[1]), "r"(a[2]), "r"(a[3]), "r"(b0), "r"(b1));
}
__device__ __forceinline__ uint32_t pack2(__nv_bfloat16 a, __nv_bfloat16 b) {
    union { __nv_bfloat162 v; uint32_t u; } c;
    c.v = __nv_bfloat162(a, b);
    return c.u;
}
__device__ __forceinline__ void split_store4(float4 v,
                                             __nv_bfloat16* hip,
                                             __nv_bfloat16* lop) {
    __nv_bfloat16 h0 = __float2bfloat16_rn(v.x);
    __nv_bfloat16 h1 = __float2bfloat16_rn(v.y);
    __nv_bfloat16 h2 = __float2bfloat16_rn(v.z);
    __nv_bfloat16 h3 = __float2bfloat16_rn(v.w);
    __nv_bfloat16 l0 = __float2bfloat16_rn(v.x - __bfloat162float(h0));
    __nv_bfloat16 l1 = __float2bfloat16_rn(v.y - __bfloat162float(h1));
    __nv_bfloat16 l2 = __float2bfloat16_rn(v.z - __bfloat162float(h2));
    __nv_bfloat16 l3 = __float2bfloat16_rn(v.w - __bfloat162float(h3));
    ((uint32_t*)hip)[0] = pack2(h0, h1);
    ((uint32_t*)hip)[1] = pack2(h2, h3);
    ((uint32_t*)lop)[0] = pack2(l0, l1);
    ((uint32_t*)lop)[1] = pack2(l2, l3);
}

// ---- MUFU-free activations ----
__device__ __forceinline__ float fast_exp(float x) {
    const float L2E = 1.4426950408889634f;
    float t  = fmaf(x, L2E, 12582912.0f);
    int   n  = __float_as_int(t) - 0x4B400000;
    float nf = t - 12582912.0f;
    float r  = fmaf(nf, -0.693359375f, x);
    r = fmaf(nf, 2.12194440e-4f, r);
    float p = 1.9841270e-4f;
    p = fmaf(p, r, 1.3888889e-3f);
    p = fmaf(p, r, 8.3333333e-3f);
    p = fmaf(p, r, 4.1666667e-2f);
    p = fmaf(p, r, 1.6666667e-1f);
    p = fmaf(p, r, 0.5f);
    p = fmaf(p, r, 1.0f);
    p = fmaf(p, r, 1.0f);
    return __int_as_float(__float_as_int(p) + (n << 23));
}
__device__ __forceinline__ float fast_rcp(float d) {
    float r = __int_as_float(0x7EF127EAu - __float_as_int(d));
    r = r * fmaf(-d, r, 2.0f);
    r = r * fmaf(-d, r, 2.0f);
    return r;
}
__device__ __forceinline__ float fsig(float x) {
    x = fminf(fmaxf(x, -30.0f), 30.0f);
    float e = fast_exp(-x);
    return fast_rcp(1.0f + e);
}
__device__ __forceinline__ float ftanh(float x) {
    return fmaf(2.0f, fsig(2.0f * x), -1.0f);
}

// ===========================================================================
// Kernel 1: x_proj = inputs @ Wx + b (unchanged — measured ~1.2 ms)
// ===========================================================================
#define XBM 128
#define XBN 128
#define XBK 32
#define KPA 40
#define NPB 136
#define A_TERM_ELEMS (XBM * KPA)
#define B_TERM_ELEMS (XBK * NPB)
#define STAGE_ELEMS  (2 * A_TERM_ELEMS + 2 * B_TERM_ELEMS)
#define XSMEM_BYTES  (2 * STAGE_ELEMS * 2)

__global__ __launch_bounds__(256) void xproj_mma_kernel(
    const float* __restrict__ A,
    const float* __restrict__ W,
    const float* __restrict__ bias)
{
    extern __shared__ __nv_bfloat16 xsm[];

    const int tid   = threadIdx.x;
    const int lane  = tid & 31;
    const int wid   = tid >> 5;
    const int warpM = wid & 3;
    const int warpN = wid >> 2;
    const int bM    = blockIdx.y;
    const int bN    = blockIdx.x;

    const int arow0 = tid >> 3;
    const int ac4   = tid & 7;
    const int bkr0  = tid >> 5;
    const int bn4   = tid & 31;

    const float* Ag = A + (size_t)bM * XBM * DIM;
    const float* Wg = W + (size_t)bN * XBN;

    float acc[2][8][4];
    #pragma unroll
    for (int mt = 0; mt < 2; mt++)
        #pragma unroll
        for (int j = 0; j < 8; j++)
            #pragma unroll
            for (int q = 0; q < 4; q++) acc[mt][j][q] = 0.f;

    const int a_row_l = (lane & 15);
    const int a_koff  = ((lane >> 4) << 3);
    const int b_krow  = (lane & 7) + ((lane >> 3) & 1) * 8;
    const int b_ncol  = ((lane >> 4) & 1) * 8;

    float4 aReg[4], bReg[4];

    #pragma unroll
    for (int i = 0; i < 4; i++) {
        aReg[i] = *(const float4*)(Ag + (size_t)(arow0 + 32 * i) * DIM + ac4 * 4);
        bReg[i] = *(const float4*)(Wg + (size_t)(bkr0 + 8 * i) * FOURH + bn4 * 4);
    }
    {
        __nv_bfloat16* Ahi = xsm;
        __nv_bfloat16* Alo = Ahi + A_TERM_ELEMS;
        __nv_bfloat16* Bhi = Alo + A_TERM_ELEMS;
        __nv_bfloat16* Blo = Bhi + B_TERM_ELEMS;
        #pragma unroll
        for (int i = 0; i < 4; i++) {
            int ar = arow0 + 32 * i;
            split_store4(aReg[i], &Ahi[ar * KPA + ac4 * 4], &Alo[ar * KPA + ac4 * 4]);
            int bk = bkr0 + 8 * i;
            split_store4(bReg[i], &Bhi[bk * NPB + bn4 * 4], &Blo[bk * NPB + bn4 * 4]);
        }
    }
    __syncthreads();

    const int NSTAGE = DIM / XBK;

    for (int s = 0; s < NSTAGE; s++) {
        if (s + 1 < NSTAGE) {
            int k0 = (s + 1) * XBK;
            #pragma unroll
            for (int i = 0; i < 4; i++) {
                aReg[i] = *(const float4*)(Ag + (size_t)(arow0 + 32 * i) * DIM + k0 + ac4 * 4);
                bReg[i] = *(const float4*)(Wg + (size_t)(k0 + bkr0 + 8 * i) * FOURH + bn4 * 4);
            }
        }

        const __nv_bfloat16* st = xsm + (s & 1) * STAGE_ELEMS;
        uint32_t sAhi = smem_u32(st);
        uint32_t sAlo = sAhi + A_TERM_ELEMS * 2;
        uint32_t sBhi = sAlo + A_TERM_ELEMS * 2;
        uint32_t sBlo = sBhi + B_TERM_ELEMS * 2;

        #pragma unroll
        for (int ks = 0; ks < 2; ks++) {
            const int kk0 = ks * 16;
            uint32_t aHi[2][4], aLo[2][4];
            #pragma unroll
            for (int mt = 0; mt < 2; mt++) {
                uint32_t off =
                    (uint32_t)((warpM * 32 + mt * 16 + a_row_l) * KPA + kk0 + a_koff) * 2;
                ldsm_x4(aHi[mt], sAhi + off);
                ldsm_x4(aLo[mt], sAlo + off);
            }
            uint32_t bHi[4][4], bLo[4][4];
            #pragma unroll
            for (int nt = 0; nt < 4; nt++) {
                uint32_t off =
                    (uint32_t)((kk0 + b_krow) * NPB + warpN * 64 + nt * 16 + b_ncol) * 2;
                ldsm_x4_t(bHi[nt], sBhi + off);
                ldsm_x4_t(bLo[nt], sBlo + off);
            }
            #pragma unroll
            for (int mt = 0; mt < 2; mt++) {
                #pragma unroll
                for (int j = 0; j < 8; j++) {
                    uint32_t bh0 = bHi[j >> 1][(j & 1) * 2];
                    uint32_t bh1 = bHi[j >> 1][(j & 1) * 2 + 1];
                    uint32_t bl0 = bLo[j >> 1][(j & 1) * 2];
                    uint32_t bl1 = bLo[j >> 1][(j & 1) * 2 + 1];
                    mma_bf16(acc[mt][j], aHi[mt], bh0, bh1);
                    mma_bf16(acc[mt][j], aHi[mt], bl0, bl1);
                    mma_bf16(acc[mt][j], aLo[mt], bh0, bh1);
                }
            }
        }

        if (s + 1 < NSTAGE) {
            __nv_bfloat16* dst = xsm + ((s + 1) & 1) * STAGE_ELEMS;
            __nv_bfloat16* Ahi = dst;
            __nv_bfloat16* Alo = Ahi + A_TERM_ELEMS;
            __nv_bfloat16* Bhi = Alo + A_TERM_ELEMS;
            __nv_bfloat16* Blo = Bhi + B_TERM_ELEMS;
            #pragma unroll
            for (int i = 0; i < 4; i++) {
                int ar = arow0 + 32 * i;
                split_store4(aReg[i], &Ahi[ar * KPA + ac4 * 4], &Alo[ar * KPA + ac4 * 4]);
                int bk = bkr0 + 8 * i;
                split_store4(bReg[i], &Bhi[bk * NPB + bn4 * 4], &Blo[bk * NPB + bn4 * 4]);
            }
        }
        __syncthreads();
    }

    const int g  = lane >> 2;
    const int t2 = (lane & 3) * 2;
    #pragma unroll
    for (int mt = 0; mt < 2; mt++) {
        int row = bM * XBM + warpM * 32 + mt * 16 + g;
        #pragma unroll
        for (int j = 0; j < 8; j++) {
            int col = bN * XBN + warpN * 64 + j * 8 + t2;
            float b0 = bias[col], b1 = bias[col + 1];
            float2 o0 = make_float2(acc[mt][j][0] + b0, acc[mt][j][1] + b1);
            float2 o1 = make_float2(acc[mt][j][2] + b0, acc[mt][j][3] + b1);
            *(float2*)&g_xproj[(size_t)row * FOURH + col] = o0;
            *(float2*)&g_xproj[(size_t)(row + 8) * FOURH + col] = o1;
        }
    }
}

// ===========================================================================
// Kernel 2: recurrent kernel — head folded into the mma ([Wh | Wo] concat),
// mbarrier cluster sync, 256 threads.
// ===========================================================================
#define CLUSTER 8
#define NB      16
#define LC      128
#define RTHREADS 256

#define HSTRIDE 264
#define WSTRIDE 136      // cols 0..127 = Wh slice, cols 128..135 = head cols
#define ZSTRIDE 140      // cols 0..127 = z, cols 128..132 = head out

#define SMB_WHHI 0
#define SMB_WHLO (SMB_WHHI + 256 * WSTRIDE * 2)        // 69632
#define SMB_HB   (SMB_WHLO + 256 * WSTRIDE * 2)        // 139264
#define HB_ARR_BYTES (NB * HSTRIDE * 2)                 // 8448
#define HB_BUF_BYTES (2 * HB_ARR_BYTES)                 // 16896
#define SMB_Z    (SMB_HB + 2 * HB_BUF_BYTES)            // 173056
#define SMB_C    (SMB_Z + NB * ZSTRIDE * 4)             // 182016
#define SMB_WO   (SMB_C + NB * 32 * 4)                  // 184064
#define SMB_BO   (SMB_WO + 5 * 256 * 4)                 // 189184
#define SMB_MBAR (SMB_BO + 32)                          // 189216
#define SMB_EP   (SMB_MBAR + 16)                        // 189232
#define RSMEM_BYTES (SMB_EP + T_STEPS * NB * 4)         // 222000

#define MBAR_COUNT 112   // 16 threads x 7 peer CTAs

__device__ __forceinline__ void st_cluster_v4(uint32_t saddr,
                                              uint32_t a, uint32_t b,
                                              uint32_t c, uint32_t d) {
    asm volatile("st.shared::cluster.v4.b32 [%0], {%1,%2,%3,%4};"
        :: "r"(saddr), "r"(a), "r"(b), "r"(c), "r"(d) : "memory");
}

__device__ __forceinline__ void mbar_wait_cluster(uint32_t mbar, uint32_t parity) {
    uint32_t done;
    asm volatile(
        "{ .reg .pred p;\n"
        " mbarrier.try_wait.parity.acquire.cluster.shared::cta.b64 p, [%1], %2;\n"
        " selp.b32 %0, 1, 0, p; }"
        : "=r"(done) : "r"(mbar), "r"(parity) : "memory");
    while (!done) {
        asm volatile(
            "{ .reg .pred p;\n"
            " mbarrier.try_wait.parity.acquire.cluster.shared::cta.b64 p, [%1], %2, 0x989680;\n"
            " selp.b32 %0, 1, 0, p; }"
            : "=r"(done) : "r"(mbar), "r"(parity) : "memory");
    }
}

// fp32 output head (used ONCE for the final timestep only)
__device__ __forceinline__ void do_head(
    const __nv_bfloat16* hHi, const __nv_bfloat16* hLo,
    const float* Wo_s, const float* bo_s,
    float* out, int tt, int b0, int rank, int wid, int lane)
{
    float sacc[8];
    #pragma unroll
    for (int u = 0; u < 8; u++) {
        int task = wid + 8 * u;
        int q = task >> 4;
        int b = task & 15;
        const __nv_bfloat16* hHr = &hHi[b * HSTRIDE];
        const __nv_bfloat16* hLr = &hLo[b * HSTRIDE];
        const float* wcol = &Wo_s[q * 256];
        float s = 0.f;
        #pragma unroll
        for (int uu = 0; uu < 8; uu++) {
            int k = lane + 32 * uu;
            float hv = __bfloat162float(hHr[k]) + __bfloat162float(hLr[k]);
            s = fmaf(hv, wcol[k], s);
        }
        sacc[u] = s;
    }
    #pragma unroll
    for (int u = 0; u < 8; u++) {
        float s = sacc[u];
        #pragma unroll
        for (int off = 16; off; off >>= 1)
            s += __shfl_xor_sync(0xFFFFFFFFu, s, off);
        if (lane == 0) {
            int task = wid + 8 * u;
            int q = task >> 4;
            int b = task & 15;
            int col = rank + 8 * q;
            out[((size_t)tt * BATCH + b0 + b) * OUTC + col] = s + bo_s[q];
        }
    }
    if (rank == 0) {
        #pragma unroll
        for (int u = 0; u < 2; u++) {
            int b = wid + 8 * u;
            const __nv_bfloat16* hHr = &hHi[b * HSTRIDE];
            const __nv_bfloat16* hLr = &hLo[b * HSTRIDE];
            const float* wcol = &Wo_s[4 * 256];
            float s = 0.f;
            #pragma unroll
            for (int uu = 0; uu < 8; uu++) {
                int k = lane + 32 * uu;
                float hv = __bfloat162float(hHr[k]) + __bfloat162float(hLr[k]);
                s = fmaf(hv, wcol[k], s);
            }
            #pragma unroll
            for (int off = 16; off; off >>= 1)
                s += __shfl_xor_sync(0xFFFFFFFFu, s, off);
            if (lane == 0)
                out[((size_t)tt * BATCH + b0 + b) * OUTC + 32] = s + bo_s[4];
        }
    }
}

__global__ void __cluster_dims__(CLUSTER, 1, 1) __launch_bounds__(RTHREADS, 1)
lstm_rec_kernel(const int*   __restrict__ epi,
                const float* __restrict__ carry_c,
                const float* __restrict__ carry_h,
                const float* __restrict__ Wh,
                const float* __restrict__ Wa,
                const float* __restrict__ ba,
                const float* __restrict__ Wv,
                const float* __restrict__ bv,
                float*       __restrict__ out)
{
    extern __shared__ char smraw[];
    __nv_bfloat16* WhHi = (__nv_bfloat16*)(smraw + SMB_WHHI);
    __nv_bfloat16* WhLo = (__nv_bfloat16*)(smraw + SMB_WHLO);
    float* z_s  = (float*)(smraw + SMB_Z);
    float* c_s  = (float*)(smraw + SMB_C);
    float* Wo_s = (float*)(smraw + SMB_WO);
    float* bo_s = (float*)(smraw + SMB_BO);
    int*   ep_s = (int*)  (smraw + SMB_EP);

    const int tid  = threadIdx.x;
    const int lane = tid & 31;
    const int wid  = tid >> 5;            // 0..7
    uint32_t rank;
    asm("mov.u32 %0, %%cluster_ctarank;" : "=r"(rank));
    const int cl = blockIdx.x / CLUSTER;
    const int b0 = cl * NB;
    const uint32_t smbase = smem_u32(smraw);

    // --- init mbarriers ---
    if (tid == 0) {
        asm volatile("mbarrier.init.shared.b64 [%0], %1;"
            :: "r"(smbase + SMB_MBAR), "r"((uint32_t)MBAR_COUNT) : "memory");
        asm volatile("mbarrier.init.shared.b64 [%0], %1;"
            :: "r"(smbase + SMB_MBAR + 8), "r"((uint32_t)MBAR_COUNT) : "memory");
    }

    // --- preload Wh slice (split bf16), cols 0..127 ---
    for (int idx = tid; idx < 256 * LC; idx += RTHREADS) {
        int k = idx >> 7;
        int c = idx & 127;
        int gcol = ((c >> 5) << 8) + ((int)rank << 5) + (c & 31);
        float w = Wh[k * FOURH + gcol];
        __nv_bfloat16 hi = __float2bfloat16_rn(w);
        __nv_bfloat16 lo = __float2bfloat16_rn(w - __bfloat162float(hi));
        WhHi[k * WSTRIDE + c] = hi;
        WhLo[k * WSTRIDE + c] = lo;
    }
    // --- preload head columns into cols 128..135 of the same B matrix ---
    // col 128+q (q=0..3): Wa column (rank + 8q); col 132: Wv (rank 0 only);
    // cols 133..135 (and 132 on rank!=0): zero.
    for (int idx = tid; idx < 256 * 8; idx += RTHREADS) {
        int k = idx >> 3;
        int c = idx & 7;
        float w = 0.f;
        if (c < 4)           w = Wa[k * NACT + (int)rank + 8 * c];
        else if (c == 4 && rank == 0) w = Wv[k];
        __nv_bfloat16 hi = __float2bfloat16_rn(w);
        __nv_bfloat16 lo = __float2bfloat16_rn(w - __bfloat162float(hi));
        WhHi[k * WSTRIDE + 128 + c] = hi;
        WhLo[k * WSTRIDE + 128 + c] = lo;
    }
    // --- preload carry_h into buffer 1 (input for t=0), split bf16 ---
    for (int idx = tid; idx < NB * HID; idx += RTHREADS) {
        int b = idx >> 8;
        int k = idx & 255;
        float v = carry_h[(size_t)(b0 + b) * HID + k];
        __nv_bfloat16 hi = __float2bfloat16_rn(v);
        __nv_bfloat16 lo = __float2bfloat16_rn(v - __bfloat162float(hi));
        __nv_bfloat16* hHi = (__nv_bfloat16*)(smraw + SMB_HB + 1 * HB_BUF_BYTES);
        __nv_bfloat16* hLo = hHi + NB * HSTRIDE;
        hHi[b * HSTRIDE + k] = hi;
        hLo[b * HSTRIDE + k] = lo;
    }
    // --- preload carry_c slice ---
    for (int idx = tid; idx < NB * 32; idx += RTHREADS) {
        int b = idx >> 5;
        int j = idx & 31;
        c_s[idx] = carry_c[(size_t)(b0 + b) * HID + (int)rank * 32 + j];
    }
    // --- preload output-head columns (fp32, for final-step do_head) ---
    #pragma unroll
    for (int q = 0; q < 5; q++) {
        int col = (int)rank + 8 * q;
        if (col <= 32) {
            for (int k = tid; k < HID; k += RTHREADS)
                Wo_s[q * 256 + k] = (col < 32) ? Wa[k * NACT + col] : Wv[k];
            if (tid == 0) bo_s[q] = (col < 32) ? ba[col] : bv[0];
        }
    }
    // --- preload epi slice ---
    for (int idx = tid; idx < T_STEPS * NB; idx += RTHREADS) {
        int t = idx >> 4;
        int b = idx & 15;
        ep_s[idx] = epi[t * BATCH + b0 + b];
    }
    __syncthreads();
    asm volatile("barrier.cluster.arrive.aligned;" ::: "memory");
    asm volatile("barrier.cluster.wait.aligned;"   ::: "memory");

    // frag geometry
    const int a_row_l = (lane & 15);
    const int a_koff  = ((lane >> 4) << 3);
    const int b_krow  = (lane & 7) + ((lane >> 3) & 1) * 8;
    const int b_ncol  = ((lane >> 4) & 1) * 8;

    const uint32_t sWhHi = smem_u32(WhHi);
    const uint32_t sWhLo = smem_u32(WhLo);

    int ph0 = 0, ph1 = 0;

    const int bc_pp  = tid >> 4;
    const int bc_p   = bc_pp + (bc_pp >= (int)rank);
    const int bc_row = tid & 15;

    for (int t = 0; t < T_STEPS; t++) {
        const int p_out = t & 1;
        const int p_in  = p_out ^ 1;
        __nv_bfloat16* hinHi  = (__nv_bfloat16*)(smraw + SMB_HB + p_in * HB_BUF_BYTES);
        __nv_bfloat16* hinLo  = hinHi + NB * HSTRIDE;
        __nv_bfloat16* houtHi = (__nv_bfloat16*)(smraw + SMB_HB + p_out * HB_BUF_BYTES);
        __nv_bfloat16* houtLo = houtHi + NB * HSTRIDE;

        // -- prefetch x_proj gate values (before the wait; hidden by it) --
        float xi[2], xf[2], xg[2], xo[2];
        #pragma unroll
        for (int pp = 0; pp < 2; pp++) {
            int pr = tid + pp * 256;
            int b = pr >> 5, j = pr & 31;
            size_t base = (size_t)t * BATCH * FOURH
                        + (size_t)(b0 + b) * FOURH + (int)rank * 32 + j;
            xi[pp] = g_xproj[base];
            xf[pp] = g_xproj[base + 256];
            xg[pp] = g_xproj[base + 512];
            xo[pp] = g_xproj[base + 768];
        }

        // -- wait for peers' h slices (hin complete) --
        if (t > 0) {
            if (t & 1) { mbar_wait_cluster(smbase + SMB_MBAR + 8, ph1); ph1 ^= 1; }
            else       { mbar_wait_cluster(smbase + SMB_MBAR,     ph0); ph0 ^= 1; }
        }

        // -- mma: z(t) = hin @ Wh_slice (N=16/warp) + head(t-1) tile (warp 0) --
        {
            const uint32_t sHinHi = smem_u32(hinHi);
            const uint32_t sHinLo = smem_u32(hinLo);
            float acc[2][4][4];
            float accH[2][4];
            #pragma unroll
            for (int t2 = 0; t2 < 2; t2++) {
                #pragma unroll
                for (int kc = 0; kc < 4; kc++)
                    #pragma unroll
                    for (int q = 0; q < 4; q++) acc[t2][kc][q] = 0.f;
                #pragma unroll
                for (int q = 0; q < 4; q++) accH[t2][q] = 0.f;
            }

            #pragma unroll
            for (int ks = 0; ks < 16; ks++) {
                const int kk0 = ks * 16;
                const int kc  = ks & 3;
                uint32_t aoff = (uint32_t)(a_row_l * HSTRIDE + kk0 + a_koff) * 2;
                uint32_t aHi[4], aLo[4];
                ldsm_x4(aHi, sHinHi + aoff);
                ldsm_x4(aLo, sHinLo + aoff);
                uint32_t boff =
                    (uint32_t)((kk0 + b_krow) * WSTRIDE + wid * 16 + b_ncol) * 2;
                uint32_t bHi[4], bLo[4];
                ldsm_x4_t(bHi, sWhHi + boff);
                ldsm_x4_t(bLo, sWhLo + boff);
                #pragma unroll
                for (int t2 = 0; t2 < 2; t2++) {
                    mma_bf16(acc[t2][kc], aHi, bHi[t2 * 2], bHi[t2 * 2 + 1]);
                    mma_bf16(acc[t2][kc], aHi, bLo[t2 * 2], bLo[t2 * 2 + 1]);
                    mma_bf16(acc[t2][kc], aLo, bHi[t2 * 2], bHi[t2 * 2 + 1]);
                }
                if (wid == 0) {
                    // head tile: cols 128..135, reuse A fragments
                    uint32_t hoff = (uint32_t)((kk0 + b_krow) * WSTRIDE + 128) * 2;
                    uint32_t hH[2], hL[2];
                    ldsm_x2_t(hH, sWhHi + hoff);
                    ldsm_x2_t(hL, sWhLo + hoff);
                    const int kc2 = ks & 1;
                    mma_bf16(accH[kc2], aHi, hH[0], hH[1]);
                    mma_bf16(accH[kc2], aHi, hL[0], hL[1]);
                    mma_bf16(accH[kc2], aLo, hH[0], hH[1]);
                }
            }
            int r0 = lane >> 2;
            int cb = wid * 16 + 2 * (lane & 3);
            #pragma unroll
            for (int t2 = 0; t2 < 2; t2++) {
                int col = cb + 8 * t2;
                float z0 = (acc[t2][0][0] + acc[t2][1][0]) + (acc[t2][2][0] + acc[t2][3][0]);
                float z1 = (acc[t2][0][1] + acc[t2][1][1]) + (acc[t2][2][1] + acc[t2][3][1]);
                float z2 = (acc[t2][0][2] + acc[t2][1][2]) + (acc[t2][2][2] + acc[t2][3][2]);
                float z3 = (acc[t2][0][3] + acc[t2][1][3]) + (acc[t2][2][3] + acc[t2][3][3]);
                *(float2*)&z_s[r0 * ZSTRIDE + col] = make_float2(z0, z1);
                *(float2*)&z_s[(r0 + 8) * ZSTRIDE + col] = make_float2(z2, z3);
            }
            if (wid == 0) {
                int colH = 128 + 2 * (lane & 3);
                float h0 = accH[0][0] + accH[1][0];
                float h1 = accH[0][1] + accH[1][1];
                float h2 = accH[0][2] + accH[1][2];
                float h3 = accH[0][3] + accH[1][3];
                *(float2*)&z_s[r0 * ZSTRIDE + colH] = make_float2(h0, h1);
                *(float2*)&z_s[(r0 + 8) * ZSTRIDE + colH] = make_float2(h2, h3);
            }
        }
        __syncthreads();

        // -- write out(t-1) from the head z columns --
        if (t > 0) {
            if (tid < 64) {
                int b = tid >> 2, q = tid & 3;
                out[((size_t)(t - 1) * BATCH + b0 + b) * OUTC + (int)rank + 8 * q]
                    = z_s[b * ZSTRIDE + 128 + q] + bo_s[q];
            } else if (rank == 0 && tid < 80) {
                int b = tid - 64;
                out[((size_t)(t - 1) * BATCH + b0 + b) * OUTC + 32]
                    = z_s[b * ZSTRIDE + 132] + bo_s[4];
            }
        }

        // -- gating (reset folded; MUFU-free) --
        #pragma unroll
        for (int pp = 0; pp < 2; pp++) {
            int pr = tid + pp * 256;
            int b = pr >> 5, j = pr & 31;
            int ep = ep_s[t * NB + b];
            float zi = z_s[b * ZSTRIDE + j];
            float zf = z_s[b * ZSTRIDE + 32 + j];
            float zg = z_s[b * ZSTRIDE + 64 + j];
            float zo = z_s[b * ZSTRIDE + 96 + j];
            float c_old = c_s[b * 32 + j];
            if (ep) { zi = 0.f; zf = 0.f; zg = 0.f; zo = 0.f; c_old = 0.f; }
            float iz = zi + xi[pp];
            float fz = zf + xf[pp];
            float gz = zg + xg[pp];
            float oz = zo + xo[pp];
            float nc = fsig(fz) * c_old + fsig(iz) * ftanh(gz);
            float nh = fsig(oz) * ftanh(nc);
            c_s[b * 32 + j] = nc;
            __nv_bfloat16 hi = __float2bfloat16_rn(nh);
            __nv_bfloat16 lo = __float2bfloat16_rn(nh - __bfloat162float(hi));
            int hoff = b * HSTRIDE + (int)rank * 32 + j;
            houtHi[hoff] = hi;
            houtLo[hoff] = lo;
        }
        __syncthreads();

        // -- DSMEM broadcast: 16 threads per peer, one row each, then arrive --
        if (tid < 112) {
            uint32_t pbase;
            asm("mapa.shared::cluster.u32 %0, %1, %2;"
                : "=r"(pbase) : "r"(smbase), "r"(bc_p));
            uint32_t hoffHi = (uint32_t)SMB_HB + (uint32_t)p_out * HB_BUF_BYTES
                            + (uint32_t)(bc_row * HSTRIDE + (int)rank * 32) * 2;
            uint32_t hoffLo = hoffHi + (uint32_t)(NB * HSTRIDE) * 2;
            const uint4* srcHi = (const uint4*)(smraw + hoffHi);
            const uint4* srcLo = (const uint4*)(smraw + hoffLo);
            #pragma unroll
            for (int s4 = 0; s4 < 4; s4++) {
                uint4 v = srcHi[s4];
                st_cluster_v4(pbase + hoffHi + s4 * 16, v.x, v.y, v.z, v.w);
            }
            #pragma unroll
            for (int s4 = 0; s4 < 4; s4++) {
                uint4 v = srcLo[s4];
                st_cluster_v4(pbase + hoffLo + s4 * 16, v.x, v.y, v.z, v.w);
            }
            uint32_t mb = pbase + SMB_MBAR + (uint32_t)(((t + 1) & 1) * 8);
            asm volatile(
                "mbarrier.arrive.release.cluster.shared::cluster.b64 _, [%0];"
                :: "r"(mb) : "memory");
        }
    }

    // final wait + fp32 head for t = 511
    {
        mbar_wait_cluster(smbase + SMB_MBAR, ph0);
        __nv_bfloat16* hHi = (__nv_bfloat16*)(smraw + SMB_HB + 1 * HB_BUF_BYTES);
        __nv_bfloat16* hLo = hHi + NB * HSTRIDE;
        do_head(hHi, hLo, Wo_s, bo_s, out, T_STEPS - 1, b0, (int)rank, wid, lane);
    }

    asm volatile("barrier.cluster.arrive.aligned;" ::: "memory");
    asm volatile("barrier.cluster.wait.aligned;"   ::: "memory");
}

// ---------------------------------------------------------------------------
extern "C" void kernel_launch(void* const* d_in, const int* in_sizes, int n_in,
                              void* d_out, int out_size) {
    const float* inputs  = (const float*)d_in[0];
    const int*   epi     = (const int*)  d_in[1];
    const float* carry_c = (const float*)d_in[2];
    const float* carry_h = (const float*)d_in[3];
    const float* Wx      = (const float*)d_in[4];
    const float* Wh      = (const float*)d_in[5];
    const float* bias    = (const float*)d_in[6];
    const float* Wa      = (const float*)d_in[7];
    const float* ba      = (const float*)d_in[8];
    const float* Wv      = (const float*)d_in[9];
    const float* bv      = (const float*)d_in[10];
    float* out = (float*)d_out;

    cudaFuncSetAttribute(xproj_mma_kernel,
                         cudaFuncAttributeMaxDynamicSharedMemorySize, XSMEM_BYTES);
    cudaFuncSetAttribute(lstm_rec_kernel,
                         cudaFuncAttributeMaxDynamicSharedMemorySize, RSMEM_BYTES);

    dim3 g1(FOURH / XBN, (T_STEPS * BATCH) / XBM);
    xproj_mma_kernel<<<g1, 256, XSMEM_BYTES>>>(inputs, Wx, bias);

    lstm_rec_kernel<<<(BATCH / NB) * CLUSTER, RTHREADS, RSMEM_BYTES>>>(
        epi, carry_c, carry_h, Wh, Wa, ba, Wv, bv, out);
}

// round 8
// speedup vs baseline: 1.1427x; 1.0453x over previous
#include <cuda_runtime.h>
#include <cuda_bf16.h>
#include <cstdint>
#include <cstddef>

// Problem dims
#define T_STEPS 512
#define BATCH   256
#define DIM     512
#define HID     256
#define FOURH   1024
#define NACT    32
#define OUTC    33

// Scratch for x_proj: [T, B, 4H] fp32
__device__ float g_xproj[(size_t)T_STEPS * BATCH * FOURH];

// ===========================================================================
// Shared helpers
// ===========================================================================
__device__ __forceinline__ uint32_t smem_u32(const void* p) {
    uint32_t a;
    asm("{ .reg .u64 t; cvta.to.shared.u64 t, %1; cvt.u32.u64 %0, t; }"
        : "=r"(a) : "l"(p));
    return a;
}
__device__ __forceinline__ void ldsm_x4(uint32_t* r, uint32_t addr) {
    asm volatile("ldmatrix.sync.aligned.m8n8.x4.shared.b16 {%0,%1,%2,%3}, [%4];"
        : "=r"(r[0]), "=r"(r[1]), "=r"(r[2]), "=r"(r[3]) : "r"(addr));
}
__device__ __forceinline__ void ldsm_x4_t(uint32_t* r, uint32_t addr) {
    asm volatile("ldmatrix.sync.aligned.m8n8.x4.trans.shared.b16 {%0,%1,%2,%3}, [%4];"
        : "=r"(r[0]), "=r"(r[1]), "=r"(r[2]), "=r"(r[3]) : "r"(addr));
}
__device__ __forceinline__ void ldsm_x2_t(uint32_t* r, uint32_t addr) {
    asm volatile("ldmatrix.sync.aligned.m8n8.x2.trans.shared.b16 {%0,%1}, [%2];"
        : "=r"(r[0]), "=r"(r[1]) : "r"(addr));
}
__device__ __forceinline__ void mma_bf16(float* c, const uint32_t* a,
                                         uint32_t b0, uint32_t b1) {
    asm volatile(
        "mma.sync.aligned.m16n8k16.row.col.f32.bf16.bf16.f32 "
        "{%0,%1,%2,%3}, {%4,%5,%6,%7}, {%8,%9}, {%0,%1,%2,%3};"
        : "+f"(c[0]), "+f"(c[1]), "+f"(c[2]), "+f"(c[3])
        : "r"(a[0]), "r"(a[1]), "r"(a[2]), "r"(a[3]), "r"(b0), "r"(b1));
}
__device__ __forceinline__ uint32_t pack2(__nv_bfloat16 a, __nv_bfloat16 b) {
    union { __nv_bfloat162 v; uint32_t u; } c;
    c.v = __nv_bfloat162(a, b);
    return c.u;
}
__device__ __forceinline__ void split_store4(float4 v,
                                             __nv_bfloat16* hip,
                                             __nv_bfloat16* lop) {
    __nv_bfloat16 h0 = __float2bfloat16_rn(v.x);
    __nv_bfloat16 h1 = __float2bfloat16_rn(v.y);
    __nv_bfloat16 h2 = __float2bfloat16_rn(v.z);
    __nv_bfloat16 h3 = __float2bfloat16_rn(v.w);
    __nv_bfloat16 l0 = __float2bfloat16_rn(v.x - __bfloat162float(h0));
    __nv_bfloat16 l1 = __float2bfloat16_rn(v.y - __bfloat162float(h1));
    __nv_bfloat16 l2 = __float2bfloat16_rn(v.z - __bfloat162float(h2));
    __nv_bfloat16 l3 = __float2bfloat16_rn(v.w - __bfloat162float(h3));
    ((uint32_t*)hip)[0] = pack2(h0, h1);
    ((uint32_t*)hip)[1] = pack2(h2, h3);
    ((uint32_t*)lop)[0] = pack2(l0, l1);
    ((uint32_t*)lop)[1] = pack2(l2, l3);
}

// ---- MUFU-free activations ----
__device__ __forceinline__ float fast_exp(float x) {
    const float L2E = 1.4426950408889634f;
    float t  = fmaf(x, L2E, 12582912.0f);
    int   n  = __float_as_int(t) - 0x4B400000;
    float nf = t - 12582912.0f;
    float r  = fmaf(nf, -0.693359375f, x);
    r = fmaf(nf, 2.12194440e-4f, r);
    float p = 1.9841270e-4f;
    p = fmaf(p, r, 1.3888889e-3f);
    p = fmaf(p, r, 8.3333333e-3f);
    p = fmaf(p, r, 4.1666667e-2f);
    p = fmaf(p, r, 1.6666667e-1f);
    p = fmaf(p, r, 0.5f);
    p = fmaf(p, r, 1.0f);
    p = fmaf(p, r, 1.0f);
    return __int_as_float(__float_as_int(p) + (n << 23));
}
__device__ __forceinline__ float fast_rcp(float d) {
    float r = __int_as_float(0x7EF127EAu - __float_as_int(d));
    r = r * fmaf(-d, r, 2.0f);
    r = r * fmaf(-d, r, 2.0f);
    return r;
}
__device__ __forceinline__ float fsig(float x) {
    x = fminf(fmaxf(x, -30.0f), 30.0f);
    float e = fast_exp(-x);
    return fast_rcp(1.0f + e);
}
__device__ __forceinline__ float ftanh(float x) {
    return fmaf(2.0f, fsig(2.0f * x), -1.0f);
}

// ===========================================================================
// Kernel 1: x_proj = inputs @ Wx + b (unchanged — measured ~1.2 ms)
// ===========================================================================
#define XBM 128
#define XBN 128
#define XBK 32
#define KPA 40
#define NPB 136
#define A_TERM_ELEMS (XBM * KPA)
#define B_TERM_ELEMS (XBK * NPB)
#define STAGE_ELEMS  (2 * A_TERM_ELEMS + 2 * B_TERM_ELEMS)
#define XSMEM_BYTES  (2 * STAGE_ELEMS * 2)

__global__ __launch_bounds__(256) void xproj_mma_kernel(
    const float* __restrict__ A,
    const float* __restrict__ W,
    const float* __restrict__ bias)
{
    extern __shared__ __nv_bfloat16 xsm[];

    const int tid   = threadIdx.x;
    const int lane  = tid & 31;
    const int wid   = tid >> 5;
    const int warpM = wid & 3;
    const int warpN = wid >> 2;
    const int bM    = blockIdx.y;
    const int bN    = blockIdx.x;

    const int arow0 = tid >> 3;
    const int ac4   = tid & 7;
    const int bkr0  = tid >> 5;
    const int bn4   = tid & 31;

    const float* Ag = A + (size_t)bM * XBM * DIM;
    const float* Wg = W + (size_t)bN * XBN;

    float acc[2][8][4];
    #pragma unroll
    for (int mt = 0; mt < 2; mt++)
        #pragma unroll
        for (int j = 0; j < 8; j++)
            #pragma unroll
            for (int q = 0; q < 4; q++) acc[mt][j][q] = 0.f;

    const int a_row_l = (lane & 15);
    const int a_koff  = ((lane >> 4) << 3);
    const int b_krow  = (lane & 7) + ((lane >> 3) & 1) * 8;
    const int b_ncol  = ((lane >> 4) & 1) * 8;

    float4 aReg[4], bReg[4];

    #pragma unroll
    for (int i = 0; i < 4; i++) {
        aReg[i] = *(const float4*)(Ag + (size_t)(arow0 + 32 * i) * DIM + ac4 * 4);
        bReg[i] = *(const float4*)(Wg + (size_t)(bkr0 + 8 * i) * FOURH + bn4 * 4);
    }
    {
        __nv_bfloat16* Ahi = xsm;
        __nv_bfloat16* Alo = Ahi + A_TERM_ELEMS;
        __nv_bfloat16* Bhi = Alo + A_TERM_ELEMS;
        __nv_bfloat16* Blo = Bhi + B_TERM_ELEMS;
        #pragma unroll
        for (int i = 0; i < 4; i++) {
            int ar = arow0 + 32 * i;
            split_store4(aReg[i], &Ahi[ar * KPA + ac4 * 4], &Alo[ar * KPA + ac4 * 4]);
            int bk = bkr0 + 8 * i;
            split_store4(bReg[i], &Bhi[bk * NPB + bn4 * 4], &Blo[bk * NPB + bn4 * 4]);
        }
    }
    __syncthreads();

    const int NSTAGE = DIM / XBK;

    for (int s = 0; s < NSTAGE; s++) {
        if (s + 1 < NSTAGE) {
            int k0 = (s + 1) * XBK;
            #pragma unroll
            for (int i = 0; i < 4; i++) {
                aReg[i] = *(const float4*)(Ag + (size_t)(arow0 + 32 * i) * DIM + k0 + ac4 * 4);
                bReg[i] = *(const float4*)(Wg + (size_t)(k0 + bkr0 + 8 * i) * FOURH + bn4 * 4);
            }
        }

        const __nv_bfloat16* st = xsm + (s & 1) * STAGE_ELEMS;
        uint32_t sAhi = smem_u32(st);
        uint32_t sAlo = sAhi + A_TERM_ELEMS * 2;
        uint32_t sBhi = sAlo + A_TERM_ELEMS * 2;
        uint32_t sBlo = sBhi + B_TERM_ELEMS * 2;

        #pragma unroll
        for (int ks = 0; ks < 2; ks++) {
            const int kk0 = ks * 16;
            uint32_t aHi[2][4], aLo[2][4];
            #pragma unroll
            for (int mt = 0; mt < 2; mt++) {
                uint32_t off =
                    (uint32_t)((warpM * 32 + mt * 16 + a_row_l) * KPA + kk0 + a_koff) * 2;
                ldsm_x4(aHi[mt], sAhi + off);
                ldsm_x4(aLo[mt], sAlo + off);
            }
            uint32_t bHi[4][4], bLo[4][4];
            #pragma unroll
            for (int nt = 0; nt < 4; nt++) {
                uint32_t off =
                    (uint32_t)((kk0 + b_krow) * NPB + warpN * 64 + nt * 16 + b_ncol) * 2;
                ldsm_x4_t(bHi[nt], sBhi + off);
                ldsm_x4_t(bLo[nt], sBlo + off);
            }
            #pragma unroll
            for (int mt = 0; mt < 2; mt++) {
                #pragma unroll
                for (int j = 0; j < 8; j++) {
                    uint32_t bh0 = bHi[j >> 1][(j & 1) * 2];
                    uint32_t bh1 = bHi[j >> 1][(j & 1) * 2 + 1];
                    uint32_t bl0 = bLo[j >> 1][(j & 1) * 2];
                    uint32_t bl1 = bLo[j >> 1][(j & 1) * 2 + 1];
                    mma_bf16(acc[mt][j], aHi[mt], bh0, bh1);
                    mma_bf16(acc[mt][j], aHi[mt], bl0, bl1);
                    mma_bf16(acc[mt][j], aLo[mt], bh0, bh1);
                }
            }
        }

        if (s + 1 < NSTAGE) {
            __nv_bfloat16* dst = xsm + ((s + 1) & 1) * STAGE_ELEMS;
            __nv_bfloat16* Ahi = dst;
            __nv_bfloat16* Alo = Ahi + A_TERM_ELEMS;
            __nv_bfloat16* Bhi = Alo + A_TERM_ELEMS;
            __nv_bfloat16* Blo = Bhi + B_TERM_ELEMS;
            #pragma unroll
            for (int i = 0; i < 4; i++) {
                int ar = arow0 + 32 * i;
                split_store4(aReg[i], &Ahi[ar * KPA + ac4 * 4], &Alo[ar * KPA + ac4 * 4]);
                int bk = bkr0 + 8 * i;
                split_store4(bReg[i], &Bhi[bk * NPB + bn4 * 4], &Blo[bk * NPB + bn4 * 4]);
            }
        }
        __syncthreads();
    }

    const int g  = lane >> 2;
    const int t2 = (lane & 3) * 2;
    #pragma unroll
    for (int mt = 0; mt < 2; mt++) {
        int row = bM * XBM + warpM * 32 + mt * 16 + g;
        #pragma unroll
        for (int j = 0; j < 8; j++) {
            int col = bN * XBN + warpN * 64 + j * 8 + t2;
            float b0 = bias[col], b1 = bias[col + 1];
            float2 o0 = make_float2(acc[mt][j][0] + b0, acc[mt][j][1] + b1);
            float2 o1 = make_float2(acc[mt][j][2] + b0, acc[mt][j][3] + b1);
            *(float2*)&g_xproj[(size_t)row * FOURH + col] = o0;
            *(float2*)&g_xproj[(size_t)(row + 8) * FOURH + col] = o1;
        }
    }
}

// ===========================================================================
// Kernel 2: recurrent kernel — 16 warps split by K (halved per-warp chains),
// head folded into mma, mbarrier cluster sync.
// ===========================================================================
#define CLUSTER 8
#define NB      16
#define LC      128
#define RTHREADS 512

#define HSTRIDE 264
#define WSTRIDE 136      // cols 0..127 = Wh slice, 128..135 = head cols
#define ZSTRIDE 140      // cols 0..127 = z partial, 128..135 = head partial

#define SMB_WHHI 0
#define SMB_WHLO (SMB_WHHI + 256 * WSTRIDE * 2)        // 69632
#define SMB_HB   (SMB_WHLO + 256 * WSTRIDE * 2)        // 139264
#define HB_ARR_BYTES (NB * HSTRIDE * 2)                 // 8448
#define HB_BUF_BYTES (2 * HB_ARR_BYTES)                 // 16896
#define SMB_Z0   (SMB_HB + 2 * HB_BUF_BYTES)            // 173056
#define SMB_Z1   (SMB_Z0 + NB * ZSTRIDE * 4)            // 182016
#define SMB_C    (SMB_Z1 + NB * ZSTRIDE * 4)            // 190976
#define SMB_WO   (SMB_C + NB * 32 * 4)                  // 193024
#define SMB_BO   (SMB_WO + 5 * 256 * 4)                 // 198144
#define SMB_MBAR (SMB_BO + 32)                          // 198176
#define SMB_EP   (SMB_MBAR + 16)                        // 198192
#define RSMEM_BYTES (SMB_EP + T_STEPS * NB)             // 206384

#define MBAR_COUNT 112   // 16 threads x 7 peer CTAs

__device__ __forceinline__ void st_cluster_v4(uint32_t saddr,
                                              uint32_t a, uint32_t b,
                                              uint32_t c, uint32_t d) {
    asm volatile("st.shared::cluster.v4.b32 [%0], {%1,%2,%3,%4};"
        :: "r"(saddr), "r"(a), "r"(b), "r"(c), "r"(d) : "memory");
}

__device__ __forceinline__ void mbar_wait_cluster(uint32_t mbar, uint32_t parity) {
    uint32_t done;
    asm volatile(
        "{ .reg .pred p;\n"
        " mbarrier.try_wait.parity.acquire.cluster.shared::cta.b64 p, [%1], %2;\n"
        " selp.b32 %0, 1, 0, p; }"
        : "=r"(done) : "r"(mbar), "r"(parity) : "memory");
    while (!done) {
        asm volatile(
            "{ .reg .pred p;\n"
            " mbarrier.try_wait.parity.acquire.cluster.shared::cta.b64 p, [%1], %2, 0x989680;\n"
            " selp.b32 %0, 1, 0, p; }"
            : "=r"(done) : "r"(mbar), "r"(parity) : "memory");
    }
}

// fp32 output head (final timestep only), adapted for 16 warps
__device__ __forceinline__ void do_head(
    const __nv_bfloat16* hHi, const __nv_bfloat16* hLo,
    const float* Wo_s, const float* bo_s,
    float* out, int tt, int b0, int rank, int wid, int lane)
{
    // 64 (q,b) tasks: warp wid handles b=wid, q=0..3
    float sacc[4];
    #pragma unroll
    for (int q = 0; q < 4; q++) {
        const __nv_bfloat16* hHr = &hHi[wid * HSTRIDE];
        const __nv_bfloat16* hLr = &hLo[wid * HSTRIDE];
        const float* wcol = &Wo_s[q * 256];
        float s = 0.f;
        #pragma unroll
        for (int uu = 0; uu < 8; uu++) {
            int k = lane + 32 * uu;
            float hv = __bfloat162float(hHr[k]) + __bfloat162float(hLr[k]);
            s = fmaf(hv, wcol[k], s);
        }
        sacc[q] = s;
    }
    float sv = 0.f;
    if (rank == 0) {
        const __nv_bfloat16* hHr = &hHi[wid * HSTRIDE];
        const __nv_bfloat16* hLr = &hLo[wid * HSTRIDE];
        const float* wcol = &Wo_s[4 * 256];
        #pragma unroll
        for (int uu = 0; uu < 8; uu++) {
            int k = lane + 32 * uu;
            float hv = __bfloat162float(hHr[k]) + __bfloat162float(hLr[k]);
            sv = fmaf(hv, wcol[k], sv);
        }
    }
    #pragma unroll
    for (int q = 0; q < 4; q++) {
        float s = sacc[q];
        #pragma unroll
        for (int off = 16; off; off >>= 1)
            s += __shfl_xor_sync(0xFFFFFFFFu, s, off);
        sacc[q] = s;
    }
    #pragma unroll
    for (int off = 16; off; off >>= 1)
        sv += __shfl_xor_sync(0xFFFFFFFFu, sv, off);
    if (lane == 0) {
        size_t obase = ((size_t)tt * BATCH + b0 + wid) * OUTC;
        #pragma unroll
        for (int q = 0; q < 4; q++)
            out[obase + rank + 8 * q] = sacc[q] + bo_s[q];
        if (rank == 0)
            out[obase + 32] = sv + bo_s[4];
    }
}

__global__ void __cluster_dims__(CLUSTER, 1, 1) __launch_bounds__(RTHREADS, 1)
lstm_rec_kernel(const int*   __restrict__ epi,
                const float* __restrict__ carry_c,
                const float* __restrict__ carry_h,
                const float* __restrict__ Wh,
                const float* __restrict__ Wa,
                const float* __restrict__ ba,
                const float* __restrict__ Wv,
                const float* __restrict__ bv,
                float*       __restrict__ out)
{
    extern __shared__ char smraw[];
    __nv_bfloat16* WhHi = (__nv_bfloat16*)(smraw + SMB_WHHI);
    __nv_bfloat16* WhLo = (__nv_bfloat16*)(smraw + SMB_WHLO);
    float* z0_s = (float*)(smraw + SMB_Z0);
    float* z1_s = (float*)(smraw + SMB_Z1);
    float* c_s  = (float*)(smraw + SMB_C);
    float* Wo_s = (float*)(smraw + SMB_WO);
    float* bo_s = (float*)(smraw + SMB_BO);
    unsigned char* ep_s = (unsigned char*)(smraw + SMB_EP);

    const int tid  = threadIdx.x;
    const int lane = tid & 31;
    const int wid  = tid >> 5;            // 0..15
    const int wn   = wid & 7;             // N-tile id within K-half
    const int kh   = wid >> 3;            // K-half: 0 or 1
    uint32_t rank;
    asm("mov.u32 %0, %%cluster_ctarank;" : "=r"(rank));
    const int cl = blockIdx.x / CLUSTER;
    const int b0 = cl * NB;
    const uint32_t smbase = smem_u32(smraw);

    // --- init mbarriers ---
    if (tid == 0) {
        asm volatile("mbarrier.init.shared.b64 [%0], %1;"
            :: "r"(smbase + SMB_MBAR), "r"((uint32_t)MBAR_COUNT) : "memory");
        asm volatile("mbarrier.init.shared.b64 [%0], %1;"
            :: "r"(smbase + SMB_MBAR + 8), "r"((uint32_t)MBAR_COUNT) : "memory");
    }

    // --- preload Wh slice (split bf16), cols 0..127 ---
    for (int idx = tid; idx < 256 * LC; idx += RTHREADS) {
        int k = idx >> 7;
        int c = idx & 127;
        int gcol = ((c >> 5) << 8) + ((int)rank << 5) + (c & 31);
        float w = Wh[k * FOURH + gcol];
        __nv_bfloat16 hi = __float2bfloat16_rn(w);
        __nv_bfloat16 lo = __float2bfloat16_rn(w - __bfloat162float(hi));
        WhHi[k * WSTRIDE + c] = hi;
        WhLo[k * WSTRIDE + c] = lo;
    }
    // --- head columns into cols 128..135 ---
    for (int idx = tid; idx < 256 * 8; idx += RTHREADS) {
        int k = idx >> 3;
        int c = idx & 7;
        float w = 0.f;
        if (c < 4)                     w = Wa[k * NACT + (int)rank + 8 * c];
        else if (c == 4 && rank == 0)  w = Wv[k];
        __nv_bfloat16 hi = __float2bfloat16_rn(w);
        __nv_bfloat16 lo = __float2bfloat16_rn(w - __bfloat162float(hi));
        WhHi[k * WSTRIDE + 128 + c] = hi;
        WhLo[k * WSTRIDE + 128 + c] = lo;
    }
    // --- carry_h into buffer 1 (input for t=0), split bf16 ---
    for (int idx = tid; idx < NB * HID; idx += RTHREADS) {
        int b = idx >> 8;
        int k = idx & 255;
        float v = carry_h[(size_t)(b0 + b) * HID + k];
        __nv_bfloat16 hi = __float2bfloat16_rn(v);
        __nv_bfloat16 lo = __float2bfloat16_rn(v - __bfloat162float(hi));
        __nv_bfloat16* hHi = (__nv_bfloat16*)(smraw + SMB_HB + 1 * HB_BUF_BYTES);
        __nv_bfloat16* hLo = hHi + NB * HSTRIDE;
        hHi[b * HSTRIDE + k] = hi;
        hLo[b * HSTRIDE + k] = lo;
    }
    // --- carry_c slice ---
    for (int idx = tid; idx < NB * 32; idx += RTHREADS) {
        int b = idx >> 5;
        int j = idx & 31;
        c_s[idx] = carry_c[(size_t)(b0 + b) * HID + (int)rank * 32 + j];
    }
    // --- fp32 head columns (final-step do_head) ---
    #pragma unroll
    for (int q = 0; q < 5; q++) {
        int col = (int)rank + 8 * q;
        if (col <= 32) {
            for (int k = tid; k < HID; k += RTHREADS)
                Wo_s[q * 256 + k] = (col < 32) ? Wa[k * NACT + col] : Wv[k];
            if (tid == 0) bo_s[q] = (col < 32) ? ba[col] : bv[0];
        }
    }
    // --- epi slice as bytes ---
    for (int idx = tid; idx < T_STEPS * NB; idx += RTHREADS) {
        int t = idx >> 4;
        int b = idx & 15;
        ep_s[idx] = (unsigned char)(epi[t * BATCH + b0 + b] != 0);
    }
    __syncthreads();
    asm volatile("barrier.cluster.arrive.aligned;" ::: "memory");
    asm volatile("barrier.cluster.wait.aligned;"   ::: "memory");

    // frag geometry
    const int a_row_l = (lane & 15);
    const int a_koff  = ((lane >> 4) << 3);
    const int b_krow  = (lane & 7) + ((lane >> 3) & 1) * 8;
    const int b_ncol  = ((lane >> 4) & 1) * 8;
    const int kbase   = kh * 128;              // this warp's K-half

    const uint32_t sWhHi = smem_u32(WhHi);
    const uint32_t sWhLo = smem_u32(WhLo);
    float* zw_s = kh ? z1_s : z0_s;            // this warp's z partial buffer

    int ph0 = 0, ph1 = 0;

    const int bc_pp  = tid >> 4;
    const int bc_p   = bc_pp + (bc_pp >= (int)rank);
    const int bc_row = tid & 15;

    // gating mapping: one element per thread
    const int gb = tid >> 5;     // batch row 0..15
    const int gj = tid & 31;     // hidden unit within slice

    for (int t = 0; t < T_STEPS; t++) {
        const int p_out = t & 1;
        const int p_in  = p_out ^ 1;
        __nv_bfloat16* hinHi  = (__nv_bfloat16*)(smraw + SMB_HB + p_in * HB_BUF_BYTES);
        __nv_bfloat16* hinLo  = hinHi + NB * HSTRIDE;
        __nv_bfloat16* houtHi = (__nv_bfloat16*)(smraw + SMB_HB + p_out * HB_BUF_BYTES);
        __nv_bfloat16* houtLo = houtHi + NB * HSTRIDE;

        // -- prefetch x_proj gate values (issued before the wait) --
        const size_t xbase = (size_t)t * BATCH * FOURH
                           + (size_t)(b0 + gb) * FOURH + (int)rank * 32 + gj;
        float xi = g_xproj[xbase];
        float xf = g_xproj[xbase + 256];
        float xg = g_xproj[xbase + 512];
        float xo = g_xproj[xbase + 768];
        int   ep = ep_s[t * NB + gb];

        // -- wait for peers' h slices --
        if (t > 0) {
            if (t & 1) { mbar_wait_cluster(smbase + SMB_MBAR + 8, ph1); ph1 ^= 1; }
            else       { mbar_wait_cluster(smbase + SMB_MBAR,     ph0); ph0 ^= 1; }
        }

        // -- mma: z partial over this warp's K-half; head tile on wn==0 --
        {
            const uint32_t sHinHi = smem_u32(hinHi);
            const uint32_t sHinLo = smem_u32(hinLo);
            float acc[2][4][4];
            float accH[2][4];
            #pragma unroll
            for (int t2 = 0; t2 < 2; t2++) {
                #pragma unroll
                for (int kc = 0; kc < 4; kc++)
                    #pragma unroll
                    for (int q = 0; q < 4; q++) acc[t2][kc][q] = 0.f;
                #pragma unroll
                for (int q = 0; q < 4; q++) accH[t2][q] = 0.f;
            }

            #pragma unroll
            for (int ks = 0; ks < 8; ks++) {
                const int kk0 = kbase + ks * 16;
                const int kc  = ks & 3;
                uint32_t aoff = (uint32_t)(a_row_l * HSTRIDE + kk0 + a_koff) * 2;
                uint32_t aHi[4], aLo[4];
                ldsm_x4(aHi, sHinHi + aoff);
                ldsm_x4(aLo, sHinLo + aoff);
                uint32_t boff =
                    (uint32_t)((kk0 + b_krow) * WSTRIDE + wn * 16 + b_ncol) * 2;
                uint32_t bHi[4], bLo[4];
                ldsm_x4_t(bHi, sWhHi + boff);
                ldsm_x4_t(bLo, sWhLo + boff);
                #pragma unroll
                for (int t2 = 0; t2 < 2; t2++) {
                    mma_bf16(acc[t2][kc], aHi, bHi[t2 * 2], bHi[t2 * 2 + 1]);
                    mma_bf16(acc[t2][kc], aHi, bLo[t2 * 2], bLo[t2 * 2 + 1]);
                    mma_bf16(acc[t2][kc], aLo, bHi[t2 * 2], bHi[t2 * 2 + 1]);
                }
                if (wn == 0) {
                    uint32_t hoff = (uint32_t)((kk0 + b_krow) * WSTRIDE + 128) * 2;
                    uint32_t hH[2], hL[2];
                    ldsm_x2_t(hH, sWhHi + hoff);
                    ldsm_x2_t(hL, sWhLo + hoff);
                    const int kc2 = ks & 1;
                    mma_bf16(accH[kc2], aHi, hH[0], hH[1]);
                    mma_bf16(accH[kc2], aHi, hL[0], hL[1]);
                    mma_bf16(accH[kc2], aLo, hH[0], hH[1]);
                }
            }
            int r0 = lane >> 2;
            int cb = wn * 16 + 2 * (lane & 3);
            #pragma unroll
            for (int t2 = 0; t2 < 2; t2++) {
                int col = cb + 8 * t2;
                float v0 = (acc[t2][0][0] + acc[t2][1][0]) + (acc[t2][2][0] + acc[t2][3][0]);
                float v1 = (acc[t2][0][1] + acc[t2][1][1]) + (acc[t2][2][1] + acc[t2][3][1]);
                float v2 = (acc[t2][0][2] + acc[t2][1][2]) + (acc[t2][2][2] + acc[t2][3][2]);
                float v3 = (acc[t2][0][3] + acc[t2][1][3]) + (acc[t2][2][3] + acc[t2][3][3]);
                *(float2*)&zw_s[r0 * ZSTRIDE + col] = make_float2(v0, v1);
                *(float2*)&zw_s[(r0 + 8) * ZSTRIDE + col] = make_float2(v2, v3);
            }
            if (wn == 0) {
                int colH = 128 + 2 * (lane & 3);
                float h0 = accH[0][0] + accH[1][0];
                float h1 = accH[0][1] + accH[1][1];
                float h2 = accH[0][2] + accH[1][2];
                float h3 = accH[0][3] + accH[1][3];
                *(float2*)&zw_s[r0 * ZSTRIDE + colH] = make_float2(h0, h1);
                *(float2*)&zw_s[(r0 + 8) * ZSTRIDE + colH] = make_float2(h2, h3);
            }
        }
        __syncthreads();

        // -- write out(t-1): sum of the two K-half head partials --
        if (t > 0) {
            if (tid < 64) {
                int b = tid >> 2, q = tid & 3;
                out[((size_t)(t - 1) * BATCH + b0 + b) * OUTC + (int)rank + 8 * q]
                    = z0_s[b * ZSTRIDE + 128 + q] + z1_s[b * ZSTRIDE + 128 + q] + bo_s[q];
            } else if (rank == 0 && tid < 80) {
                int b = tid - 64;
                out[((size_t)(t - 1) * BATCH + b0 + b) * OUTC + 32]
                    = z0_s[b * ZSTRIDE + 132] + z1_s[b * ZSTRIDE + 132] + bo_s[4];
            }
        }

        // -- gating (1 element/thread; reset folded; MUFU-free) --
        {
            float zi = z0_s[gb * ZSTRIDE + gj]      + z1_s[gb * ZSTRIDE + gj];
            float zf = z0_s[gb * ZSTRIDE + 32 + gj] + z1_s[gb * ZSTRIDE + 32 + gj];
            float zg = z0_s[gb * ZSTRIDE + 64 + gj] + z1_s[gb * ZSTRIDE + 64 + gj];
            float zo = z0_s[gb * ZSTRIDE + 96 + gj] + z1_s[gb * ZSTRIDE + 96 + gj];
            float c_old = c_s[gb * 32 + gj];
            if (ep) { zi = 0.f; zf = 0.f; zg = 0.f; zo = 0.f; c_old = 0.f; }
            float iz = zi + xi;
            float fz = zf + xf;
            float gz = zg + xg;
            float oz = zo + xo;
            float nc = fsig(fz) * c_old + fsig(iz) * ftanh(gz);
            float nh = fsig(oz) * ftanh(nc);
            c_s[gb * 32 + gj] = nc;
            __nv_bfloat16 hi = __float2bfloat16_rn(nh);
            __nv_bfloat16 lo = __float2bfloat16_rn(nh - __bfloat162float(hi));
            int hoff = gb * HSTRIDE + (int)rank * 32 + gj;
            houtHi[hoff] = hi;
            houtLo[hoff] = lo;
        }
        __syncthreads();

        // -- DSMEM broadcast: 16 threads per peer, one row each, then arrive --
        if (tid < 112) {
            uint32_t pbase;
            asm("mapa.shared::cluster.u32 %0, %1, %2;"
                : "=r"(pbase) : "r"(smbase), "r"(bc_p));
            uint32_t hoffHi = (uint32_t)SMB_HB + (uint32_t)p_out * HB_BUF_BYTES
                            + (uint32_t)(bc_row * HSTRIDE + (int)rank * 32) * 2;
            uint32_t hoffLo = hoffHi + (uint32_t)(NB * HSTRIDE) * 2;
            const uint4* srcHi = (const uint4*)(smraw + hoffHi);
            const uint4* srcLo = (const uint4*)(smraw + hoffLo);
            #pragma unroll
            for (int s4 = 0; s4 < 4; s4++) {
                uint4 v = srcHi[s4];
                st_cluster_v4(pbase + hoffHi + s4 * 16, v.x, v.y, v.z, v.w);
            }
            #pragma unroll
            for (int s4 = 0; s4 < 4; s4++) {
                uint4 v = srcLo[s4];
                st_cluster_v4(pbase + hoffLo + s4 * 16, v.x, v.y, v.z, v.w);
            }
            uint32_t mb = pbase + SMB_MBAR + (uint32_t)(((t + 1) & 1) * 8);
            asm volatile(
                "mbarrier.arrive.release.cluster.shared::cluster.b64 _, [%0];"
                :: "r"(mb) : "memory");
        }
    }

    // final wait + fp32 head for t = 511
    {
        mbar_wait_cluster(smbase + SMB_MBAR, ph0);
        __nv_bfloat16* hHi = (__nv_bfloat16*)(smraw + SMB_HB + 1 * HB_BUF_BYTES);
        __nv_bfloat16* hLo = hHi + NB * HSTRIDE;
        do_head(hHi, hLo, Wo_s, bo_s, out, T_STEPS - 1, b0, (int)rank, wid, lane);
    }

    asm volatile("barrier.cluster.arrive.aligned;" ::: "memory");
    asm volatile("barrier.cluster.wait.aligned;"   ::: "memory");
}

// ---------------------------------------------------------------------------
extern "C" void kernel_launch(void* const* d_in, const int* in_sizes, int n_in,
                              void* d_out, int out_size) {
    const float* inputs  = (const float*)d_in[0];
    const int*   epi     = (const int*)  d_in[1];
    const float* carry_c = (const float*)d_in[2];
    const float* carry_h = (const float*)d_in[3];
    const float* Wx      = (const float*)d_in[4];
    const float* Wh      = (const float*)d_in[5];
    const float* bias    = (const float*)d_in[6];
    const float* Wa      = (const float*)d_in[7];
    const float* ba      = (const float*)d_in[8];
    const float* Wv      = (const float*)d_in[9];
    const float* bv      = (const float*)d_in[10];
    float* out = (float*)d_out;

    cudaFuncSetAttribute(xproj_mma_kernel,
                         cudaFuncAttributeMaxDynamicSharedMemorySize, XSMEM_BYTES);
    cudaFuncSetAttribute(lstm_rec_kernel,
                         cudaFuncAttributeMaxDynamicSharedMemorySize, RSMEM_BYTES);

    dim3 g1(FOURH / XBN, (T_STEPS * BATCH) / XBM);
    xproj_mma_kernel<<<g1, 256, XSMEM_BYTES>>>(inputs, Wx, bias);

    lstm_rec_kernel<<<(BATCH / NB) * CLUSTER, RTHREADS, RSMEM_BYTES>>>(
        epi, carry_c, carry_h, Wh, Wa, ba, Wv, bv, out);
}

// round 10
// speedup vs baseline: 1.4031x; 1.2278x over previous
#include <cuda_runtime.h>
#include <cuda_bf16.h>
#include <cstdint>
#include <cstddef>

// Problem dims
#define T_STEPS 512
#define BATCH   256
#define DIM     512
#define HID     256
#define FOURH   1024
#define NACT    32
#define OUTC    33

// Scratch for x_proj: [T, B, 4H] fp32
__device__ float g_xproj[(size_t)T_STEPS * BATCH * FOURH];

// ===========================================================================
// Shared helpers
// ===========================================================================
__device__ __forceinline__ uint32_t smem_u32(const void* p) {
    uint32_t a;
    asm("{ .reg .u64 t; cvta.to.shared.u64 t, %1; cvt.u32.u64 %0, t; }"
        : "=r"(a) : "l"(p));
    return a;
}
__device__ __forceinline__ void ldsm_x4(uint32_t* r, uint32_t addr) {
    asm volatile("ldmatrix.sync.aligned.m8n8.x4.shared.b16 {%0,%1,%2,%3}, [%4];"
        : "=r"(r[0]), "=r"(r[1]), "=r"(r[2]), "=r"(r[3]) : "r"(addr));
}
__device__ __forceinline__ void ldsm_x4_t(uint32_t* r, uint32_t addr) {
    asm volatile("ldmatrix.sync.aligned.m8n8.x4.trans.shared.b16 {%0,%1,%2,%3}, [%4];"
        : "=r"(r[0]), "=r"(r[1]), "=r"(r[2]), "=r"(r[3]) : "r"(addr));
}
__device__ __forceinline__ void ldsm_x2_t(uint32_t* r, uint32_t addr) {
    asm volatile("ldmatrix.sync.aligned.m8n8.x2.trans.shared.b16 {%0,%1}, [%2];"
        : "=r"(r[0]), "=r"(r[1]) : "r"(addr));
}
__device__ __forceinline__ void mma_bf16(float* c, const uint32_t* a,
                                         uint32_t b0, uint32_t b1) {
    asm volatile(
        "mma.sync.aligned.m16n8k16.row.col.f32.bf16.bf16.f32 "
        "{%0,%1,%2,%3}, {%4,%5,%6,%7}, {%8,%9}, {%0,%1,%2,%3};"
        : "+f"(c[0]), "+f"(c[1]), "+f"(c[2]), "+f"(c[3])
        : "r"(a[0]), "r"(a[1]), "r"(a[2]), "r"(a[3]), "r"(b0), "r"(b1));
}
__device__ __forceinline__ uint32_t pack2(__nv_bfloat16 a, __nv_bfloat16 b) {
    union { __nv_bfloat162 v; uint32_t u; } c;
    c.v = __nv_bfloat162(a, b);
    return c.u;
}
__device__ __forceinline__ void split_store4(float4 v,
                                             __nv_bfloat16* hip,
                                             __nv_bfloat16* lop) {
    __nv_bfloat16 h0 = __float2bfloat16_rn(v.x);
    __nv_bfloat16 h1 = __float2bfloat16_rn(v.y);
    __nv_bfloat16 h2 = __float2bfloat16_rn(v.z);
    __nv_bfloat16 h3 = __float2bfloat16_rn(v.w);
    __nv_bfloat16 l0 = __float2bfloat16_rn(v.x - __bfloat162float(h0));
    __nv_bfloat16 l1 = __float2bfloat16_rn(v.y - __bfloat162float(h1));
    __nv_bfloat16 l2 = __float2bfloat16_rn(v.z - __bfloat162float(h2));
    __nv_bfloat16 l3 = __float2bfloat16_rn(v.w - __bfloat162float(h3));
    ((uint32_t*)hip)[0] = pack2(h0, h1);
    ((uint32_t*)hip)[1] = pack2(h2, h3);
    ((uint32_t*)lop)[0] = pack2(l0, l1);
    ((uint32_t*)lop)[1] = pack2(l2, l3);
}

// ---- MUFU-free activations ----
__device__ __forceinline__ float fast_exp(float x) {
    const float L2E = 1.4426950408889634f;
    float t  = fmaf(x, L2E, 12582912.0f);
    int   n  = __float_as_int(t) - 0x4B400000;
    float nf = t - 12582912.0f;
    float r  = fmaf(nf, -0.693359375f, x);
    r = fmaf(nf, 2.12194440e-4f, r);
    float p = 1.9841270e-4f;
    p = fmaf(p, r, 1.3888889e-3f);
    p = fmaf(p, r, 8.3333333e-3f);
    p = fmaf(p, r, 4.1666667e-2f);
    p = fmaf(p, r, 1.6666667e-1f);
    p = fmaf(p, r, 0.5f);
    p = fmaf(p, r, 1.0f);
    p = fmaf(p, r, 1.0f);
    return __int_as_float(__float_as_int(p) + (n << 23));
}
__device__ __forceinline__ float fast_rcp(float d) {
    float r = __int_as_float(0x7EF127EAu - __float_as_int(d));
    r = r * fmaf(-d, r, 2.0f);
    r = r * fmaf(-d, r, 2.0f);
    return r;
}
__device__ __forceinline__ float fsig(float x) {
    x = fminf(fmaxf(x, -30.0f), 30.0f);
    float e = fast_exp(-x);
    return fast_rcp(1.0f + e);
}
__device__ __forceinline__ float ftanh(float x) {
    return fmaf(2.0f, fsig(2.0f * x), -1.0f);
}

// ===========================================================================
// Kernel 1: x_proj = inputs @ Wx + b (unchanged — measured ~1.2 ms)
// ===========================================================================
#define XBM 128
#define XBN 128
#define XBK 32
#define KPA 40
#define NPB 136
#define A_TERM_ELEMS (XBM * KPA)
#define B_TERM_ELEMS (XBK * NPB)
#define STAGE_ELEMS  (2 * A_TERM_ELEMS + 2 * B_TERM_ELEMS)
#define XSMEM_BYTES  (2 * STAGE_ELEMS * 2)

__global__ __launch_bounds__(256) void xproj_mma_kernel(
    const float* __restrict__ A,
    const float* __restrict__ W,
    const float* __restrict__ bias)
{
    extern __shared__ __nv_bfloat16 xsm[];

    const int tid   = threadIdx.x;
    const int lane  = tid & 31;
    const int wid   = tid >> 5;
    const int warpM = wid & 3;
    const int warpN = wid >> 2;
    const int bM    = blockIdx.y;
    const int bN    = blockIdx.x;

    const int arow0 = tid >> 3;
    const int ac4   = tid & 7;
    const int bkr0  = tid >> 5;
    const int bn4   = tid & 31;

    const float* Ag = A + (size_t)bM * XBM * DIM;
    const float* Wg = W + (size_t)bN * XBN;

    float acc[2][8][4];
    #pragma unroll
    for (int mt = 0; mt < 2; mt++)
        #pragma unroll
        for (int j = 0; j < 8; j++)
            #pragma unroll
            for (int q = 0; q < 4; q++) acc[mt][j][q] = 0.f;

    const int a_row_l = (lane & 15);
    const int a_koff  = ((lane >> 4) << 3);
    const int b_krow  = (lane & 7) + ((lane >> 3) & 1) * 8;
    const int b_ncol  = ((lane >> 4) & 1) * 8;

    float4 aReg[4], bReg[4];

    #pragma unroll
    for (int i = 0; i < 4; i++) {
        aReg[i] = *(const float4*)(Ag + (size_t)(arow0 + 32 * i) * DIM + ac4 * 4);
        bReg[i] = *(const float4*)(Wg + (size_t)(bkr0 + 8 * i) * FOURH + bn4 * 4);
    }
    {
        __nv_bfloat16* Ahi = xsm;
        __nv_bfloat16* Alo = Ahi + A_TERM_ELEMS;
        __nv_bfloat16* Bhi = Alo + A_TERM_ELEMS;
        __nv_bfloat16* Blo = Bhi + B_TERM_ELEMS;
        #pragma unroll
        for (int i = 0; i < 4; i++) {
            int ar = arow0 + 32 * i;
            split_store4(aReg[i], &Ahi[ar * KPA + ac4 * 4], &Alo[ar * KPA + ac4 * 4]);
            int bk = bkr0 + 8 * i;
            split_store4(bReg[i], &Bhi[bk * NPB + bn4 * 4], &Blo[bk * NPB + bn4 * 4]);
        }
    }
    __syncthreads();

    const int NSTAGE = DIM / XBK;

    for (int s = 0; s < NSTAGE; s++) {
        if (s + 1 < NSTAGE) {
            int k0 = (s + 1) * XBK;
            #pragma unroll
            for (int i = 0; i < 4; i++) {
                aReg[i] = *(const float4*)(Ag + (size_t)(arow0 + 32 * i) * DIM + k0 + ac4 * 4);
                bReg[i] = *(const float4*)(Wg + (size_t)(k0 + bkr0 + 8 * i) * FOURH + bn4 * 4);
            }
        }

        const __nv_bfloat16* st = xsm + (s & 1) * STAGE_ELEMS;
        uint32_t sAhi = smem_u32(st);
        uint32_t sAlo = sAhi + A_TERM_ELEMS * 2;
        uint32_t sBhi = sAlo + A_TERM_ELEMS * 2;
        uint32_t sBlo = sBhi + B_TERM_ELEMS * 2;

        #pragma unroll
        for (int ks = 0; ks < 2; ks++) {
            const int kk0 = ks * 16;
            uint32_t aHi[2][4], aLo[2][4];
            #pragma unroll
            for (int mt = 0; mt < 2; mt++) {
                uint32_t off =
                    (uint32_t)((warpM * 32 + mt * 16 + a_row_l) * KPA + kk0 + a_koff) * 2;
                ldsm_x4(aHi[mt], sAhi + off);
                ldsm_x4(aLo[mt], sAlo + off);
            }
            uint32_t bHi[4][4], bLo[4][4];
            #pragma unroll
            for (int nt = 0; nt < 4; nt++) {
                uint32_t off =
                    (uint32_t)((kk0 + b_krow) * NPB + warpN * 64 + nt * 16 + b_ncol) * 2;
                ldsm_x4_t(bHi[nt], sBhi + off);
                ldsm_x4_t(bLo[nt], sBlo + off);
            }
            #pragma unroll
            for (int mt = 0; mt < 2; mt++) {
                #pragma unroll
                for (int j = 0; j < 8; j++) {
                    uint32_t bh0 = bHi[j >> 1][(j & 1) * 2];
                    uint32_t bh1 = bHi[j >> 1][(j & 1) * 2 + 1];
                    uint32_t bl0 = bLo[j >> 1][(j & 1) * 2];
                    uint32_t bl1 = bLo[j >> 1][(j & 1) * 2 + 1];
                    mma_bf16(acc[mt][j], aHi[mt], bh0, bh1);
                    mma_bf16(acc[mt][j], aHi[mt], bl0, bl1);
                    mma_bf16(acc[mt][j], aLo[mt], bh0, bh1);
                }
            }
        }

        if (s + 1 < NSTAGE) {
            __nv_bfloat16* dst = xsm + ((s + 1) & 1) * STAGE_ELEMS;
            __nv_bfloat16* Ahi = dst;
            __nv_bfloat16* Alo = Ahi + A_TERM_ELEMS;
            __nv_bfloat16* Bhi = Alo + A_TERM_ELEMS;
            __nv_bfloat16* Blo = Bhi + B_TERM_ELEMS;
            #pragma unroll
            for (int i = 0; i < 4; i++) {
                int ar = arow0 + 32 * i;
                split_store4(aReg[i], &Ahi[ar * KPA + ac4 * 4], &Alo[ar * KPA + ac4 * 4]);
                int bk = bkr0 + 8 * i;
                split_store4(bReg[i], &Bhi[bk * NPB + bn4 * 4], &Blo[bk * NPB + bn4 * 4]);
            }
        }
        __syncthreads();
    }

    const int g  = lane >> 2;
    const int t2 = (lane & 3) * 2;
    #pragma unroll
    for (int mt = 0; mt < 2; mt++) {
        int row = bM * XBM + warpM * 32 + mt * 16 + g;
        #pragma unroll
        for (int j = 0; j < 8; j++) {
            int col = bN * XBN + warpN * 64 + j * 8 + t2;
            float b0 = bias[col], b1 = bias[col + 1];
            float2 o0 = make_float2(acc[mt][j][0] + b0, acc[mt][j][1] + b1);
            float2 o1 = make_float2(acc[mt][j][2] + b0, acc[mt][j][3] + b1);
            *(float2*)&g_xproj[(size_t)row * FOURH + col] = o0;
            *(float2*)&g_xproj[(size_t)(row + 8) * FOURH + col] = o1;
        }
    }
}

// ===========================================================================
// Kernel 2: recurrent kernel — bulk DSMEM copies with complete_tx mbarriers,
// rank-blocked h layout (80 B row stride: ldmatrix-aligned), 16 warps K-split,
// head folded into mma.
// ===========================================================================
#define CLUSTER 8
#define NB      16
#define LC      128
#define RTHREADS 512

#define WSTRIDE 136      // cols 0..127 = Wh slice, 128..135 = head cols
#define ZSTRIDE 140      // cols 0..127 = z partial, 128..135 = head partial

// h layout: per buffer, 8 rank blocks of 2560 B:
//   block = [hi: 16 rows x 80 B][lo: 16 rows x 80 B]   (cols 0..31 valid)
// 80 B row stride = 5 x 16B: ldmatrix-aligned and conflict-free (same as KPA).
#define HROW     80
#define LO_OFF   1280                     // 16 * 80
#define RANK_BLK 2560
#define HBUF     (CLUSTER * RANK_BLK)     // 20480

#define SMB_WHHI 0
#define SMB_WHLO (SMB_WHHI + 256 * WSTRIDE * 2)        // 69632
#define SMB_HB   (SMB_WHLO + 256 * WSTRIDE * 2)        // 139264
#define SMB_Z0   (SMB_HB + 2 * HBUF)                    // 180224
#define SMB_Z1   (SMB_Z0 + NB * ZSTRIDE * 4)            // 189184
#define SMB_C    (SMB_Z1 + NB * ZSTRIDE * 4)            // 198144
#define SMB_WO   (SMB_C + NB * 32 * 4)                  // 200192
#define SMB_BO   (SMB_WO + 5 * 256 * 4)                 // 205312
#define SMB_MBAR (SMB_BO + 32)                          // 205344 (2 x 8B)
#define SMB_EP   (SMB_MBAR + 16)                        // 205360
#define RSMEM_BYTES (SMB_EP + T_STEPS * NB)             // 213552

__device__ __forceinline__ void mbar_wait_cluster(uint32_t mbar, uint32_t parity) {
    uint32_t done;
    asm volatile(
        "{ .reg .pred p;\n"
        " mbarrier.try_wait.parity.acquire.cluster.shared::cta.b64 p, [%1], %2;\n"
        " selp.b32 %0, 1, 0, p; }"
        : "=r"(done) : "r"(mbar), "r"(parity) : "memory");
    while (!done) {
        asm volatile(
            "{ .reg .pred p;\n"
            " mbarrier.try_wait.parity.acquire.cluster.shared::cta.b64 p, [%1], %2, 0x989680;\n"
            " selp.b32 %0, 1, 0, p; }"
            : "=r"(done) : "r"(mbar), "r"(parity) : "memory");
    }
}

// fp32 output head (final timestep only); h in rank-blocked layout
__device__ __forceinline__ void do_head(
    const char* hb,           // buffer base (rank blocks)
    const float* Wo_s, const float* bo_s,
    float* out, int tt, int b0, int rank, int wid, int lane)
{
    float sacc[4];
    #pragma unroll
    for (int q = 0; q < 4; q++) {
        const float* wcol = &Wo_s[q * 256];
        float s = 0.f;
        #pragma unroll
        for (int uu = 0; uu < 8; uu++) {
            const char* blk = hb + uu * RANK_BLK + wid * HROW + lane * 2;
            float hv = __bfloat162float(*(const __nv_bfloat16*)blk)
                     + __bfloat162float(*(const __nv_bfloat16*)(blk + LO_OFF));
            s = fmaf(hv, wcol[lane + 32 * uu], s);
        }
        sacc[q] = s;
    }
    float sv = 0.f;
    if (rank == 0) {
        const float* wcol = &Wo_s[4 * 256];
        #pragma unroll
        for (int uu = 0; uu < 8; uu++) {
            const char* blk = hb + uu * RANK_BLK + wid * HROW + lane * 2;
            float hv = __bfloat162float(*(const __nv_bfloat16*)blk)
                     + __bfloat162float(*(const __nv_bfloat16*)(blk + LO_OFF));
            sv = fmaf(hv, wcol[lane + 32 * uu], sv);
        }
    }
    #pragma unroll
    for (int q = 0; q < 4; q++) {
        float s = sacc[q];
        #pragma unroll
        for (int off = 16; off; off >>= 1)
            s += __shfl_xor_sync(0xFFFFFFFFu, s, off);
        sacc[q] = s;
    }
    #pragma unroll
    for (int off = 16; off; off >>= 1)
        sv += __shfl_xor_sync(0xFFFFFFFFu, sv, off);
    if (lane == 0) {
        size_t obase = ((size_t)tt * BATCH + b0 + wid) * OUTC;
        #pragma unroll
        for (int q = 0; q < 4; q++)
            out[obase + rank + 8 * q] = sacc[q] + bo_s[q];
        if (rank == 0)
            out[obase + 32] = sv + bo_s[4];
    }
}

__global__ void __cluster_dims__(CLUSTER, 1, 1) __launch_bounds__(RTHREADS, 1)
lstm_rec_kernel(const int*   __restrict__ epi,
                const float* __restrict__ carry_c,
                const float* __restrict__ carry_h,
                const float* __restrict__ Wh,
                const float* __restrict__ Wa,
                const float* __restrict__ ba,
                const float* __restrict__ Wv,
                const float* __restrict__ bv,
                float*       __restrict__ out)
{
    extern __shared__ char smraw[];
    __nv_bfloat16* WhHi = (__nv_bfloat16*)(smraw + SMB_WHHI);
    __nv_bfloat16* WhLo = (__nv_bfloat16*)(smraw + SMB_WHLO);
    float* z0_s = (float*)(smraw + SMB_Z0);
    float* z1_s = (float*)(smraw + SMB_Z1);
    float* c_s  = (float*)(smraw + SMB_C);
    float* Wo_s = (float*)(smraw + SMB_WO);
    float* bo_s = (float*)(smraw + SMB_BO);
    unsigned char* ep_s = (unsigned char*)(smraw + SMB_EP);

    const int tid  = threadIdx.x;
    const int lane = tid & 31;
    const int wid  = tid >> 5;            // 0..15
    const int wn   = wid & 7;             // N-tile id within K-half
    const int kh   = wid >> 3;            // K-half: 0 or 1
    uint32_t rank;
    asm("mov.u32 %0, %%cluster_ctarank;" : "=r"(rank));
    const int cl = blockIdx.x / CLUSTER;
    const int b0 = cl * NB;
    const uint32_t smbase = smem_u32(smraw);

    // --- init mbarriers (count = 1: the local expect_tx arrival) ---
    if (tid == 0) {
        asm volatile("mbarrier.init.shared.b64 [%0], %1;"
            :: "r"(smbase + SMB_MBAR), "r"(1u) : "memory");
        asm volatile("mbarrier.init.shared.b64 [%0], %1;"
            :: "r"(smbase + SMB_MBAR + 8), "r"(1u) : "memory");
    }

    // --- preload Wh slice (split bf16), cols 0..127 ---
    for (int idx = tid; idx < 256 * LC; idx += RTHREADS) {
        int k = idx >> 7;
        int c = idx & 127;
        int gcol = ((c >> 5) << 8) + ((int)rank << 5) + (c & 31);
        float w = Wh[k * FOURH + gcol];
        __nv_bfloat16 hi = __float2bfloat16_rn(w);
        __nv_bfloat16 lo = __float2bfloat16_rn(w - __bfloat162float(hi));
        WhHi[k * WSTRIDE + c] = hi;
        WhLo[k * WSTRIDE + c] = lo;
    }
    // --- head columns into cols 128..135 ---
    for (int idx = tid; idx < 256 * 8; idx += RTHREADS) {
        int k = idx >> 3;
        int c = idx & 7;
        float w = 0.f;
        if (c < 4)                     w = Wa[k * NACT + (int)rank + 8 * c];
        else if (c == 4 && rank == 0)  w = Wv[k];
        __nv_bfloat16 hi = __float2bfloat16_rn(w);
        __nv_bfloat16 lo = __float2bfloat16_rn(w - __bfloat162float(hi));
        WhHi[k * WSTRIDE + 128 + c] = hi;
        WhLo[k * WSTRIDE + 128 + c] = lo;
    }
    // --- carry_h into buffer 1 (input for t=0), rank-blocked split bf16 ---
    for (int idx = tid; idx < NB * HID; idx += RTHREADS) {
        int b = idx >> 8;
        int k = idx & 255;
        float v = carry_h[(size_t)(b0 + b) * HID + k];
        __nv_bfloat16 hi = __float2bfloat16_rn(v);
        __nv_bfloat16 lo = __float2bfloat16_rn(v - __bfloat162float(hi));
        char* blk = smraw + SMB_HB + 1 * HBUF + (k >> 5) * RANK_BLK;
        *(__nv_bfloat16*)(blk + b * HROW + (k & 31) * 2) = hi;
        *(__nv_bfloat16*)(blk + LO_OFF + b * HROW + (k & 31) * 2) = lo;
    }
    // --- carry_c slice ---
    for (int idx = tid; idx < NB * 32; idx += RTHREADS) {
        int b = idx >> 5;
        int j = idx & 31;
        c_s[idx] = carry_c[(size_t)(b0 + b) * HID + (int)rank * 32 + j];
    }
    // --- fp32 head columns (final-step do_head) ---
    #pragma unroll
    for (int q = 0; q < 5; q++) {
        int col = (int)rank + 8 * q;
        if (col <= 32) {
            for (int k = tid; k < HID; k += RTHREADS)
                Wo_s[q * 256 + k] = (col < 32) ? Wa[k * NACT + col] : Wv[k];
            if (tid == 0) bo_s[q] = (col < 32) ? ba[col] : bv[0];
        }
    }
    // --- epi slice as bytes ---
    for (int idx = tid; idx < T_STEPS * NB; idx += RTHREADS) {
        int t = idx >> 4;
        int b = idx & 15;
        ep_s[idx] = (unsigned char)(epi[t * BATCH + b0 + b] != 0);
    }
    __syncthreads();
    asm volatile("barrier.cluster.arrive.aligned;" ::: "memory");
    asm volatile("barrier.cluster.wait.aligned;"   ::: "memory");

    // frag geometry
    const int a_row_l = (lane & 15);
    const int a_koff  = ((lane >> 4) << 3);
    const int b_krow  = (lane & 7) + ((lane >> 3) & 1) * 8;
    const int b_ncol  = ((lane >> 4) & 1) * 8;
    const int kbase   = kh * 128;              // this warp's K-half

    const uint32_t sWhHi = smem_u32(WhHi);
    const uint32_t sWhLo = smem_u32(WhLo);
    float* zw_s = kh ? z1_s : z0_s;

    int ph0 = 0, ph1 = 0;

    // gating mapping: one element per thread
    const int gb = tid >> 5;
    const int gj = tid & 31;

    // bulk-copy peer for tid < 7
    const int cp_peer = tid + (tid >= (int)rank);

    for (int t = 0; t < T_STEPS; t++) {
        const int p_out = t & 1;
        const int p_in  = p_out ^ 1;
        const uint32_t hinBase  = smbase + SMB_HB + (uint32_t)p_in * HBUF;
        char* houtB = smraw + SMB_HB + p_out * HBUF + (int)rank * RANK_BLK;

        // -- arm the barrier peers will complete for step t+1 data --
        if (tid == 0) {
            uint32_t mb = smbase + SMB_MBAR + (uint32_t)(((t + 1) & 1) * 8);
            asm volatile("mbarrier.arrive.expect_tx.shared.b64 _, [%0], %1;"
                :: "r"(mb), "r"((uint32_t)(7 * RANK_BLK)) : "memory");
        }

        // -- prefetch x_proj gate values (issued before the wait) --
        const size_t xbase = (size_t)t * BATCH * FOURH
                           + (size_t)(b0 + gb) * FOURH + (int)rank * 32 + gj;
        float xi = g_xproj[xbase];
        float xf = g_xproj[xbase + 256];
        float xg = g_xproj[xbase + 512];
        float xo = g_xproj[xbase + 768];
        int   ep = ep_s[t * NB + gb];

        // -- wait for peers' h blocks --
        if (t > 0) {
            if (t & 1) { mbar_wait_cluster(smbase + SMB_MBAR + 8, ph1); ph1 ^= 1; }
            else       { mbar_wait_cluster(smbase + SMB_MBAR,     ph0); ph0 ^= 1; }
        }

        // -- mma: z partial over this warp's K-half; head tile on wn==0 --
        {
            float acc[2][4][4];
            float accH[2][4];
            #pragma unroll
            for (int t2 = 0; t2 < 2; t2++) {
                #pragma unroll
                for (int kc = 0; kc < 4; kc++)
                    #pragma unroll
                    for (int q = 0; q < 4; q++) acc[t2][kc][q] = 0.f;
                #pragma unroll
                for (int q = 0; q < 4; q++) accH[t2][q] = 0.f;
            }

            #pragma unroll
            for (int ks = 0; ks < 8; ks++) {
                const int kk0 = kbase + ks * 16;
                const int kc  = ks & 3;
                const int blk = kk0 >> 5;
                uint32_t aoff = hinBase + (uint32_t)(blk * RANK_BLK
                               + a_row_l * HROW + ((kk0 & 16) + a_koff) * 2);
                uint32_t aHi[4], aLo[4];
                ldsm_x4(aHi, aoff);
                ldsm_x4(aLo, aoff + LO_OFF);
                uint32_t boff =
                    (uint32_t)((kk0 + b_krow) * WSTRIDE + wn * 16 + b_ncol) * 2;
                uint32_t bHi[4], bLo[4];
                ldsm_x4_t(bHi, sWhHi + boff);
                ldsm_x4_t(bLo, sWhLo + boff);
                #pragma unroll
                for (int t2 = 0; t2 < 2; t2++) {
                    mma_bf16(acc[t2][kc], aHi, bHi[t2 * 2], bHi[t2 * 2 + 1]);
                    mma_bf16(acc[t2][kc], aHi, bLo[t2 * 2], bLo[t2 * 2 + 1]);
                    mma_bf16(acc[t2][kc], aLo, bHi[t2 * 2], bHi[t2 * 2 + 1]);
                }
                if (wn == 0) {
                    uint32_t hoff = (uint32_t)((kk0 + b_krow) * WSTRIDE + 128) * 2;
                    uint32_t hH[2], hL[2];
                    ldsm_x2_t(hH, sWhHi + hoff);
                    ldsm_x2_t(hL, sWhLo + hoff);
                    const int kc2 = ks & 1;
                    mma_bf16(accH[kc2], aHi, hH[0], hH[1]);
                    mma_bf16(accH[kc2], aHi, hL[0], hL[1]);
                    mma_bf16(accH[kc2], aLo, hH[0], hH[1]);
                }
            }
            int r0 = lane >> 2;
            int cb = wn * 16 + 2 * (lane & 3);
            #pragma unroll
            for (int t2 = 0; t2 < 2; t2++) {
                int col = cb + 8 * t2;
                float v0 = (acc[t2][0][0] + acc[t2][1][0]) + (acc[t2][2][0] + acc[t2][3][0]);
                float v1 = (acc[t2][0][1] + acc[t2][1][1]) + (acc[t2][2][1] + acc[t2][3][1]);
                float v2 = (acc[t2][0][2] + acc[t2][1][2]) + (acc[t2][2][2] + acc[t2][3][2]);
                float v3 = (acc[t2][0][3] + acc[t2][1][3]) + (acc[t2][2][3] + acc[t2][3][3]);
                *(float2*)&zw_s[r0 * ZSTRIDE + col] = make_float2(v0, v1);
                *(float2*)&zw_s[(r0 + 8) * ZSTRIDE + col] = make_float2(v2, v3);
            }
            if (wn == 0) {
                int colH = 128 + 2 * (lane & 3);
                float h0 = accH[0][0] + accH[1][0];
                float h1 = accH[0][1] + accH[1][1];
                float h2 = accH[0][2] + accH[1][2];
                float h3 = accH[0][3] + accH[1][3];
                *(float2*)&zw_s[r0 * ZSTRIDE + colH] = make_float2(h0, h1);
                *(float2*)&zw_s[(r0 + 8) * ZSTRIDE + colH] = make_float2(h2, h3);
            }
        }
        __syncthreads();

        // -- write out(t-1): sum of the two K-half head partials --
        if (t > 0) {
            if (tid < 64) {
                int b = tid >> 2, q = tid & 3;
                out[((size_t)(t - 1) * BATCH + b0 + b) * OUTC + (int)rank + 8 * q]
                    = z0_s[b * ZSTRIDE + 128 + q] + z1_s[b * ZSTRIDE + 128 + q] + bo_s[q];
            } else if (rank == 0 && tid < 80) {
                int b = tid - 64;
                out[((size_t)(t - 1) * BATCH + b0 + b) * OUTC + 32]
                    = z0_s[b * ZSTRIDE + 132] + z1_s[b * ZSTRIDE + 132] + bo_s[4];
            }
        }

        // -- gating (1 element/thread; reset folded; MUFU-free) --
        {
            float zi = z0_s[gb * ZSTRIDE + gj]      + z1_s[gb * ZSTRIDE + gj];
            float zf = z0_s[gb * ZSTRIDE + 32 + gj] + z1_s[gb * ZSTRIDE + 32 + gj];
            float zg = z0_s[gb * ZSTRIDE + 64 + gj] + z1_s[gb * ZSTRIDE + 64 + gj];
            float zo = z0_s[gb * ZSTRIDE + 96 + gj] + z1_s[gb * ZSTRIDE + 96 + gj];
            float c_old = c_s[gb * 32 + gj];
            if (ep) { zi = 0.f; zf = 0.f; zg = 0.f; zo = 0.f; c_old = 0.f; }
            float iz = zi + xi;
            float fz = zf + xf;
            float gz = zg + xg;
            float oz = zo + xo;
            float nc = fsig(fz) * c_old + fsig(iz) * ftanh(gz);
            float nh = fsig(oz) * ftanh(nc);
            c_s[gb * 32 + gj] = nc;
            __nv_bfloat16 hi = __float2bfloat16_rn(nh);
            __nv_bfloat16 lo = __float2bfloat16_rn(nh - __bfloat162float(hi));
            *(__nv_bfloat16*)(houtB + gb * HROW + gj * 2) = hi;
            *(__nv_bfloat16*)(houtB + LO_OFF + gb * HROW + gj * 2) = lo;
        }
        __syncthreads();

        // -- bulk DSMEM copy of my 2560 B block to each peer + complete_tx --
        if (tid < 7) {
            asm volatile("fence.proxy.async.shared::cta;" ::: "memory");
            uint32_t src = smbase + (uint32_t)(SMB_HB + p_out * HBUF
                                               + (int)rank * RANK_BLK);
            uint32_t dst, mb;
            asm("mapa.shared::cluster.u32 %0, %1, %2;"
                : "=r"(dst) : "r"(src), "r"(cp_peer));
            uint32_t mbl = smbase + SMB_MBAR + (uint32_t)(((t + 1) & 1) * 8);
            asm("mapa.shared::cluster.u32 %0, %1, %2;"
                : "=r"(mb) : "r"(mbl), "r"(cp_peer));
            asm volatile(
                "cp.async.bulk.shared::cluster.shared::cta.mbarrier::complete_tx::bytes "
                "[%0], [%1], %2, [%3];"
                :: "r"(dst), "r"(src), "r"((uint32_t)RANK_BLK), "r"(mb) : "memory");
        }
    }

    // final wait + fp32 head for t = 511 (hout buffer = 1)
    {
        mbar_wait_cluster(smbase + SMB_MBAR, ph0);
        do_head(smraw + SMB_HB + 1 * HBUF, Wo_s, bo_s, out,
                T_STEPS - 1, b0, (int)rank, wid, lane);
    }

    asm volatile("barrier.cluster.arrive.aligned;" ::: "memory");
    asm volatile("barrier.cluster.wait.aligned;"   ::: "memory");
}

// ---------------------------------------------------------------------------
extern "C" void kernel_launch(void* const* d_in, const int* in_sizes, int n_in,
                              void* d_out, int out_size) {
    const float* inputs  = (const float*)d_in[0];
    const int*   epi     = (const int*)  d_in[1];
    const float* carry_c = (const float*)d_in[2];
    const float* carry_h = (const float*)d_in[3];
    const float* Wx      = (const float*)d_in[4];
    const float* Wh      = (const float*)d_in[5];
    const float* bias    = (const float*)d_in[6];
    const float* Wa      = (const float*)d_in[7];
    const float* ba      = (const float*)d_in[8];
    const float* Wv      = (const float*)d_in[9];
    const float* bv      = (const float*)d_in[10];
    float* out = (float*)d_out;

    cudaFuncSetAttribute(xproj_mma_kernel,
                         cudaFuncAttributeMaxDynamicSharedMemorySize, XSMEM_BYTES);
    cudaFuncSetAttribute(lstm_rec_kernel,
                         cudaFuncAttributeMaxDynamicSharedMemorySize, RSMEM_BYTES);

    dim3 g1(FOURH / XBN, (T_STEPS * BATCH) / XBM);
    xproj_mma_kernel<<<g1, 256, XSMEM_BYTES>>>(inputs, Wx, bias);

    lstm_rec_kernel<<<(BATCH / NB) * CLUSTER, RTHREADS, RSMEM_BYTES>>>(
        epi, carry_c, carry_h, Wh, Wa, ba, Wv, bv, out);
}

// round 11
// speedup vs baseline: 1.4589x; 1.0398x over previous
#include <cuda_runtime.h>
#include <cuda_bf16.h>
#include <cstdint>
#include <cstddef>

// Problem dims
#define T_STEPS 512
#define BATCH   256
#define DIM     512
#define HID     256
#define FOURH   1024
#define NACT    32
#define OUTC    33
#define M_ROWS  (T_STEPS * BATCH)   // 131072

// Global scratch
__device__ float g_xproj[(size_t)M_ROWS * FOURH];
__device__ __nv_bfloat16 g_ahi[(size_t)M_ROWS * DIM];
__device__ __nv_bfloat16 g_alo[(size_t)M_ROWS * DIM];
__device__ __nv_bfloat16 g_whi[(size_t)DIM * FOURH];
__device__ __nv_bfloat16 g_wlo[(size_t)DIM * FOURH];

// ===========================================================================
// Shared helpers
// ===========================================================================
__device__ __forceinline__ uint32_t smem_u32(const void* p) {
    uint32_t a;
    asm("{ .reg .u64 t; cvta.to.shared.u64 t, %1; cvt.u32.u64 %0, t; }"
        : "=r"(a) : "l"(p));
    return a;
}
__device__ __forceinline__ void ldsm_x4(uint32_t* r, uint32_t addr) {
    asm volatile("ldmatrix.sync.aligned.m8n8.x4.shared.b16 {%0,%1,%2,%3}, [%4];"
        : "=r"(r[0]), "=r"(r[1]), "=r"(r[2]), "=r"(r[3]) : "r"(addr));
}
__device__ __forceinline__ void ldsm_x4_t(uint32_t* r, uint32_t addr) {
    asm volatile("ldmatrix.sync.aligned.m8n8.x4.trans.shared.b16 {%0,%1,%2,%3}, [%4];"
        : "=r"(r[0]), "=r"(r[1]), "=r"(r[2]), "=r"(r[3]) : "r"(addr));
}
__device__ __forceinline__ void ldsm_x2_t(uint32_t* r, uint32_t addr) {
    asm volatile("ldmatrix.sync.aligned.m8n8.x2.trans.shared.b16 {%0,%1}, [%2];"
        : "=r"(r[0]), "=r"(r[1]) : "r"(addr));
}
__device__ __forceinline__ void mma_bf16(float* c, const uint32_t* a,
                                         uint32_t b0, uint32_t b1) {
    asm volatile(
        "mma.sync.aligned.m16n8k16.row.col.f32.bf16.bf16.f32 "
        "{%0,%1,%2,%3}, {%4,%5,%6,%7}, {%8,%9}, {%0,%1,%2,%3};"
        : "+f"(c[0]), "+f"(c[1]), "+f"(c[2]), "+f"(c[3])
        : "r"(a[0]), "r"(a[1]), "r"(a[2]), "r"(a[3]), "r"(b0), "r"(b1));
}
__device__ __forceinline__ uint32_t pack2(__nv_bfloat16 a, __nv_bfloat16 b) {
    union { __nv_bfloat162 v; uint32_t u; } c;
    c.v = __nv_bfloat162(a, b);
    return c.u;
}
__device__ __forceinline__ void split_store4(float4 v,
                                             __nv_bfloat16* hip,
                                             __nv_bfloat16* lop) {
    __nv_bfloat16 h0 = __float2bfloat16_rn(v.x);
    __nv_bfloat16 h1 = __float2bfloat16_rn(v.y);
    __nv_bfloat16 h2 = __float2bfloat16_rn(v.z);
    __nv_bfloat16 h3 = __float2bfloat16_rn(v.w);
    __nv_bfloat16 l0 = __float2bfloat16_rn(v.x - __bfloat162float(h0));
    __nv_bfloat16 l1 = __float2bfloat16_rn(v.y - __bfloat162float(h1));
    __nv_bfloat16 l2 = __float2bfloat16_rn(v.z - __bfloat162float(h2));
    __nv_bfloat16 l3 = __float2bfloat16_rn(v.w - __bfloat162float(h3));
    ((uint32_t*)hip)[0] = pack2(h0, h1);
    ((uint32_t*)hip)[1] = pack2(h2, h3);
    ((uint32_t*)lop)[0] = pack2(l0, l1);
    ((uint32_t*)lop)[1] = pack2(l2, l3);
}
__device__ __forceinline__ void cp16(uint32_t dst, const void* src) {
    asm volatile("cp.async.cg.shared.global [%0], [%1], 16;"
        :: "r"(dst), "l"(src) : "memory");
}
#define CP_COMMIT() asm volatile("cp.async.commit_group;" ::: "memory")
#define CP_WAIT1()  asm volatile("cp.async.wait_group 1;" ::: "memory")

// ---- MUFU-free activations ----
__device__ __forceinline__ float fast_exp(float x) {
    const float L2E = 1.4426950408889634f;
    float t  = fmaf(x, L2E, 12582912.0f);
    int   n  = __float_as_int(t) - 0x4B400000;
    float nf = t - 12582912.0f;
    float r  = fmaf(nf, -0.693359375f, x);
    r = fmaf(nf, 2.12194440e-4f, r);
    float p = 1.9841270e-4f;
    p = fmaf(p, r, 1.3888889e-3f);
    p = fmaf(p, r, 8.3333333e-3f);
    p = fmaf(p, r, 4.1666667e-2f);
    p = fmaf(p, r, 1.6666667e-1f);
    p = fmaf(p, r, 0.5f);
    p = fmaf(p, r, 1.0f);
    p = fmaf(p, r, 1.0f);
    return __int_as_float(__float_as_int(p) + (n << 23));
}
__device__ __forceinline__ float fast_rcp(float d) {
    float r = __int_as_float(0x7EF127EAu - __float_as_int(d));
    r = r * fmaf(-d, r, 2.0f);
    r = r * fmaf(-d, r, 2.0f);
    return r;
}
__device__ __forceinline__ float fsig(float x) {
    x = fminf(fmaxf(x, -30.0f), 30.0f);
    float e = fast_exp(-x);
    return fast_rcp(1.0f + e);
}
__device__ __forceinline__ float ftanh(float x) {
    return fmaf(2.0f, fsig(2.0f * x), -1.0f);
}

// ===========================================================================
// Kernel 0: split inputs + Wx into global bf16 hi/lo (memory-bound pre-pass)
// ===========================================================================
__global__ __launch_bounds__(256) void split_kernel(
    const float* __restrict__ A, const float* __restrict__ W)
{
    const size_t A4 = (size_t)M_ROWS * DIM / 4;     // 16777216
    const size_t W4 = (size_t)DIM * FOURH / 4;      // 131072
    size_t stride = (size_t)gridDim.x * blockDim.x;
    for (size_t i = (size_t)blockIdx.x * blockDim.x + threadIdx.x;
         i < A4 + W4; i += stride) {
        float4 v;
        __nv_bfloat16 *hp, *lp;
        if (i < A4) {
            v = ((const float4*)A)[i];
            hp = g_ahi + i * 4;
            lp = g_alo + i * 4;
        } else {
            size_t j = i - A4;
            v = ((const float4*)W)[j];
            hp = g_whi + j * 4;
            lp = g_wlo + j * 4;
        }
        split_store4(v, hp, lp);
    }
}

// ===========================================================================
// Kernel 1: x_proj GEMM — pre-split bf16 operands, cp.async 3-stage pipeline.
// Block tile 128x128x32, 256 threads, 8 warps (4M x 2N), warp tile 32x64.
// ===========================================================================
#define X2_A_BYTES (128 * 80)                 // Ahi per stage (row stride 80 B)
#define X2_W_BYTES (32 * 272)                 // Whi per stage (row stride 272 B)
#define X2_STAGE   (2 * X2_A_BYTES + 2 * X2_W_BYTES)   // 37888
#define X2_SMEM    (3 * X2_STAGE)             // 113664

__global__ __launch_bounds__(256) void xproj_mma_kernel(
    const float* __restrict__ bias)
{
    extern __shared__ char xsm2[];
    const uint32_t smb = smem_u32(xsm2);

    const int tid   = threadIdx.x;
    const int lane  = tid & 31;
    const int wid   = tid >> 5;
    const int warpM = wid & 3;
    const int warpN = wid >> 2;
    const int bM    = blockIdx.y;
    const int bN    = blockIdx.x;

    const size_t aRowBase = (size_t)bM * 128;
    const size_t wColBase = (size_t)bN * 128;

    float acc[2][8][4];
    #pragma unroll
    for (int mt = 0; mt < 2; mt++)
        #pragma unroll
        for (int j = 0; j < 8; j++)
            #pragma unroll
            for (int q = 0; q < 4; q++) acc[mt][j][q] = 0.f;

    const int a_row_l = (lane & 15);
    const int a_koff  = ((lane >> 4) << 3);
    const int b_krow  = (lane & 7) + ((lane >> 3) & 1) * 8;
    const int b_ncol  = ((lane >> 4) & 1) * 8;

    // per-thread loader geometry (2 chunks per array per stage)
    const int ar0 = tid >> 2, ac0 = tid & 3;          // A chunk: id = tid + 256*i
    const int kr0 = tid >> 4, c160 = tid & 15;        // W chunk

    // issue one stage's cp.asyncs
    auto issue = [&](int st, int k0) {
        uint32_t base = smb + st * X2_STAGE;
        #pragma unroll
        for (int i = 0; i < 2; i++) {
            int id = tid + 256 * i;
            int ar = (i == 0) ? ar0 : (ar0 + 64);
            int ac = ac0;
            size_t asrc = (aRowBase + ar) * DIM + k0 + ac * 8;
            cp16(base + ar * 80 + ac * 16, g_ahi + asrc);
            cp16(base + X2_A_BYTES + ar * 80 + ac * 16, g_alo + asrc);
            int kr = (i == 0) ? kr0 : (kr0 + 16);
            int c16 = c160;
            size_t wsrc = (size_t)(k0 + kr) * FOURH + wColBase + c16 * 8;
            cp16(base + 2 * X2_A_BYTES + kr * 272 + c16 * 16, g_whi + wsrc);
            cp16(base + 2 * X2_A_BYTES + X2_W_BYTES + kr * 272 + c16 * 16,
                 g_wlo + wsrc);
            (void)id;
        }
    };

    issue(0, 0);  CP_COMMIT();
    issue(1, 32); CP_COMMIT();

    const int NSTAGE = DIM / 32;   // 16

    for (int s = 0; s < NSTAGE; s++) {
        CP_WAIT1();
        __syncthreads();

        if (s + 2 < NSTAGE) {
            issue((s + 2) % 3, (s + 2) * 32);
            CP_COMMIT();
        } else {
            CP_COMMIT();   // keep group accounting uniform
        }

        // compute stage s%3
        uint32_t sAhi = smb + (s % 3) * X2_STAGE;
        uint32_t sAlo = sAhi + X2_A_BYTES;
        uint32_t sBhi = sAhi + 2 * X2_A_BYTES;
        uint32_t sBlo = sBhi + X2_W_BYTES;

        #pragma unroll
        for (int ks = 0; ks < 2; ks++) {
            const int kk0 = ks * 16;
            uint32_t aHi[2][4], aLo[2][4];
            #pragma unroll
            for (int mt = 0; mt < 2; mt++) {
                uint32_t off =
                    (uint32_t)((warpM * 32 + mt * 16 + a_row_l) * 40 + kk0 + a_koff) * 2;
                ldsm_x4(aHi[mt], sAhi + off);
                ldsm_x4(aLo[mt], sAlo + off);
            }
            uint32_t bHi[4][4], bLo[4][4];
            #pragma unroll
            for (int nt = 0; nt < 4; nt++) {
                uint32_t off =
                    (uint32_t)((kk0 + b_krow) * 136 + warpN * 64 + nt * 16 + b_ncol) * 2;
                ldsm_x4_t(bHi[nt], sBhi + off);
                ldsm_x4_t(bLo[nt], sBlo + off);
            }
            #pragma unroll
            for (int mt = 0; mt < 2; mt++) {
                #pragma unroll
                for (int j = 0; j < 8; j++) {
                    uint32_t bh0 = bHi[j >> 1][(j & 1) * 2];
                    uint32_t bh1 = bHi[j >> 1][(j & 1) * 2 + 1];
                    uint32_t bl0 = bLo[j >> 1][(j & 1) * 2];
                    uint32_t bl1 = bLo[j >> 1][(j & 1) * 2 + 1];
                    mma_bf16(acc[mt][j], aHi[mt], bh0, bh1);
                    mma_bf16(acc[mt][j], aHi[mt], bl0, bl1);
                    mma_bf16(acc[mt][j], aLo[mt], bh0, bh1);
                }
            }
        }
    }

    // epilogue: add bias, write fp32
    const int g  = lane >> 2;
    const int t2 = (lane & 3) * 2;
    #pragma unroll
    for (int mt = 0; mt < 2; mt++) {
        size_t row = aRowBase + warpM * 32 + mt * 16 + g;
        #pragma unroll
        for (int j = 0; j < 8; j++) {
            int col = (int)wColBase + warpN * 64 + j * 8 + t2;
            float b0 = bias[col], b1 = bias[col + 1];
            float2 o0 = make_float2(acc[mt][j][0] + b0, acc[mt][j][1] + b1);
            float2 o1 = make_float2(acc[mt][j][2] + b0, acc[mt][j][3] + b1);
            *(float2*)&g_xproj[row * FOURH + col] = o0;
            *(float2*)&g_xproj[(row + 8) * FOURH + col] = o1;
        }
    }
}

// ===========================================================================
// Kernel 2: recurrent kernel — UNCHANGED from R10 (bulk DSMEM + complete_tx).
// ===========================================================================
#define CLUSTER 8
#define NB      16
#define LC      128
#define RTHREADS 512

#define WSTRIDE 136
#define ZSTRIDE 140

#define HROW     80
#define LO_OFF   1280
#define RANK_BLK 2560
#define HBUF     (CLUSTER * RANK_BLK)

#define SMB_WHHI 0
#define SMB_WHLO (SMB_WHHI + 256 * WSTRIDE * 2)
#define SMB_HB   (SMB_WHLO + 256 * WSTRIDE * 2)
#define SMB_Z0   (SMB_HB + 2 * HBUF)
#define SMB_Z1   (SMB_Z0 + NB * ZSTRIDE * 4)
#define SMB_C    (SMB_Z1 + NB * ZSTRIDE * 4)
#define SMB_WO   (SMB_C + NB * 32 * 4)
#define SMB_BO   (SMB_WO + 5 * 256 * 4)
#define SMB_MBAR (SMB_BO + 32)
#define SMB_EP   (SMB_MBAR + 16)
#define RSMEM_BYTES (SMB_EP + T_STEPS * NB)

__device__ __forceinline__ void mbar_wait_cluster(uint32_t mbar, uint32_t parity) {
    uint32_t done;
    asm volatile(
        "{ .reg .pred p;\n"
        " mbarrier.try_wait.parity.acquire.cluster.shared::cta.b64 p, [%1], %2;\n"
        " selp.b32 %0, 1, 0, p; }"
        : "=r"(done) : "r"(mbar), "r"(parity) : "memory");
    while (!done) {
        asm volatile(
            "{ .reg .pred p;\n"
            " mbarrier.try_wait.parity.acquire.cluster.shared::cta.b64 p, [%1], %2, 0x989680;\n"
            " selp.b32 %0, 1, 0, p; }"
            : "=r"(done) : "r"(mbar), "r"(parity) : "memory");
    }
}

__device__ __forceinline__ void do_head(
    const char* hb,
    const float* Wo_s, const float* bo_s,
    float* out, int tt, int b0, int rank, int wid, int lane)
{
    float sacc[4];
    #pragma unroll
    for (int q = 0; q < 4; q++) {
        const float* wcol = &Wo_s[q * 256];
        float s = 0.f;
        #pragma unroll
        for (int uu = 0; uu < 8; uu++) {
            const char* blk = hb + uu * RANK_BLK + wid * HROW + lane * 2;
            float hv = __bfloat162float(*(const __nv_bfloat16*)blk)
                     + __bfloat162float(*(const __nv_bfloat16*)(blk + LO_OFF));
            s = fmaf(hv, wcol[lane + 32 * uu], s);
        }
        sacc[q] = s;
    }
    float sv = 0.f;
    if (rank == 0) {
        const float* wcol = &Wo_s[4 * 256];
        #pragma unroll
        for (int uu = 0; uu < 8; uu++) {
            const char* blk = hb + uu * RANK_BLK + wid * HROW + lane * 2;
            float hv = __bfloat162float(*(const __nv_bfloat16*)blk)
                     + __bfloat162float(*(const __nv_bfloat16*)(blk + LO_OFF));
            sv = fmaf(hv, wcol[lane + 32 * uu], sv);
        }
    }
    #pragma unroll
    for (int q = 0; q < 4; q++) {
        float s = sacc[q];
        #pragma unroll
        for (int off = 16; off; off >>= 1)
            s += __shfl_xor_sync(0xFFFFFFFFu, s, off);
        sacc[q] = s;
    }
    #pragma unroll
    for (int off = 16; off; off >>= 1)
        sv += __shfl_xor_sync(0xFFFFFFFFu, sv, off);
    if (lane == 0) {
        size_t obase = ((size_t)tt * BATCH + b0 + wid) * OUTC;
        #pragma unroll
        for (int q = 0; q < 4; q++)
            out[obase + rank + 8 * q] = sacc[q] + bo_s[q];
        if (rank == 0)
            out[obase + 32] = sv + bo_s[4];
    }
}

__global__ void __cluster_dims__(CLUSTER, 1, 1) __launch_bounds__(RTHREADS, 1)
lstm_rec_kernel(const int*   __restrict__ epi,
                const float* __restrict__ carry_c,
                const float* __restrict__ carry_h,
                const float* __restrict__ Wh,
                const float* __restrict__ Wa,
                const float* __restrict__ ba,
                const float* __restrict__ Wv,
                const float* __restrict__ bv,
                float*       __restrict__ out)
{
    extern __shared__ char smraw[];
    __nv_bfloat16* WhHi = (__nv_bfloat16*)(smraw + SMB_WHHI);
    __nv_bfloat16* WhLo = (__nv_bfloat16*)(smraw + SMB_WHLO);
    float* z0_s = (float*)(smraw + SMB_Z0);
    float* z1_s = (float*)(smraw + SMB_Z1);
    float* c_s  = (float*)(smraw + SMB_C);
    float* Wo_s = (float*)(smraw + SMB_WO);
    float* bo_s = (float*)(smraw + SMB_BO);
    unsigned char* ep_s = (unsigned char*)(smraw + SMB_EP);

    const int tid  = threadIdx.x;
    const int lane = tid & 31;
    const int wid  = tid >> 5;
    const int wn   = wid & 7;
    const int kh   = wid >> 3;
    uint32_t rank;
    asm("mov.u32 %0, %%cluster_ctarank;" : "=r"(rank));
    const int cl = blockIdx.x / CLUSTER;
    const int b0 = cl * NB;
    const uint32_t smbase = smem_u32(smraw);

    if (tid == 0) {
        asm volatile("mbarrier.init.shared.b64 [%0], %1;"
            :: "r"(smbase + SMB_MBAR), "r"(1u) : "memory");
        asm volatile("mbarrier.init.shared.b64 [%0], %1;"
            :: "r"(smbase + SMB_MBAR + 8), "r"(1u) : "memory");
    }

    for (int idx = tid; idx < 256 * LC; idx += RTHREADS) {
        int k = idx >> 7;
        int c = idx & 127;
        int gcol = ((c >> 5) << 8) + ((int)rank << 5) + (c & 31);
        float w = Wh[k * FOURH + gcol];
        __nv_bfloat16 hi = __float2bfloat16_rn(w);
        __nv_bfloat16 lo = __float2bfloat16_rn(w - __bfloat162float(hi));
        WhHi[k * WSTRIDE + c] = hi;
        WhLo[k * WSTRIDE + c] = lo;
    }
    for (int idx = tid; idx < 256 * 8; idx += RTHREADS) {
        int k = idx >> 3;
        int c = idx & 7;
        float w = 0.f;
        if (c < 4)                     w = Wa[k * NACT + (int)rank + 8 * c];
        else if (c == 4 && rank == 0)  w = Wv[k];
        __nv_bfloat16 hi = __float2bfloat16_rn(w);
        __nv_bfloat16 lo = __float2bfloat16_rn(w - __bfloat162float(hi));
        WhHi[k * WSTRIDE + 128 + c] = hi;
        WhLo[k * WSTRIDE + 128 + c] = lo;
    }
    for (int idx = tid; idx < NB * HID; idx += RTHREADS) {
        int b = idx >> 8;
        int k = idx & 255;
        float v = carry_h[(size_t)(b0 + b) * HID + k];
        __nv_bfloat16 hi = __float2bfloat16_rn(v);
        __nv_bfloat16 lo = __float2bfloat16_rn(v - __bfloat162float(hi));
        char* blk = smraw + SMB_HB + 1 * HBUF + (k >> 5) * RANK_BLK;
        *(__nv_bfloat16*)(blk + b * HROW + (k & 31) * 2) = hi;
        *(__nv_bfloat16*)(blk + LO_OFF + b * HROW + (k & 31) * 2) = lo;
    }
    for (int idx = tid; idx < NB * 32; idx += RTHREADS) {
        int b = idx >> 5;
        int j = idx & 31;
        c_s[idx] = carry_c[(size_t)(b0 + b) * HID + (int)rank * 32 + j];
    }
    #pragma unroll
    for (int q = 0; q < 5; q++) {
        int col = (int)rank + 8 * q;
        if (col <= 32) {
            for (int k = tid; k < HID; k += RTHREADS)
                Wo_s[q * 256 + k] = (col < 32) ? Wa[k * NACT + col] : Wv[k];
            if (tid == 0) bo_s[q] = (col < 32) ? ba[col] : bv[0];
        }
    }
    for (int idx = tid; idx < T_STEPS * NB; idx += RTHREADS) {
        int t = idx >> 4;
        int b = idx & 15;
        ep_s[idx] = (unsigned char)(epi[t * BATCH + b0 + b] != 0);
    }
    __syncthreads();
    asm volatile("barrier.cluster.arrive.aligned;" ::: "memory");
    asm volatile("barrier.cluster.wait.aligned;"   ::: "memory");

    const int a_row_l = (lane & 15);
    const int a_koff  = ((lane >> 4) << 3);
    const int b_krow  = (lane & 7) + ((lane >> 3) & 1) * 8;
    const int b_ncol  = ((lane >> 4) & 1) * 8;
    const int kbase   = kh * 128;

    const uint32_t sWhHi = smem_u32(WhHi);
    const uint32_t sWhLo = smem_u32(WhLo);
    float* zw_s = kh ? z1_s : z0_s;

    int ph0 = 0, ph1 = 0;

    const int gb = tid >> 5;
    const int gj = tid & 31;

    const int cp_peer = tid + (tid >= (int)rank);

    for (int t = 0; t < T_STEPS; t++) {
        const int p_out = t & 1;
        const int p_in  = p_out ^ 1;
        const uint32_t hinBase  = smbase + SMB_HB + (uint32_t)p_in * HBUF;
        char* houtB = smraw + SMB_HB + p_out * HBUF + (int)rank * RANK_BLK;

        if (tid == 0) {
            uint32_t mb = smbase + SMB_MBAR + (uint32_t)(((t + 1) & 1) * 8);
            asm volatile("mbarrier.arrive.expect_tx.shared.b64 _, [%0], %1;"
                :: "r"(mb), "r"((uint32_t)(7 * RANK_BLK)) : "memory");
        }

        const size_t xbase = (size_t)t * BATCH * FOURH
                           + (size_t)(b0 + gb) * FOURH + (int)rank * 32 + gj;
        float xi = g_xproj[xbase];
        float xf = g_xproj[xbase + 256];
        float xg = g_xproj[xbase + 512];
        float xo = g_xproj[xbase + 768];
        int   ep = ep_s[t * NB + gb];

        if (t > 0) {
            if (t & 1) { mbar_wait_cluster(smbase + SMB_MBAR + 8, ph1); ph1 ^= 1; }
            else       { mbar_wait_cluster(smbase + SMB_MBAR,     ph0); ph0 ^= 1; }
        }

        {
            float acc[2][4][4];
            float accH[2][4];
            #pragma unroll
            for (int t2 = 0; t2 < 2; t2++) {
                #pragma unroll
                for (int kc = 0; kc < 4; kc++)
                    #pragma unroll
                    for (int q = 0; q < 4; q++) acc[t2][kc][q] = 0.f;
                #pragma unroll
                for (int q = 0; q < 4; q++) accH[t2][q] = 0.f;
            }

            #pragma unroll
            for (int ks = 0; ks < 8; ks++) {
                const int kk0 = kbase + ks * 16;
                const int kc  = ks & 3;
                const int blk = kk0 >> 5;
                uint32_t aoff = hinBase + (uint32_t)(blk * RANK_BLK
                               + a_row_l * HROW + ((kk0 & 16) + a_koff) * 2);
                uint32_t aHi[4], aLo[4];
                ldsm_x4(aHi, aoff);
                ldsm_x4(aLo, aoff + LO_OFF);
                uint32_t boff =
                    (uint32_t)((kk0 + b_krow) * WSTRIDE + wn * 16 + b_ncol) * 2;
                uint32_t bHi[4], bLo[4];
                ldsm_x4_t(bHi, sWhHi + boff);
                ldsm_x4_t(bLo, sWhLo + boff);
                #pragma unroll
                for (int t2 = 0; t2 < 2; t2++) {
                    mma_bf16(acc[t2][kc], aHi, bHi[t2 * 2], bHi[t2 * 2 + 1]);
                    mma_bf16(acc[t2][kc], aHi, bLo[t2 * 2], bLo[t2 * 2 + 1]);
                    mma_bf16(acc[t2][kc], aLo, bHi[t2 * 2], bHi[t2 * 2 + 1]);
                }
                if (wn == 0) {
                    uint32_t hoff = (uint32_t)((kk0 + b_krow) * WSTRIDE + 128) * 2;
                    uint32_t hH[2], hL[2];
                    ldsm_x2_t(hH, sWhHi + hoff);
                    ldsm_x2_t(hL, sWhLo + hoff);
                    const int kc2 = ks & 1;
                    mma_bf16(accH[kc2], aHi, hH[0], hH[1]);
                    mma_bf16(accH[kc2], aHi, hL[0], hL[1]);
                    mma_bf16(accH[kc2], aLo, hH[0], hH[1]);
                }
            }
            int r0 = lane >> 2;
            int cb = wn * 16 + 2 * (lane & 3);
            #pragma unroll
            for (int t2 = 0; t2 < 2; t2++) {
                int col = cb + 8 * t2;
                float v0 = (acc[t2][0][0] + acc[t2][1][0]) + (acc[t2][2][0] + acc[t2][3][0]);
                float v1 = (acc[t2][0][1] + acc[t2][1][1]) + (acc[t2][2][1] + acc[t2][3][1]);
                float v2 = (acc[t2][0][2] + acc[t2][1][2]) + (acc[t2][2][2] + acc[t2][3][2]);
                float v3 = (acc[t2][0][3] + acc[t2][1][3]) + (acc[t2][2][3] + acc[t2][3][3]);
                *(float2*)&zw_s[r0 * ZSTRIDE + col] = make_float2(v0, v1);
                *(float2*)&zw_s[(r0 + 8) * ZSTRIDE + col] = make_float2(v2, v3);
            }
            if (wn == 0) {
                int colH = 128 + 2 * (lane & 3);
                float h0 = accH[0][0] + accH[1][0];
                float h1 = accH[0][1] + accH[1][1];
                float h2 = accH[0][2] + accH[1][2];
                float h3 = accH[0][3] + accH[1][3];
                *(float2*)&zw_s[r0 * ZSTRIDE + colH] = make_float2(h0, h1);
                *(float2*)&zw_s[(r0 + 8) * ZSTRIDE + colH] = make_float2(h2, h3);
            }
        }
        __syncthreads();

        if (t > 0) {
            if (tid < 64) {
                int b = tid >> 2, q = tid & 3;
                out[((size_t)(t - 1) * BATCH + b0 + b) * OUTC + (int)rank + 8 * q]
                    = z0_s[b * ZSTRIDE + 128 + q] + z1_s[b * ZSTRIDE + 128 + q] + bo_s[q];
            } else if (rank == 0 && tid < 80) {
                int b = tid - 64;
                out[((size_t)(t - 1) * BATCH + b0 + b) * OUTC + 32]
                    = z0_s[b * ZSTRIDE + 132] + z1_s[b * ZSTRIDE + 132] + bo_s[4];
            }
        }

        {
            float zi = z0_s[gb * ZSTRIDE + gj]      + z1_s[gb * ZSTRIDE + gj];
            float zf = z0_s[gb * ZSTRIDE + 32 + gj] + z1_s[gb * ZSTRIDE + 32 + gj];
            float zg = z0_s[gb * ZSTRIDE + 64 + gj] + z1_s[gb * ZSTRIDE + 64 + gj];
            float zo = z0_s[gb * ZSTRIDE + 96 + gj] + z1_s[gb * ZSTRIDE + 96 + gj];
            float c_old = c_s[gb * 32 + gj];
            if (ep) { zi = 0.f; zf = 0.f; zg = 0.f; zo = 0.f; c_old = 0.f; }
            float iz = zi + xi;
            float fz = zf + xf;
            float gz = zg + xg;
            float oz = zo + xo;
            float nc = fsig(fz) * c_old + fsig(iz) * ftanh(gz);
            float nh = fsig(oz) * ftanh(nc);
            c_s[gb * 32 + gj] = nc;
            __nv_bfloat16 hi = __float2bfloat16_rn(nh);
            __nv_bfloat16 lo = __float2bfloat16_rn(nh - __bfloat162float(hi));
            *(__nv_bfloat16*)(houtB + gb * HROW + gj * 2) = hi;
            *(__nv_bfloat16*)(houtB + LO_OFF + gb * HROW + gj * 2) = lo;
        }
        __syncthreads();

        if (tid < 7) {
            asm volatile("fence.proxy.async.shared::cta;" ::: "memory");
            uint32_t src = smbase + (uint32_t)(SMB_HB + p_out * HBUF
                                               + (int)rank * RANK_BLK);
            uint32_t dst, mb;
            asm("mapa.shared::cluster.u32 %0, %1, %2;"
                : "=r"(dst) : "r"(src), "r"(cp_peer));
            uint32_t mbl = smbase + SMB_MBAR + (uint32_t)(((t + 1) & 1) * 8);
            asm("mapa.shared::cluster.u32 %0, %1, %2;"
                : "=r"(mb) : "r"(mbl), "r"(cp_peer));
            asm volatile(
                "cp.async.bulk.shared::cluster.shared::cta.mbarrier::complete_tx::bytes "
                "[%0], [%1], %2, [%3];"
                :: "r"(dst), "r"(src), "r"((uint32_t)RANK_BLK), "r"(mb) : "memory");
        }
    }

    {
        mbar_wait_cluster(smbase + SMB_MBAR, ph0);
        do_head(smraw + SMB_HB + 1 * HBUF, Wo_s, bo_s, out,
                T_STEPS - 1, b0, (int)rank, wid, lane);
    }

    asm volatile("barrier.cluster.arrive.aligned;" ::: "memory");
    asm volatile("barrier.cluster.wait.aligned;"   ::: "memory");
}

// ---------------------------------------------------------------------------
extern "C" void kernel_launch(void* const* d_in, const int* in_sizes, int n_in,
                              void* d_out, int out_size) {
    const float* inputs  = (const float*)d_in[0];
    const int*   epi     = (const int*)  d_in[1];
    const float* carry_c = (const float*)d_in[2];
    const float* carry_h = (const float*)d_in[3];
    const float* Wx      = (const float*)d_in[4];
    const float* Wh      = (const float*)d_in[5];
    const float* bias    = (const float*)d_in[6];
    const float* Wa      = (const float*)d_in[7];
    const float* ba      = (const float*)d_in[8];
    const float* Wv      = (const float*)d_in[9];
    const float* bv      = (const float*)d_in[10];
    float* out = (float*)d_out;

    cudaFuncSetAttribute(xproj_mma_kernel,
                         cudaFuncAttributeMaxDynamicSharedMemorySize, X2_SMEM);
    cudaFuncSetAttribute(lstm_rec_kernel,
                         cudaFuncAttributeMaxDynamicSharedMemorySize, RSMEM_BYTES);

    split_kernel<<<2048, 256>>>(inputs, Wx);

    dim3 g1(FOURH / 128, M_ROWS / 128);   // (8, 1024)
    xproj_mma_kernel<<<g1, 256, X2_SMEM>>>(bias);

    lstm_rec_kernel<<<(BATCH / NB) * CLUSTER, RTHREADS, RSMEM_BYTES>>>(
        epi, carry_c, carry_h, Wh, Wa, ba, Wv, bv, out);
}

// round 12
// speedup vs baseline: 1.4598x; 1.0006x over previous
#include <cuda_runtime.h>
#include <cuda_bf16.h>
#include <cstdint>
#include <cstddef>

// Problem dims
#define T_STEPS 512
#define BATCH   256
#define DIM     512
#define HID     256
#define FOURH   1024
#define NACT    32
#define OUTC    33
#define M_ROWS  (T_STEPS * BATCH)   // 131072

// Global scratch
__device__ float g_xproj[(size_t)M_ROWS * FOURH];
__device__ __nv_bfloat16 g_ahi[(size_t)M_ROWS * DIM];
__device__ __nv_bfloat16 g_alo[(size_t)M_ROWS * DIM];
__device__ __nv_bfloat16 g_whi[(size_t)DIM * FOURH];
__device__ __nv_bfloat16 g_wlo[(size_t)DIM * FOURH];

// ===========================================================================
// Shared helpers
// ===========================================================================
__device__ __forceinline__ uint32_t smem_u32(const void* p) {
    uint32_t a;
    asm("{ .reg .u64 t; cvta.to.shared.u64 t, %1; cvt.u32.u64 %0, t; }"
        : "=r"(a) : "l"(p));
    return a;
}
__device__ __forceinline__ void ldsm_x4(uint32_t* r, uint32_t addr) {
    asm volatile("ldmatrix.sync.aligned.m8n8.x4.shared.b16 {%0,%1,%2,%3}, [%4];"
        : "=r"(r[0]), "=r"(r[1]), "=r"(r[2]), "=r"(r[3]) : "r"(addr));
}
__device__ __forceinline__ void ldsm_x4_t(uint32_t* r, uint32_t addr) {
    asm volatile("ldmatrix.sync.aligned.m8n8.x4.trans.shared.b16 {%0,%1,%2,%3}, [%4];"
        : "=r"(r[0]), "=r"(r[1]), "=r"(r[2]), "=r"(r[3]) : "r"(addr));
}
__device__ __forceinline__ void ldsm_x2_t(uint32_t* r, uint32_t addr) {
    asm volatile("ldmatrix.sync.aligned.m8n8.x2.trans.shared.b16 {%0,%1}, [%2];"
        : "=r"(r[0]), "=r"(r[1]) : "r"(addr));
}
__device__ __forceinline__ void mma_bf16(float* c, const uint32_t* a,
                                         uint32_t b0, uint32_t b1) {
    asm volatile(
        "mma.sync.aligned.m16n8k16.row.col.f32.bf16.bf16.f32 "
        "{%0,%1,%2,%3}, {%4,%5,%6,%7}, {%8,%9}, {%0,%1,%2,%3};"
        : "+f"(c[0]), "+f"(c[1]), "+f"(c[2]), "+f"(c[3])
        : "r"(a[0]), "r"(a[1]), "r"(a[2]), "r"(a[3]), "r"(b0), "r"(b1));
}
__device__ __forceinline__ uint32_t pack2(__nv_bfloat16 a, __nv_bfloat16 b) {
    union { __nv_bfloat162 v; uint32_t u; } c;
    c.v = __nv_bfloat162(a, b);
    return c.u;
}
__device__ __forceinline__ void split_store4(float4 v,
                                             __nv_bfloat16* hip,
                                             __nv_bfloat16* lop) {
    __nv_bfloat16 h0 = __float2bfloat16_rn(v.x);
    __nv_bfloat16 h1 = __float2bfloat16_rn(v.y);
    __nv_bfloat16 h2 = __float2bfloat16_rn(v.z);
    __nv_bfloat16 h3 = __float2bfloat16_rn(v.w);
    __nv_bfloat16 l0 = __float2bfloat16_rn(v.x - __bfloat162float(h0));
    __nv_bfloat16 l1 = __float2bfloat16_rn(v.y - __bfloat162float(h1));
    __nv_bfloat16 l2 = __float2bfloat16_rn(v.z - __bfloat162float(h2));
    __nv_bfloat16 l3 = __float2bfloat16_rn(v.w - __bfloat162float(h3));
    ((uint32_t*)hip)[0] = pack2(h0, h1);
    ((uint32_t*)hip)[1] = pack2(h2, h3);
    ((uint32_t*)lop)[0] = pack2(l0, l1);
    ((uint32_t*)lop)[1] = pack2(l2, l3);
}
__device__ __forceinline__ void cp16(uint32_t dst, const void* src) {
    asm volatile("cp.async.cg.shared.global [%0], [%1], 16;"
        :: "r"(dst), "l"(src) : "memory");
}
#define CP_COMMIT() asm volatile("cp.async.commit_group;" ::: "memory")
#define CP_WAIT1()  asm volatile("cp.async.wait_group 1;" ::: "memory")

// ---- MUFU-free activations ----
__device__ __forceinline__ float fast_exp(float x) {
    const float L2E = 1.4426950408889634f;
    float t  = fmaf(x, L2E, 12582912.0f);
    int   n  = __float_as_int(t) - 0x4B400000;
    float nf = t - 12582912.0f;
    float r  = fmaf(nf, -0.693359375f, x);
    r = fmaf(nf, 2.12194440e-4f, r);
    float p = 1.9841270e-4f;
    p = fmaf(p, r, 1.3888889e-3f);
    p = fmaf(p, r, 8.3333333e-3f);
    p = fmaf(p, r, 4.1666667e-2f);
    p = fmaf(p, r, 1.6666667e-1f);
    p = fmaf(p, r, 0.5f);
    p = fmaf(p, r, 1.0f);
    p = fmaf(p, r, 1.0f);
    return __int_as_float(__float_as_int(p) + (n << 23));
}
__device__ __forceinline__ float fast_rcp(float d) {
    float r = __int_as_float(0x7EF127EAu - __float_as_int(d));
    r = r * fmaf(-d, r, 2.0f);
    r = r * fmaf(-d, r, 2.0f);
    return r;
}
__device__ __forceinline__ float fsig(float x) {
    x = fminf(fmaxf(x, -30.0f), 30.0f);
    float e = fast_exp(-x);
    return fast_rcp(1.0f + e);
}
__device__ __forceinline__ float ftanh(float x) {
    return fmaf(2.0f, fsig(2.0f * x), -1.0f);
}

// ===========================================================================
// Kernel 0: split inputs + Wx into global bf16 hi/lo (memory-bound pre-pass)
// ===========================================================================
__global__ __launch_bounds__(256) void split_kernel(
    const float* __restrict__ A, const float* __restrict__ W)
{
    const size_t A4 = (size_t)M_ROWS * DIM / 4;     // 16777216
    const size_t W4 = (size_t)DIM * FOURH / 4;      // 131072
    size_t stride = (size_t)gridDim.x * blockDim.x;
    for (size_t i = (size_t)blockIdx.x * blockDim.x + threadIdx.x;
         i < A4 + W4; i += stride) {
        float4 v;
        __nv_bfloat16 *hp, *lp;
        if (i < A4) {
            v = ((const float4*)A)[i];
            hp = g_ahi + i * 4;
            lp = g_alo + i * 4;
        } else {
            size_t j = i - A4;
            v = ((const float4*)W)[j];
            hp = g_whi + j * 4;
            lp = g_wlo + j * 4;
        }
        split_store4(v, hp, lp);
    }
}

// ===========================================================================
// Kernel 1: x_proj GEMM — pre-split bf16 operands, cp.async 3-stage pipeline.
// Block tile 128x128x32, 256 threads, 8 warps (4M x 2N), warp tile 32x64.
// ===========================================================================
#define X2_A_BYTES (128 * 80)                 // Ahi per stage (row stride 80 B)
#define X2_W_BYTES (32 * 272)                 // Whi per stage (row stride 272 B)
#define X2_STAGE   (2 * X2_A_BYTES + 2 * X2_W_BYTES)   // 37888
#define X2_SMEM    (3 * X2_STAGE)             // 113664

__global__ __launch_bounds__(256) void xproj_mma_kernel(
    const float* __restrict__ bias)
{
    extern __shared__ char xsm2[];
    const uint32_t smb = smem_u32(xsm2);

    const int tid   = threadIdx.x;
    const int lane  = tid & 31;
    const int wid   = tid >> 5;
    const int warpM = wid & 3;
    const int warpN = wid >> 2;
    const int bM    = blockIdx.y;
    const int bN    = blockIdx.x;

    const size_t aRowBase = (size_t)bM * 128;
    const size_t wColBase = (size_t)bN * 128;

    float acc[2][8][4];
    #pragma unroll
    for (int mt = 0; mt < 2; mt++)
        #pragma unroll
        for (int j = 0; j < 8; j++)
            #pragma unroll
            for (int q = 0; q < 4; q++) acc[mt][j][q] = 0.f;

    const int a_row_l = (lane & 15);
    const int a_koff  = ((lane >> 4) << 3);
    const int b_krow  = (lane & 7) + ((lane >> 3) & 1) * 8;
    const int b_ncol  = ((lane >> 4) & 1) * 8;

    // per-thread loader geometry (2 chunks per array per stage)
    const int ar0 = tid >> 2, ac0 = tid & 3;          // A chunk: id = tid + 256*i
    const int kr0 = tid >> 4, c160 = tid & 15;        // W chunk

    // issue one stage's cp.asyncs
    auto issue = [&](int st, int k0) {
        uint32_t base = smb + st * X2_STAGE;
        #pragma unroll
        for (int i = 0; i < 2; i++) {
            int id = tid + 256 * i;
            int ar = (i == 0) ? ar0 : (ar0 + 64);
            int ac = ac0;
            size_t asrc = (aRowBase + ar) * DIM + k0 + ac * 8;
            cp16(base + ar * 80 + ac * 16, g_ahi + asrc);
            cp16(base + X2_A_BYTES + ar * 80 + ac * 16, g_alo + asrc);
            int kr = (i == 0) ? kr0 : (kr0 + 16);
            int c16 = c160;
            size_t wsrc = (size_t)(k0 + kr) * FOURH + wColBase + c16 * 8;
            cp16(base + 2 * X2_A_BYTES + kr * 272 + c16 * 16, g_whi + wsrc);
            cp16(base + 2 * X2_A_BYTES + X2_W_BYTES + kr * 272 + c16 * 16,
                 g_wlo + wsrc);
            (void)id;
        }
    };

    issue(0, 0);  CP_COMMIT();
    issue(1, 32); CP_COMMIT();

    const int NSTAGE = DIM / 32;   // 16

    for (int s = 0; s < NSTAGE; s++) {
        CP_WAIT1();
        __syncthreads();

        if (s + 2 < NSTAGE) {
            issue((s + 2) % 3, (s + 2) * 32);
            CP_COMMIT();
        } else {
            CP_COMMIT();   // keep group accounting uniform
        }

        // compute stage s%3
        uint32_t sAhi = smb + (s % 3) * X2_STAGE;
        uint32_t sAlo = sAhi + X2_A_BYTES;
        uint32_t sBhi = sAhi + 2 * X2_A_BYTES;
        uint32_t sBlo = sBhi + X2_W_BYTES;

        #pragma unroll
        for (int ks = 0; ks < 2; ks++) {
            const int kk0 = ks * 16;
            uint32_t aHi[2][4], aLo[2][4];
            #pragma unroll
            for (int mt = 0; mt < 2; mt++) {
                uint32_t off =
                    (uint32_t)((warpM * 32 + mt * 16 + a_row_l) * 40 + kk0 + a_koff) * 2;
                ldsm_x4(aHi[mt], sAhi + off);
                ldsm_x4(aLo[mt], sAlo + off);
            }
            uint32_t bHi[4][4], bLo[4][4];
            #pragma unroll
            for (int nt = 0; nt < 4; nt++) {
                uint32_t off =
                    (uint32_t)((kk0 + b_krow) * 136 + warpN * 64 + nt * 16 + b_ncol) * 2;
                ldsm_x4_t(bHi[nt], sBhi + off);
                ldsm_x4_t(bLo[nt], sBlo + off);
            }
            #pragma unroll
            for (int mt = 0; mt < 2; mt++) {
                #pragma unroll
                for (int j = 0; j < 8; j++) {
                    uint32_t bh0 = bHi[j >> 1][(j & 1) * 2];
                    uint32_t bh1 = bHi[j >> 1][(j & 1) * 2 + 1];
                    uint32_t bl0 = bLo[j >> 1][(j & 1) * 2];
                    uint32_t bl1 = bLo[j >> 1][(j & 1) * 2 + 1];
                    mma_bf16(acc[mt][j], aHi[mt], bh0, bh1);
                    mma_bf16(acc[mt][j], aHi[mt], bl0, bl1);
                    mma_bf16(acc[mt][j], aLo[mt], bh0, bh1);
                }
            }
        }
    }

    // epilogue: add bias, write fp32
    const int g  = lane >> 2;
    const int t2 = (lane & 3) * 2;
    #pragma unroll
    for (int mt = 0; mt < 2; mt++) {
        size_t row = aRowBase + warpM * 32 + mt * 16 + g;
        #pragma unroll
        for (int j = 0; j < 8; j++) {
            int col = (int)wColBase + warpN * 64 + j * 8 + t2;
            float b0 = bias[col], b1 = bias[col + 1];
            float2 o0 = make_float2(acc[mt][j][0] + b0, acc[mt][j][1] + b1);
            float2 o1 = make_float2(acc[mt][j][2] + b0, acc[mt][j][3] + b1);
            *(float2*)&g_xproj[row * FOURH + col] = o0;
            *(float2*)&g_xproj[(row + 8) * FOURH + col] = o1;
        }
    }
}

// ===========================================================================
// Kernel 2: recurrent kernel — UNCHANGED from R10 (bulk DSMEM + complete_tx).
// ===========================================================================
#define CLUSTER 8
#define NB      16
#define LC      128
#define RTHREADS 512

#define WSTRIDE 136
#define ZSTRIDE 140

#define HROW     80
#define LO_OFF   1280
#define RANK_BLK 2560
#define HBUF     (CLUSTER * RANK_BLK)

#define SMB_WHHI 0
#define SMB_WHLO (SMB_WHHI + 256 * WSTRIDE * 2)
#define SMB_HB   (SMB_WHLO + 256 * WSTRIDE * 2)
#define SMB_Z0   (SMB_HB + 2 * HBUF)
#define SMB_Z1   (SMB_Z0 + NB * ZSTRIDE * 4)
#define SMB_C    (SMB_Z1 + NB * ZSTRIDE * 4)
#define SMB_WO   (SMB_C + NB * 32 * 4)
#define SMB_BO   (SMB_WO + 5 * 256 * 4)
#define SMB_MBAR (SMB_BO + 32)
#define SMB_EP   (SMB_MBAR + 16)
#define RSMEM_BYTES (SMB_EP + T_STEPS * NB)

__device__ __forceinline__ void mbar_wait_cluster(uint32_t mbar, uint32_t parity) {
    uint32_t done;
    asm volatile(
        "{ .reg .pred p;\n"
        " mbarrier.try_wait.parity.acquire.cluster.shared::cta.b64 p, [%1], %2;\n"
        " selp.b32 %0, 1, 0, p; }"
        : "=r"(done) : "r"(mbar), "r"(parity) : "memory");
    while (!done) {
        asm volatile(
            "{ .reg .pred p;\n"
            " mbarrier.try_wait.parity.acquire.cluster.shared::cta.b64 p, [%1], %2, 0x989680;\n"
            " selp.b32 %0, 1, 0, p; }"
            : "=r"(done) : "r"(mbar), "r"(parity) : "memory");
    }
}

__device__ __forceinline__ void do_head(
    const char* hb,
    const float* Wo_s, const float* bo_s,
    float* out, int tt, int b0, int rank, int wid, int lane)
{
    float sacc[4];
    #pragma unroll
    for (int q = 0; q < 4; q++) {
        const float* wcol = &Wo_s[q * 256];
        float s = 0.f;
        #pragma unroll
        for (int uu = 0; uu < 8; uu++) {
            const char* blk = hb + uu * RANK_BLK + wid * HROW + lane * 2;
            float hv = __bfloat162float(*(const __nv_bfloat16*)blk)
                     + __bfloat162float(*(const __nv_bfloat16*)(blk + LO_OFF));
            s = fmaf(hv, wcol[lane + 32 * uu], s);
        }
        sacc[q] = s;
    }
    float sv = 0.f;
    if (rank == 0) {
        const float* wcol = &Wo_s[4 * 256];
        #pragma unroll
        for (int uu = 0; uu < 8; uu++) {
            const char* blk = hb + uu * RANK_BLK + wid * HROW + lane * 2;
            float hv = __bfloat162float(*(const __nv_bfloat16*)blk)
                     + __bfloat162float(*(const __nv_bfloat16*)(blk + LO_OFF));
            sv = fmaf(hv, wcol[lane + 32 * uu], sv);
        }
    }
    #pragma unroll
    for (int q = 0; q < 4; q++) {
        float s = sacc[q];
        #pragma unroll
        for (int off = 16; off; off >>= 1)
            s += __shfl_xor_sync(0xFFFFFFFFu, s, off);
        sacc[q] = s;
    }
    #pragma unroll
    for (int off = 16; off; off >>= 1)
        sv += __shfl_xor_sync(0xFFFFFFFFu, sv, off);
    if (lane == 0) {
        size_t obase = ((size_t)tt * BATCH + b0 + wid) * OUTC;
        #pragma unroll
        for (int q = 0; q < 4; q++)
            out[obase + rank + 8 * q] = sacc[q] + bo_s[q];
        if (rank == 0)
            out[obase + 32] = sv + bo_s[4];
    }
}

__global__ void __cluster_dims__(CLUSTER, 1, 1) __launch_bounds__(RTHREADS, 1)
lstm_rec_kernel(const int*   __restrict__ epi,
                const float* __restrict__ carry_c,
                const float* __restrict__ carry_h,
                const float* __restrict__ Wh,
                const float* __restrict__ Wa,
                const float* __restrict__ ba,
                const float* __restrict__ Wv,
                const float* __restrict__ bv,
                float*       __restrict__ out)
{
    extern __shared__ char smraw[];
    __nv_bfloat16* WhHi = (__nv_bfloat16*)(smraw + SMB_WHHI);
    __nv_bfloat16* WhLo = (__nv_bfloat16*)(smraw + SMB_WHLO);
    float* z0_s = (float*)(smraw + SMB_Z0);
    float* z1_s = (float*)(smraw + SMB_Z1);
    float* c_s  = (float*)(smraw + SMB_C);
    float* Wo_s = (float*)(smraw + SMB_WO);
    float* bo_s = (float*)(smraw + SMB_BO);
    unsigned char* ep_s = (unsigned char*)(smraw + SMB_EP);

    const int tid  = threadIdx.x;
    const int lane = tid & 31;
    const int wid  = tid >> 5;
    const int wn   = wid & 7;
    const int kh   = wid >> 3;
    uint32_t rank;
    asm("mov.u32 %0, %%cluster_ctarank;" : "=r"(rank));
    const int cl = blockIdx.x / CLUSTER;
    const int b0 = cl * NB;
    const uint32_t smbase = smem_u32(smraw);

    if (tid == 0) {
        asm volatile("mbarrier.init.shared.b64 [%0], %1;"
            :: "r"(smbase + SMB_MBAR), "r"(1u) : "memory");
        asm volatile("mbarrier.init.shared.b64 [%0], %1;"
            :: "r"(smbase + SMB_MBAR + 8), "r"(1u) : "memory");
    }

    for (int idx = tid; idx < 256 * LC; idx += RTHREADS) {
        int k = idx >> 7;
        int c = idx & 127;
        int gcol = ((c >> 5) << 8) + ((int)rank << 5) + (c & 31);
        float w = Wh[k * FOURH + gcol];
        __nv_bfloat16 hi = __float2bfloat16_rn(w);
        __nv_bfloat16 lo = __float2bfloat16_rn(w - __bfloat162float(hi));
        WhHi[k * WSTRIDE + c] = hi;
        WhLo[k * WSTRIDE + c] = lo;
    }
    for (int idx = tid; idx < 256 * 8; idx += RTHREADS) {
        int k = idx >> 3;
        int c = idx & 7;
        float w = 0.f;
        if (c < 4)                     w = Wa[k * NACT + (int)rank + 8 * c];
        else if (c == 4 && rank == 0)  w = Wv[k];
        __nv_bfloat16 hi = __float2bfloat16_rn(w);
        __nv_bfloat16 lo = __float2bfloat16_rn(w - __bfloat162float(hi));
        WhHi[k * WSTRIDE + 128 + c] = hi;
        WhLo[k * WSTRIDE + 128 + c] = lo;
    }
    for (int idx = tid; idx < NB * HID; idx += RTHREADS) {
        int b = idx >> 8;
        int k = idx & 255;
        float v = carry_h[(size_t)(b0 + b) * HID + k];
        __nv_bfloat16 hi = __float2bfloat16_rn(v);
        __nv_bfloat16 lo = __float2bfloat16_rn(v - __bfloat162float(hi));
        char* blk = smraw + SMB_HB + 1 * HBUF + (k >> 5) * RANK_BLK;
        *(__nv_bfloat16*)(blk + b * HROW + (k & 31) * 2) = hi;
        *(__nv_bfloat16*)(blk + LO_OFF + b * HROW + (k & 31) * 2) = lo;
    }
    for (int idx = tid; idx < NB * 32; idx += RTHREADS) {
        int b = idx >> 5;
        int j = idx & 31;
        c_s[idx] = carry_c[(size_t)(b0 + b) * HID + (int)rank * 32 + j];
    }
    #pragma unroll
    for (int q = 0; q < 5; q++) {
        int col = (int)rank + 8 * q;
        if (col <= 32) {
            for (int k = tid; k < HID; k += RTHREADS)
                Wo_s[q * 256 + k] = (col < 32) ? Wa[k * NACT + col] : Wv[k];
            if (tid == 0) bo_s[q] = (col < 32) ? ba[col] : bv[0];
        }
    }
    for (int idx = tid; idx < T_STEPS * NB; idx += RTHREADS) {
        int t = idx >> 4;
        int b = idx & 15;
        ep_s[idx] = (unsigned char)(epi[t * BATCH + b0 + b] != 0);
    }
    __syncthreads();
    asm volatile("barrier.cluster.arrive.aligned;" ::: "memory");
    asm volatile("barrier.cluster.wait.aligned;"   ::: "memory");

    const int a_row_l = (lane & 15);
    const int a_koff  = ((lane >> 4) << 3);
    const int b_krow  = (lane & 7) + ((lane >> 3) & 1) * 8;
    const int b_ncol  = ((lane >> 4) & 1) * 8;
    const int kbase   = kh * 128;

    const uint32_t sWhHi = smem_u32(WhHi);
    const uint32_t sWhLo = smem_u32(WhLo);
    float* zw_s = kh ? z1_s : z0_s;

    int ph0 = 0, ph1 = 0;

    const int gb = tid >> 5;
    const int gj = tid & 31;

    const int cp_peer = tid + (tid >= (int)rank);

    for (int t = 0; t < T_STEPS; t++) {
        const int p_out = t & 1;
        const int p_in  = p_out ^ 1;
        const uint32_t hinBase  = smbase + SMB_HB + (uint32_t)p_in * HBUF;
        char* houtB = smraw + SMB_HB + p_out * HBUF + (int)rank * RANK_BLK;

        if (tid == 0) {
            uint32_t mb = smbase + SMB_MBAR + (uint32_t)(((t + 1) & 1) * 8);
            asm volatile("mbarrier.arrive.expect_tx.shared.b64 _, [%0], %1;"
                :: "r"(mb), "r"((uint32_t)(7 * RANK_BLK)) : "memory");
        }

        const size_t xbase = (size_t)t * BATCH * FOURH
                           + (size_t)(b0 + gb) * FOURH + (int)rank * 32 + gj;
        float xi = g_xproj[xbase];
        float xf = g_xproj[xbase + 256];
        float xg = g_xproj[xbase + 512];
        float xo = g_xproj[xbase + 768];
        int   ep = ep_s[t * NB + gb];

        if (t > 0) {
            if (t & 1) { mbar_wait_cluster(smbase + SMB_MBAR + 8, ph1); ph1 ^= 1; }
            else       { mbar_wait_cluster(smbase + SMB_MBAR,     ph0); ph0 ^= 1; }
        }

        {
            float acc[2][4][4];
            float accH[2][4];
            #pragma unroll
            for (int t2 = 0; t2 < 2; t2++) {
                #pragma unroll
                for (int kc = 0; kc < 4; kc++)
                    #pragma unroll
                    for (int q = 0; q < 4; q++) acc[t2][kc][q] = 0.f;
                #pragma unroll
                for (int q = 0; q < 4; q++) accH[t2][q] = 0.f;
            }

            #pragma unroll
            for (int ks = 0; ks < 8; ks++) {
                const int kk0 = kbase + ks * 16;
                const int kc  = ks & 3;
                const int blk = kk0 >> 5;
                uint32_t aoff = hinBase + (uint32_t)(blk * RANK_BLK
                               + a_row_l * HROW + ((kk0 & 16) + a_koff) * 2);
                uint32_t aHi[4], aLo[4];
                ldsm_x4(aHi, aoff);
                ldsm_x4(aLo, aoff + LO_OFF);
                uint32_t boff =
                    (uint32_t)((kk0 + b_krow) * WSTRIDE + wn * 16 + b_ncol) * 2;
                uint32_t bHi[4], bLo[4];
                ldsm_x4_t(bHi, sWhHi + boff);
                ldsm_x4_t(bLo, sWhLo + boff);
                #pragma unroll
                for (int t2 = 0; t2 < 2; t2++) {
                    mma_bf16(acc[t2][kc], aHi, bHi[t2 * 2], bHi[t2 * 2 + 1]);
                    mma_bf16(acc[t2][kc], aHi, bLo[t2 * 2], bLo[t2 * 2 + 1]);
                    mma_bf16(acc[t2][kc], aLo, bHi[t2 * 2], bHi[t2 * 2 + 1]);
                }
                if (wn == 0) {
                    uint32_t hoff = (uint32_t)((kk0 + b_krow) * WSTRIDE + 128) * 2;
                    uint32_t hH[2], hL[2];
                    ldsm_x2_t(hH, sWhHi + hoff);
                    ldsm_x2_t(hL, sWhLo + hoff);
                    const int kc2 = ks & 1;
                    mma_bf16(accH[kc2], aHi, hH[0], hH[1]);
                    mma_bf16(accH[kc2], aHi, hL[0], hL[1]);
                    mma_bf16(accH[kc2], aLo, hH[0], hH[1]);
                }
            }
            int r0 = lane >> 2;
            int cb = wn * 16 + 2 * (lane & 3);
            #pragma unroll
            for (int t2 = 0; t2 < 2; t2++) {
                int col = cb + 8 * t2;
                float v0 = (acc[t2][0][0] + acc[t2][1][0]) + (acc[t2][2][0] + acc[t2][3][0]);
                float v1 = (acc[t2][0][1] + acc[t2][1][1]) + (acc[t2][2][1] + acc[t2][3][1]);
                float v2 = (acc[t2][0][2] + acc[t2][1][2]) + (acc[t2][2][2] + acc[t2][3][2]);
                float v3 = (acc[t2][0][3] + acc[t2][1][3]) + (acc[t2][2][3] + acc[t2][3][3]);
                *(float2*)&zw_s[r0 * ZSTRIDE + col] = make_float2(v0, v1);
                *(float2*)&zw_s[(r0 + 8) * ZSTRIDE + col] = make_float2(v2, v3);
            }
            if (wn == 0) {
                int colH = 128 + 2 * (lane & 3);
                float h0 = accH[0][0] + accH[1][0];
                float h1 = accH[0][1] + accH[1][1];
                float h2 = accH[0][2] + accH[1][2];
                float h3 = accH[0][3] + accH[1][3];
                *(float2*)&zw_s[r0 * ZSTRIDE + colH] = make_float2(h0, h1);
                *(float2*)&zw_s[(r0 + 8) * ZSTRIDE + colH] = make_float2(h2, h3);
            }
        }
        __syncthreads();

        if (t > 0) {
            if (tid < 64) {
                int b = tid >> 2, q = tid & 3;
                out[((size_t)(t - 1) * BATCH + b0 + b) * OUTC + (int)rank + 8 * q]
                    = z0_s[b * ZSTRIDE + 128 + q] + z1_s[b * ZSTRIDE + 128 + q] + bo_s[q];
            } else if (rank == 0 && tid < 80) {
                int b = tid - 64;
                out[((size_t)(t - 1) * BATCH + b0 + b) * OUTC + 32]
                    = z0_s[b * ZSTRIDE + 132] + z1_s[b * ZSTRIDE + 132] + bo_s[4];
            }
        }

        {
            float zi = z0_s[gb * ZSTRIDE + gj]      + z1_s[gb * ZSTRIDE + gj];
            float zf = z0_s[gb * ZSTRIDE + 32 + gj] + z1_s[gb * ZSTRIDE + 32 + gj];
            float zg = z0_s[gb * ZSTRIDE + 64 + gj] + z1_s[gb * ZSTRIDE + 64 + gj];
            float zo = z0_s[gb * ZSTRIDE + 96 + gj] + z1_s[gb * ZSTRIDE + 96 + gj];
            float c_old = c_s[gb * 32 + gj];
            if (ep) { zi = 0.f; zf = 0.f; zg = 0.f; zo = 0.f; c_old = 0.f; }
            float iz = zi + xi;
            float fz = zf + xf;
            float gz = zg + xg;
            float oz = zo + xo;
            float nc = fsig(fz) * c_old + fsig(iz) * ftanh(gz);
            float nh = fsig(oz) * ftanh(nc);
            c_s[gb * 32 + gj] = nc;
            __nv_bfloat16 hi = __float2bfloat16_rn(nh);
            __nv_bfloat16 lo = __float2bfloat16_rn(nh - __bfloat162float(hi));
            *(__nv_bfloat16*)(houtB + gb * HROW + gj * 2) = hi;
            *(__nv_bfloat16*)(houtB + LO_OFF + gb * HROW + gj * 2) = lo;
        }
        __syncthreads();

        if (tid < 7) {
            asm volatile("fence.proxy.async.shared::cta;" ::: "memory");
            uint32_t src = smbase + (uint32_t)(SMB_HB + p_out * HBUF
                                               + (int)rank * RANK_BLK);
            uint32_t dst, mb;
            asm("mapa.shared::cluster.u32 %0, %1, %2;"
                : "=r"(dst) : "r"(src), "r"(cp_peer));
            uint32_t mbl = smbase + SMB_MBAR + (uint32_t)(((t + 1) & 1) * 8);
            asm("mapa.shared::cluster.u32 %0, %1, %2;"
                : "=r"(mb) : "r"(mbl), "r"(cp_peer));
            asm volatile(
                "cp.async.bulk.shared::cluster.shared::cta.mbarrier::complete_tx::bytes "
                "[%0], [%1], %2, [%3];"
                :: "r"(dst), "r"(src), "r"((uint32_t)RANK_BLK), "r"(mb) : "memory");
        }
    }

    {
        mbar_wait_cluster(smbase + SMB_MBAR, ph0);
        do_head(smraw + SMB_HB + 1 * HBUF, Wo_s, bo_s, out,
                T_STEPS - 1, b0, (int)rank, wid, lane);
    }

    asm volatile("barrier.cluster.arrive.aligned;" ::: "memory");
    asm volatile("barrier.cluster.wait.aligned;"   ::: "memory");
}

// ---------------------------------------------------------------------------
extern "C" void kernel_launch(void* const* d_in, const int* in_sizes, int n_in,
                              void* d_out, int out_size) {
    const float* inputs  = (const float*)d_in[0];
    const int*   epi     = (const int*)  d_in[1];
    const float* carry_c = (const float*)d_in[2];
    const float* carry_h = (const float*)d_in[3];
    const float* Wx      = (const float*)d_in[4];
    const float* Wh      = (const float*)d_in[5];
    const float* bias    = (const float*)d_in[6];
    const float* Wa      = (const float*)d_in[7];
    const float* ba      = (const float*)d_in[8];
    const float* Wv      = (const float*)d_in[9];
    const float* bv      = (const float*)d_in[10];
    float* out = (float*)d_out;

    cudaFuncSetAttribute(xproj_mma_kernel,
                         cudaFuncAttributeMaxDynamicSharedMemorySize, X2_SMEM);
    cudaFuncSetAttribute(lstm_rec_kernel,
                         cudaFuncAttributeMaxDynamicSharedMemorySize, RSMEM_BYTES);

    split_kernel<<<2048, 256>>>(inputs, Wx);

    dim3 g1(FOURH / 128, M_ROWS / 128);   // (8, 1024)
    xproj_mma_kernel<<<g1, 256, X2_SMEM>>>(bias);

    lstm_rec_kernel<<<(BATCH / NB) * CLUSTER, RTHREADS, RSMEM_BYTES>>>(
        epi, carry_c, carry_h, Wh, Wa, ba, Wv, bv, out);
}